// round 13
// baseline (speedup 1.0000x reference)
#include <cuda_runtime.h>
#include <cuda_fp16.h>
#include <math.h>
#include <stdint.h>

// ---------------------------------------------------------------------------
// Problem dims
// ---------------------------------------------------------------------------
#define BB 16
#define MM 512
#define NNd 512
#define RR 8
#define DD 256
#define HH 4
#define NN1 1024
#define TM  (BB*MM*RR)    // 65536
#define TT  (BB*MM)       // 8192
#define ND  (BB*NNd)      // 8192
#define ROWS1 (BB*NN1)    // 16384

#define F_BIAS 1
#define F_RELU 2
#define F_AUX  4
#define F_SIG  8
#define F_DIAG 16
#define F_OUT16 32

// ---------------------------------------------------------------------------
// Scratch
// ---------------------------------------------------------------------------
__device__ __half g_h1[(TM+ND)*DD];
__device__ __half g_emb[(TM+ND)*DD];
__device__ __half g_lnb[TM*DD];
__device__ __half g_kv[TM*512];
__device__ __half g_q0[TT*DD];
__device__ __half g_o0[TT*DD];
__device__ float  g_x1[TT*DD];
__device__ __half g_ln2[TT*DD];
__device__ __half g_ffh[TT*1024];
__device__ float  g_ffout[TT*DD];
__device__ float  g_feat0[ROWS1*DD];
__device__ float  g_detf[ND*DD];
__device__ __half g_x[ROWS1*DD];
__device__ __half g_hh[ROWS1*DD];
__device__ float g_src[ROWS1*HH];
__device__ float g_dstT[BB*HH*NN1];
__device__ float2 g_stat[BB*HH*NN1];
__device__ __half g_anum[(size_t)BB*HH*NN1*NN1];
__device__ unsigned char g_adj[(size_t)BB*NN1*NN1];
__device__ unsigned char g_adjd[(size_t)BB*NNd*NNd];
__device__ float g_pos[BB*NN1*2];
__device__ unsigned char g_vm[BB*NN1];
__device__ __half g_xq[ROWS1*DD];
__device__ __half g_xk[ROWS1*DD];
// fp16 weights
__device__ __half g_w2h[256*256];
__device__ __half g_wqkvh[256*768];
__device__ __half g_woh[256*256];
__device__ __half g_ff1h[256*1024];
__device__ __half g_ff2h[1024*256];
__device__ __half g_gatWh[2*256*256];
__device__ __half g_dgatWh[2*256*256];
__device__ __half g_clsWqh[2*256*256];
__device__ __half g_clsWkh[2*256*256];

// ---------------------------------------------------------------------------
// helpers
// ---------------------------------------------------------------------------
__device__ __forceinline__ uint32_t pk(float lo, float hi) {
    __half2 v = __floats2half2_rn(lo, hi);
    return *reinterpret_cast<uint32_t*>(&v);
}
__device__ __forceinline__ void mma_f16(float* c, const uint32_t* a, const uint32_t* b) {
    asm volatile(
        "mma.sync.aligned.m16n8k16.row.col.f32.f16.f16.f32 "
        "{%0,%1,%2,%3}, {%4,%5,%6,%7}, {%8,%9}, {%0,%1,%2,%3};\n"
        : "+f"(c[0]), "+f"(c[1]), "+f"(c[2]), "+f"(c[3])
        : "r"(a[0]), "r"(a[1]), "r"(a[2]), "r"(a[3]), "r"(b[0]), "r"(b[1]));
}
__device__ __forceinline__ void ldm_x4(uint32_t* r, uint32_t addr) {
    asm volatile("ldmatrix.sync.aligned.m8n8.x4.shared.b16 {%0,%1,%2,%3}, [%4];"
        : "=r"(r[0]), "=r"(r[1]), "=r"(r[2]), "=r"(r[3]) : "r"(addr));
}
__device__ __forceinline__ void ldm_x4_t(uint32_t* r, uint32_t addr) {
    asm volatile("ldmatrix.sync.aligned.m8n8.x4.trans.shared.b16 {%0,%1,%2,%3}, [%4];"
        : "=r"(r[0]), "=r"(r[1]), "=r"(r[2]), "=r"(r[3]) : "r"(addr));
}
__device__ __forceinline__ uint32_t cvs(const void* p) {
    return (uint32_t)__cvta_generic_to_shared(p);
}
__device__ __forceinline__ void cp16(uint32_t dst, const void* src) {
    asm volatile("cp.async.cg.shared.global [%0], [%1], 16;" :: "r"(dst), "l"(src));
}
__device__ __forceinline__ void cp8(uint32_t dst, const void* src) {
    asm volatile("cp.async.ca.shared.global [%0], [%1], 8;" :: "r"(dst), "l"(src));
}
__device__ __forceinline__ void cp4(uint32_t dst, const void* src) {
    asm volatile("cp.async.ca.shared.global [%0], [%1], 4;" :: "r"(dst), "l"(src));
}
#define CP_COMMIT() asm volatile("cp.async.commit_group;")
#define CP_WAIT2()  asm volatile("cp.async.wait_group 2;")
#define CP_WAIT1()  asm volatile("cp.async.wait_group 1;")
#define CP_WAIT0()  asm volatile("cp.async.wait_group 0;")

// combined weight fp32->fp16
struct WPack {
    const float* s[9];
    __half* d[9];
    int n[9];
};
__global__ void k_f2h_all(WPack p)
{
    int g = blockIdx.y;
    int i = (blockIdx.x * 256 + threadIdx.x) * 4;
    if (i >= p.n[g]) return;
    float4 v = *(const float4*)(p.s[g] + i);
    uint2 o;
    o.x = pk(v.x, v.y);
    o.y = pk(v.z, v.w);
    *(uint2*)(p.d[g] + i) = o;
}

// ---------------------------------------------------------------------------
// BIG GEMM (fp16, cp.async 4-stage, dynamic smem 48KB):
// CTA 128x128, BK=16, 256 thr, warp 64x32.
// Stage layout: [A 1536 words][B 1536 words] per stage, 4 stages.
// ---------------------------------------------------------------------------
#define STG_BYTES 12288u
template<bool TRANSB, int FLAGS>
__global__ __launch_bounds__(256, 2)
void tgemm_big(const __half* __restrict__ A, int lda, long long sA,
               const __half* __restrict__ B, int ldb, long long sB,
               void* __restrict__ Cv, int ldc, long long sC,
               int K,
               const float* __restrict__ bias,
               const __half* __restrict__ aux, int auxld,
               const unsigned char* __restrict__ adjp, long long sAdj,
               const __half* __restrict__ B2, void* __restrict__ C2v, int dual)
{
    extern __shared__ uint32_t dsm[];
    int bz = blockIdx.z;
    if (dual && bz) { B = B2; Cv = C2v; bz = 0; }
    A += (long long)bz * sA;
    B += (long long)bz * sB;
    size_t coff = (size_t)((long long)bz * sC);
    if (FLAGS & F_SIG) adjp += (long long)bz * sAdj;

    int m0 = blockIdx.y * 128, n0 = blockIdx.x * 128;

    int tid = threadIdx.x;
    int arow = tid >> 1, ahalf = tid & 1;
    const __half* gA = A + (size_t)(m0 + arow) * lda + ahalf * 8;

    const __half* gB;
    int kp = tid >> 5, nq = tid & 31;
    if (!TRANSB) gB = B + (size_t)(2 * kp) * ldb + n0 + nq * 4;
    else         gB = B + (size_t)(n0 + arow) * ldb + ahalf * 8;

    uint32_t aD = cvs(&dsm[arow * 12 + ahalf * 4]);
    uint32_t bD1, bD2;
    if (!TRANSB) {
        int w0 = (2 * kp) * 68 + nq * 2;
        bD1 = cvs(&dsm[1536 + w0]);
        bD2 = cvs(&dsm[1536 + w0 + 68]);
    } else {
        bD1 = cvs(&dsm[1536 + arow * 12 + ahalf * 4]);
        bD2 = 0;
    }

    int w = tid >> 5, l = tid & 31;
    int mbase = (w >> 2) * 64, nbase = (w & 3) * 32;
    int grp = l >> 2, tig = l & 3;

    int lrowA = ((l >> 3) & 1) * 8 + (l & 7);
    int khalf = l >> 4;
    uint32_t aBase[4];
    #pragma unroll
    for (int fm = 0; fm < 4; fm++)
        aBase[fm] = cvs(&dsm[(mbase + fm * 16 + lrowA) * 12 + khalf * 4]);
    uint32_t bBase[2];
    if (!TRANSB) {
        int krow = ((l >> 4) & 1) * 8 + (l & 7);
        int nblk = ((l >> 3) & 1) * 8;
        #pragma unroll
        for (int fp = 0; fp < 2; fp++)
            bBase[fp] = cvs(&dsm[1536 + krow * 68 + ((nbase + fp * 16 + nblk) >> 1)]);
    } else {
        #pragma unroll
        for (int fp = 0; fp < 2; fp++)
            bBase[fp] = cvs(&dsm[1536 + (nbase + fp * 16 + lrowA) * 12 + khalf * 4]);
    }

    float acc[4][4][4];
    #pragma unroll
    for (int i = 0; i < 4; i++)
        #pragma unroll
        for (int j = 0; j < 4; j++)
            #pragma unroll
            for (int q = 0; q < 4; q++) acc[i][j][q] = 0.f;

    int nk = K >> 4;

    // prologue: issue up to 3 stages
    int nst = nk < 3 ? nk : 3;
    for (int p = 0; p < nst; p++) {
        uint32_t toff = (uint32_t)p * STG_BYTES;
        int k0 = p * 16;
        cp16(aD + toff, gA + k0);
        if (!TRANSB) {
            cp8(bD1 + toff, gB + (size_t)k0 * ldb);
            cp8(bD2 + toff, gB + (size_t)(k0 + 1) * ldb);
        } else {
            cp16(bD1 + toff, gB + k0);
        }
        CP_COMMIT();
    }

    int s = 0;
    for (int i = 0; i < nk; i++) {
        int rem = nk - i - 1;
        if (rem >= 2) CP_WAIT2(); else if (rem == 1) CP_WAIT1(); else CP_WAIT0();
        __syncthreads();
        uint32_t soff = (uint32_t)s * STG_BYTES;
        uint32_t af[4][4];
        #pragma unroll
        for (int fm = 0; fm < 4; fm++) ldm_x4(af[fm], aBase[fm] + soff);
        uint32_t bfr[4][2];
        #pragma unroll
        for (int fp = 0; fp < 2; fp++) {
            uint32_t t4[4];
            if (!TRANSB) ldm_x4_t(t4, bBase[fp] + soff);
            else         ldm_x4(t4, bBase[fp] + soff);
            bfr[fp * 2][0] = t4[0]; bfr[fp * 2 + 1][0] = t4[1];
            bfr[fp * 2][1] = t4[2]; bfr[fp * 2 + 1][1] = t4[3];
        }
        #pragma unroll
        for (int fm = 0; fm < 4; fm++)
            #pragma unroll
            for (int fn = 0; fn < 4; fn++)
                mma_f16(acc[fm][fn], af[fm], bfr[fn]);
        if (i + 3 < nk) {
            int st = (s + 3) & 3;
            uint32_t toff = (uint32_t)st * STG_BYTES;
            int k0 = (i + 3) * 16;
            cp16(aD + toff, gA + k0);
            if (!TRANSB) {
                cp8(bD1 + toff, gB + (size_t)k0 * ldb);
                cp8(bD2 + toff, gB + (size_t)(k0 + 1) * ldb);
            } else {
                cp16(bD1 + toff, gB + k0);
            }
            CP_COMMIT();
        }
        s = (s + 1) & 3;
    }

    // epilogue
    #pragma unroll
    for (int fm = 0; fm < 4; fm++) {
        int row0 = m0 + mbase + fm * 16 + grp;
        #pragma unroll
        for (int fn = 0; fn < 4; fn++) {
            int col = n0 + nbase + fn * 8 + 2 * tig;
            float v0 = acc[fm][fn][0], v1 = acc[fm][fn][1];
            float v2 = acc[fm][fn][2], v3 = acc[fm][fn][3];
            if (FLAGS & F_BIAS) {
                float bb0 = bias[col], bb1 = bias[col + 1];
                v0 += bb0; v1 += bb1; v2 += bb0; v3 += bb1;
            }
            if (FLAGS & F_RELU) {
                v0 = fmaxf(v0, 0.f); v1 = fmaxf(v1, 0.f);
                v2 = fmaxf(v2, 0.f); v3 = fmaxf(v3, 0.f);
            }
            if (FLAGS & F_AUX) {
                float2 a0 = __half22float2(*(const __half2*)(aux + (size_t)row0 * auxld + col));
                float2 a8 = __half22float2(*(const __half2*)(aux + (size_t)(row0 + 8) * auxld + col));
                v0 += a0.x; v1 += a0.y; v2 += a8.x; v3 += a8.y;
            }
            if (FLAGS & F_SIG) {
                const unsigned char* q0p = adjp + (size_t)row0 * ldc + col;
                const unsigned char* q8p = adjp + (size_t)(row0 + 8) * ldc + col;
                v0 = q0p[0] ? 1.f / (1.f + __expf(-v0 * 0.0625f)) : 0.f;
                v1 = q0p[1] ? 1.f / (1.f + __expf(-v1 * 0.0625f)) : 0.f;
                v2 = q8p[0] ? 1.f / (1.f + __expf(-v2 * 0.0625f)) : 0.f;
                v3 = q8p[1] ? 1.f / (1.f + __expf(-v3 * 0.0625f)) : 0.f;
                if (FLAGS & F_DIAG) {
                    if (row0 == col) v0 = 0.f;
                    if (row0 == col + 1) v1 = 0.f;
                    if (row0 + 8 == col) v2 = 0.f;
                    if (row0 + 8 == col + 1) v3 = 0.f;
                }
            }
            if (FLAGS & F_OUT16) {
                __half* Ch = (__half*)Cv + coff;
                *(uint32_t*)&Ch[(size_t)row0 * ldc + col] = pk(v0, v1);
                *(uint32_t*)&Ch[(size_t)(row0 + 8) * ldc + col] = pk(v2, v3);
            } else {
                float* C = (float*)Cv + coff;
                *(float2*)&C[(size_t)row0 * ldc + col] = make_float2(v0, v1);
                *(float2*)&C[(size_t)(row0 + 8) * ldc + col] = make_float2(v2, v3);
            }
        }
    }
}

// ---------------------------------------------------------------------------
// GAT aggregation (fp16 GEMM, cp.async 4-stage): CTA 128x64, warp 32x32.
// ---------------------------------------------------------------------------
__global__ __launch_bounds__(256)
void agg_fused(const __half* __restrict__ anum, const float2* __restrict__ stat,
               const __half* __restrict__ hmat,
               const float* __restrict__ aux, __half* __restrict__ xout, int NN)
{
    int z = blockIdx.z;
    int b = z >> 2, h = z & 3;
    const __half* B = hmat + (size_t)b * NN * 256 + h * 64;
    __half* C = xout + (size_t)b * NN * 256 + h * 64;
    const float* auxp = aux + (size_t)b * NN * 256 + h * 64;
    const float2* statz = stat + (size_t)z * NN;

    int m0 = blockIdx.y * 128;
    __shared__ uint32_t As[4][1536];
    __shared__ uint32_t Bs[4][576];
    int tid = threadIdx.x;

    int arow = tid >> 1, ahalf = tid & 1;
    const __half* gA = anum + ((size_t)z * NN + m0 + arow) * NN + ahalf * 8;

    int kp = tid >> 5, nq = tid & 31;
    const __half* gB = B + (size_t)(2 * kp) * 256 + 2 * nq;

    uint32_t aD = cvs(&As[0][arow * 12 + ahalf * 4]);
    uint32_t bD1 = cvs(&Bs[0][(2 * kp) * 36 + nq]);
    uint32_t bD2 = cvs(&Bs[0][(2 * kp + 1) * 36 + nq]);

    int w = tid >> 5, l = tid & 31;
    int wm = w >> 1, wn = w & 1;
    int mrow = wm * 32, ncol = wn * 32;
    int grp = l >> 2, tig = l & 3;

    int lrowA = ((l >> 3) & 1) * 8 + (l & 7);
    int khalf = l >> 4;
    uint32_t aBase[2];
    #pragma unroll
    for (int fm = 0; fm < 2; fm++)
        aBase[fm] = cvs(&As[0][(mrow + fm * 16 + lrowA) * 12 + khalf * 4]);
    int krow = ((l >> 4) & 1) * 8 + (l & 7);
    int nblk = ((l >> 3) & 1) * 8;
    uint32_t bBase[2];
    #pragma unroll
    for (int fp = 0; fp < 2; fp++)
        bBase[fp] = cvs(&Bs[0][krow * 36 + ((ncol + fp * 16 + nblk) >> 1)]);

    float acc[2][4][4];
    #pragma unroll
    for (int i = 0; i < 2; i++)
        #pragma unroll
        for (int j = 0; j < 4; j++)
            #pragma unroll
            for (int q = 0; q < 4; q++) acc[i][j][q] = 0.f;

    int nk = NN >> 4;

    // prologue: up to 3 stages
    int nst = nk < 3 ? nk : 3;
    for (int p = 0; p < nst; p++) {
        int k0 = p * 16;
        cp16(aD + p * 6144, gA + k0);
        cp4(bD1 + p * 2304, gB + (size_t)k0 * 256);
        cp4(bD2 + p * 2304, gB + (size_t)(k0 + 1) * 256);
        CP_COMMIT();
    }

    int s = 0;
    for (int i = 0; i < nk; i++) {
        int rem = nk - i - 1;
        if (rem >= 2) CP_WAIT2(); else if (rem == 1) CP_WAIT1(); else CP_WAIT0();
        __syncthreads();
        uint32_t sa = (uint32_t)(s * 6144);
        uint32_t sbo = (uint32_t)(s * 2304);
        uint32_t af[2][4];
        #pragma unroll
        for (int fm = 0; fm < 2; fm++) ldm_x4(af[fm], aBase[fm] + sa);
        uint32_t bfr[4][2];
        #pragma unroll
        for (int fp = 0; fp < 2; fp++) {
            uint32_t t4[4];
            ldm_x4_t(t4, bBase[fp] + sbo);
            bfr[fp * 2][0] = t4[0]; bfr[fp * 2 + 1][0] = t4[1];
            bfr[fp * 2][1] = t4[2]; bfr[fp * 2 + 1][1] = t4[3];
        }
        #pragma unroll
        for (int fm = 0; fm < 2; fm++)
            #pragma unroll
            for (int fn = 0; fn < 4; fn++)
                mma_f16(acc[fm][fn], af[fm], bfr[fn]);
        if (i + 3 < nk) {
            int st = (s + 3) & 3;
            int k0 = (i + 3) * 16;
            cp16(aD + st * 6144, gA + k0);
            cp4(bD1 + st * 2304, gB + (size_t)k0 * 256);
            cp4(bD2 + st * 2304, gB + (size_t)(k0 + 1) * 256);
            CP_COMMIT();
        }
        s = (s + 1) & 3;
    }

    #pragma unroll
    for (int fm = 0; fm < 2; fm++) {
        int row = m0 + mrow + fm * 16 + grp;
        float inv0 = statz[row].y;
        float inv8 = statz[row + 8].y;
        #pragma unroll
        for (int fn = 0; fn < 4; fn++) {
            int col = ncol + fn * 8 + 2 * tig;
            float v0 = acc[fm][fn][0] * inv0, v1 = acc[fm][fn][1] * inv0;
            float v2 = acc[fm][fn][2] * inv8, v3 = acc[fm][fn][3] * inv8;
            v0 = (v0 > 0.f) ? v0 : expm1f(v0);
            v1 = (v1 > 0.f) ? v1 : expm1f(v1);
            v2 = (v2 > 0.f) ? v2 : expm1f(v2);
            v3 = (v3 > 0.f) ? v3 : expm1f(v3);
            float2 x0 = *(const float2*)&auxp[(size_t)row * 256 + col];
            float2 x1 = *(const float2*)&auxp[(size_t)(row + 8) * 256 + col];
            *(uint32_t*)&C[(size_t)row * 256 + col] =
                pk(0.5f * v0 + 0.5f * x0.x, 0.5f * v1 + 0.5f * x0.y);
            *(uint32_t*)&C[(size_t)(row + 8) * 256 + col] =
                pk(0.5f * v2 + 0.5f * x1.x, 0.5f * v3 + 0.5f * x1.y);
        }
    }
}

// ---------------------------------------------------------------------------
// Small kernels
// ---------------------------------------------------------------------------
// merged tr+det feature layer1
__global__ void k_feat1(const float* __restrict__ tr, const float* __restrict__ de,
                        const float* __restrict__ W1, const float* __restrict__ b1,
                        __half* __restrict__ out)
{
    int tid = threadIdx.x;
    size_t row = (size_t)blockIdx.x * 4 + (tid >> 6);
    int c4 = (tid & 63) * 4;
    const float* xr = (row < TM) ? (tr + row * 4) : (de + (row - TM) * 4);
    const float4 x4 = *(const float4*)xr;
    float4 v = *(const float4*)(b1 + c4);
    float4 w0 = *(const float4*)(W1 + c4);
    float4 w1 = *(const float4*)(W1 + 256 + c4);
    float4 w2 = *(const float4*)(W1 + 512 + c4);
    float4 w3 = *(const float4*)(W1 + 768 + c4);
    v.x += x4.x * w0.x + x4.y * w1.x + x4.z * w2.x + x4.w * w3.x;
    v.y += x4.x * w0.y + x4.y * w1.y + x4.z * w2.y + x4.w * w3.y;
    v.z += x4.x * w0.z + x4.y * w1.z + x4.z * w2.z + x4.w * w3.z;
    v.w += x4.x * w0.w + x4.y * w1.w + x4.z * w2.w + x4.w * w3.w;
    v.x = (v.x > 0.f) ? v.x : (__expf(v.x) - 1.f);
    v.y = (v.y > 0.f) ? v.y : (__expf(v.y) - 1.f);
    v.z = (v.z > 0.f) ? v.z : (__expf(v.z) - 1.f);
    v.w = (v.w > 0.f) ? v.w : (__expf(v.w) - 1.f);
    uint2 p;
    p.x = pk(v.x, v.y);
    p.y = pk(v.z, v.w);
    *(uint2*)(out + row * 256 + c4) = p;
}

__global__ void k_ln_h(const __half* __restrict__ in, __half* __restrict__ out)
{
    int w = threadIdx.x >> 5, lane = threadIdx.x & 31;
    size_t row = (size_t)blockIdx.x * 8 + w;
    const uint4* ip = (const uint4*)(in + row * 256);
    uint4 u = ip[lane];
    float2 f0 = __half22float2(*(__half2*)&u.x);
    float2 f1 = __half22float2(*(__half2*)&u.y);
    float2 f2 = __half22float2(*(__half2*)&u.z);
    float2 f3 = __half22float2(*(__half2*)&u.w);
    float a = f0.x + f0.y + f1.x + f1.y + f2.x + f2.y + f3.x + f3.y;
    float b = f0.x*f0.x + f0.y*f0.y + f1.x*f1.x + f1.y*f1.y
            + f2.x*f2.x + f2.y*f2.y + f3.x*f3.x + f3.y*f3.y;
    #pragma unroll
    for (int o = 16; o; o >>= 1) {
        a += __shfl_xor_sync(0xffffffff, a, o);
        b += __shfl_xor_sync(0xffffffff, b, o);
    }
    float mean = a * (1.f / 256.f);
    float var = b * (1.f / 256.f) - mean * mean;
    float rstd = rsqrtf(var + 1e-5f);
    uint4 r;
    r.x = pk((f0.x - mean) * rstd, (f0.y - mean) * rstd);
    r.y = pk((f1.x - mean) * rstd, (f1.y - mean) * rstd);
    r.z = pk((f2.x - mean) * rstd, (f2.y - mean) * rstd);
    r.w = pk((f3.x - mean) * rstd, (f3.y - mean) * rstd);
    ((uint4*)(out + row * 256))[lane] = r;
}

__global__ void k_ln_f(const float* __restrict__ in, __half* __restrict__ out)
{
    int w = threadIdx.x >> 5, lane = threadIdx.x & 31;
    size_t row = (size_t)blockIdx.x * 8 + w;
    const float4* ip = (const float4*)(in + row * 256);
    float4 v0 = ip[lane], v1 = ip[lane + 32];
    float a = v0.x + v0.y + v0.z + v0.w + v1.x + v1.y + v1.z + v1.w;
    float b = v0.x*v0.x + v0.y*v0.y + v0.z*v0.z + v0.w*v0.w
            + v1.x*v1.x + v1.y*v1.y + v1.z*v1.z + v1.w*v1.w;
    #pragma unroll
    for (int o = 16; o; o >>= 1) {
        a += __shfl_xor_sync(0xffffffff, a, o);
        b += __shfl_xor_sync(0xffffffff, b, o);
    }
    float mean = a * (1.f / 256.f);
    float var = b * (1.f / 256.f) - mean * mean;
    float rstd = rsqrtf(var + 1e-5f);
    uint2 p0, p1;
    p0.x = pk((v0.x - mean) * rstd, (v0.y - mean) * rstd);
    p0.y = pk((v0.z - mean) * rstd, (v0.w - mean) * rstd);
    p1.x = pk((v1.x - mean) * rstd, (v1.y - mean) * rstd);
    p1.y = pk((v1.z - mean) * rstd, (v1.w - mean) * rstd);
    *(uint2*)(out + row * 256 + lane * 4) = p0;
    *(uint2*)(out + row * 256 + 128 + lane * 4) = p1;
}

__global__ void k_attn(const __half* __restrict__ q0, const __half* __restrict__ kv,
                       __half* __restrict__ o0)
{
    size_t t = blockIdx.x;
    int d = threadIdx.x;
    int w = d >> 5, lane = d & 31, h = d >> 6;
    __shared__ float red[8][8];
    const __half* kvb = kv + t * 8 * 512;
    float qd = __half2float(q0[t * 256 + d]);
    #pragma unroll
    for (int s = 0; s < 8; s++) {
        float v = qd * __half2float(kvb[s * 512 + d]);
        #pragma unroll
        for (int o = 16; o; o >>= 1) v += __shfl_xor_sync(0xffffffff, v, o);
        if (lane == 0) red[w][s] = v;
    }
    __syncthreads();
    float lg[8];
    float m = -1e30f;
    #pragma unroll
    for (int s = 0; s < 8; s++) {
        lg[s] = (red[2 * h][s] + red[2 * h + 1][s]) * 0.125f;
        m = fmaxf(m, lg[s]);
    }
    float sum = 0.f;
    #pragma unroll
    for (int s = 0; s < 8; s++) { lg[s] = __expf(lg[s] - m); sum += lg[s]; }
    float inv = 1.f / sum;
    float o = 0.f;
    #pragma unroll
    for (int s = 0; s < 8; s++) o += lg[s] * inv * __half2float(kvb[s * 512 + 256 + d]);
    o0[t * 256 + d] = __float2half(o);
}

__global__ void k_feat0(const __half* __restrict__ tr_emb, const float* __restrict__ x1,
                        const float* __restrict__ ffout, const __half* __restrict__ det_emb,
                        float* __restrict__ feat0, __half* __restrict__ x,
                        float* __restrict__ detf)
{
    size_t idx = (size_t)blockIdx.x * 256 + threadIdx.x;
    int d = idx & 255;
    size_t row = idx >> 8;
    int i = row & 1023;
    int b = row >> 10;
    float v;
    if (i < 512) {
        size_t t = (size_t)b * 512 + i;
        v = __half2float(tr_emb[t * 2048 + d]) + 0.9f * (x1[t * 256 + d] + ffout[t * 256 + d]);
    } else {
        size_t t = (size_t)b * 512 + (i - 512);
        v = __half2float(det_emb[t * 256 + d]);
        detf[t * 256 + d] = v;
    }
    feat0[idx] = v;
    x[idx] = __float2half(v);
}

__global__ void k_posvm(const float* __restrict__ tracks, const float* __restrict__ dets,
                        const int* __restrict__ tmarks, const int* __restrict__ dmarks,
                        float* __restrict__ pos, unsigned char* __restrict__ vm)
{
    int idx = blockIdx.x * 256 + threadIdx.x;
    if (idx >= BB * NN1) return;
    int b = idx >> 10, i = idx & 1023;
    float x, y; unsigned char v;
    if (i < 512) {
        const float* p = tracks + ((size_t)(b * 512 + i)) * 8 * 4;
        x = p[0]; y = p[1];
        v = (i < tmarks[b]);
    } else {
        int n = i - 512;
        const float* p = dets + ((size_t)(b * 512 + n)) * 4;
        x = p[0]; y = p[1];
        v = (n < dmarks[b]);
    }
    pos[idx * 2] = x; pos[idx * 2 + 1] = y; vm[idx] = v;
}

__global__ void k_adj(const float* __restrict__ pos, const unsigned char* __restrict__ vm,
                      unsigned char* __restrict__ adj)
{
    int i = blockIdx.x, b = blockIdx.y;
    size_t base = (size_t)b * NN1;
    const float2* p2 = (const float2*)pos;
    float2 pi = p2[base + i];
    unsigned char vi = vm[base + i];
    int j0 = threadIdx.x * 4;
    uchar4 r;
    unsigned char* rp = &r.x;
    #pragma unroll
    for (int u = 0; u < 4; u++) {
        int j = j0 + u;
        float2 pj = p2[base + j];
        float dx = pi.x - pj.x, dy = pi.y - pj.y;
        rp[u] = (unsigned char)((dx * dx + dy * dy < 4.0f) && vi && vm[base + j]);
    }
    ((uchar4*)(adj + ((size_t)b * NN1 + i) * NN1))[threadIdx.x] = r;
}

__global__ void k_adjd(const float* __restrict__ pos, const unsigned char* __restrict__ vm,
                       unsigned char* __restrict__ adjd)
{
    int i = blockIdx.x, b = blockIdx.y;
    size_t base = (size_t)b * NN1 + 512;
    const float2* p2 = (const float2*)pos;
    float2 pi = p2[base + i];
    unsigned char vi = vm[base + i];
    int j0 = threadIdx.x * 4;
    uchar4 r;
    unsigned char* rp = &r.x;
    #pragma unroll
    for (int u = 0; u < 4; u++) {
        int j = j0 + u;
        float2 pj = p2[base + j];
        float dx = pi.x - pj.x, dy = pi.y - pj.y;
        rp[u] = (unsigned char)((dx * dx + dy * dy < 4.0f) && vi && vm[base + j]);
    }
    ((uchar4*)(adjd + ((size_t)b * NNd + i) * NNd))[threadIdx.x] = r;
}

__global__ void k_srcdst(const __half* __restrict__ Hm, const float* __restrict__ a0,
                         float* __restrict__ src, float* __restrict__ dstT, int NN)
{
    size_t row = blockIdx.x;
    int d = threadIdx.x;
    float hv = __half2float(Hm[row * 256 + d]);
    float s = hv * a0[d];
    float t2 = hv * a0[256 + d];
    #pragma unroll
    for (int o = 16; o; o >>= 1) {
        s  += __shfl_xor_sync(0xffffffff, s, o);
        t2 += __shfl_xor_sync(0xffffffff, t2, o);
    }
    __shared__ float ps[8], pt[8];
    if ((d & 31) == 0) { ps[d >> 5] = s; pt[d >> 5] = t2; }
    __syncthreads();
    if (d < 4) {
        int b = (int)(row / NN);
        int i = (int)(row - (size_t)b * NN);
        src[row * 4 + d] = ps[2 * d] + ps[2 * d + 1];
        dstT[((size_t)b * 4 + d) * NN + i] = pt[2 * d] + pt[2 * d + 1];
    }
}

__global__ void k_rowstat(const float* __restrict__ src, const float* __restrict__ dstT,
                          const unsigned char* __restrict__ adj, float2* __restrict__ stat,
                          __half* __restrict__ anum, int NN)
{
    int i = blockIdx.x, b = blockIdx.y;
    int h = threadIdx.x >> 5, lane = threadIdx.x & 31;
    int z = b * 4 + h;
    float s = src[((size_t)b * NN + i) * 4 + h];
    const uchar4* adjrow = (const uchar4*)(adj + ((size_t)b * NN + i) * NN);
    const float4* dsth = (const float4*)(dstT + ((size_t)z) * NN);
    __half* arow = anum + ((size_t)z * NN + i) * NN;
    int nq = NN >> 2;
    float mx = -1e30f;
    for (int jq = lane; jq < nq; jq += 32) {
        uchar4 a4 = adjrow[jq];
        float4 d4 = dsth[jq];
        float e0 = s + d4.x; e0 = e0 > 0.f ? e0 : 0.2f * e0; e0 = a4.x ? e0 : -1e9f;
        float e1 = s + d4.y; e1 = e1 > 0.f ? e1 : 0.2f * e1; e1 = a4.y ? e1 : -1e9f;
        float e2 = s + d4.z; e2 = e2 > 0.f ? e2 : 0.2f * e2; e2 = a4.z ? e2 : -1e9f;
        float e3 = s + d4.w; e3 = e3 > 0.f ? e3 : 0.2f * e3; e3 = a4.w ? e3 : -1e9f;
        mx = fmaxf(mx, fmaxf(fmaxf(e0, e1), fmaxf(e2, e3)));
    }
    #pragma unroll
    for (int o = 16; o; o >>= 1) mx = fmaxf(mx, __shfl_xor_sync(0xffffffff, mx, o));
    float sum = 0.f;
    for (int jq = lane; jq < nq; jq += 32) {
        uchar4 a4 = adjrow[jq];
        float4 d4 = dsth[jq];
        float e0 = s + d4.x; e0 = e0 > 0.f ? e0 : 0.2f * e0; e0 = a4.x ? e0 : -1e9f;
        float e1 = s + d4.y; e1 = e1 > 0.f ? e1 : 0.2f * e1; e1 = a4.y ? e1 : -1e9f;
        float e2 = s + d4.z; e2 = e2 > 0.f ? e2 : 0.2f * e2; e2 = a4.z ? e2 : -1e9f;
        float e3 = s + d4.w; e3 = e3 > 0.f ? e3 : 0.2f * e3; e3 = a4.w ? e3 : -1e9f;
        float n0 = __expf(e0 - mx), n1 = __expf(e1 - mx);
        float n2 = __expf(e2 - mx), n3 = __expf(e3 - mx);
        sum += n0 + n1 + n2 + n3;
        uint2 pkd;
        pkd.x = pk(n0, n1);
        pkd.y = pk(n2, n3);
        *(uint2*)(arow + jq * 4) = pkd;
    }
    #pragma unroll
    for (int o = 16; o; o >>= 1) sum += __shfl_xor_sync(0xffffffff, sum, o);
    if (lane == 0)
        stat[(size_t)z * NN + i] = make_float2(mx, 1.f / sum);
}

__global__ void k_asso(const float* __restrict__ scores, float* __restrict__ out)
{
    size_t idx = (size_t)blockIdx.x * 256 + threadIdx.x;
    int j = idx & 511;
    size_t r = idx >> 9;
    int m = r & 511;
    int b = (int)(r >> 9);
    out[idx] = scores[(((size_t)b * 1024 + m) * 1024) + 512 + j];
}

// ---------------------------------------------------------------------------
// Host side
// ---------------------------------------------------------------------------
#define TG_SMEM 49152

static void run_big(const __half* A, int lda, long long sA,
                    const __half* B, int ldb, long long sB,
                    void* C, int ldc, long long sC,
                    int M, int N, int K, int batch,
                    const float* bias, const __half* aux, int auxld,
                    const unsigned char* adjp, long long sAdj,
                    int flags, bool transb,
                    const __half* B2 = nullptr, void* C2 = nullptr, int dual = 0)
{
    dim3 g(N / 128, M / 128, batch);
#define CALLBIG(T, F) do { \
        cudaFuncSetAttribute(tgemm_big<T, F>, cudaFuncAttributeMaxDynamicSharedMemorySize, TG_SMEM); \
        tgemm_big<T, F><<<g, 256, TG_SMEM>>>(A, lda, sA, B, ldb, sB, \
            C, ldc, sC, K, bias, aux, auxld, adjp, sAdj, B2, C2, dual); \
    } while (0)
    if (!transb) {
        if (flags == (F_BIAS | F_OUT16))      CALLBIG(false, F_BIAS | F_OUT16);
        else if (flags == F_OUT16)            CALLBIG(false, F_OUT16);
        else if (flags == F_AUX)              CALLBIG(false, F_AUX);
        else if (flags == (F_RELU | F_OUT16)) CALLBIG(false, F_RELU | F_OUT16);
        else                                  CALLBIG(false, 0);
    } else {
        if (flags == F_SIG)                   CALLBIG(true, F_SIG);
        else                                  CALLBIG(true, F_SIG | F_DIAG);
    }
#undef CALLBIG
}

#define SYM(p, s) cudaGetSymbolAddress((void**)&p, s)

extern "C" void kernel_launch(void* const* d_in, const int* in_sizes, int n_in,
                              void* d_out, int out_size)
{
    (void)in_sizes; (void)n_in; (void)out_size;
    const float* tracks = (const float*)d_in[0];
    const float* dets   = (const float*)d_in[1];
    const int* tmarks   = (const int*)d_in[2];
    const int* dmarks   = (const int*)d_in[3];
    const float* W1     = (const float*)d_in[4];
    const float* b1     = (const float*)d_in[5];
    const float* W2     = (const float*)d_in[6];
    const float* b2     = (const float*)d_in[7];
    const float* Wqkv   = (const float*)d_in[8];
    const float* Wo     = (const float*)d_in[9];
    const float* ff1    = (const float*)d_in[10];
    const float* ff2    = (const float*)d_in[11];
    const float* gatW   = (const float*)d_in[12];
    const float* gata   = (const float*)d_in[13];
    const float* dgatW  = (const float*)d_in[14];
    const float* dgata  = (const float*)d_in[15];
    const float* clsWq  = (const float*)d_in[16];
    const float* clsWk  = (const float*)d_in[17];

    float* out = (float*)d_out;
    float* out_scores = out;
    float* out_det    = out + (size_t)BB * NN1 * NN1;
    float* out_asso   = out_det + (size_t)BB * NNd * NNd;

    __half *h1, *emb, *lnb, *kv, *q0, *o0, *ln2, *ffh, *x, *hh, *xq, *xk, *anum;
    __half *w2h, *wqkvh, *woh, *ff1h, *ff2h, *gatWh, *dgatWh, *clsWqh, *clsWkh;
    float *x1, *ffout, *feat0, *detf, *src, *dstT, *pos;
    float2* stat;
    unsigned char *adj, *adjd, *vm;
    SYM(h1, g_h1);         SYM(emb, g_emb);       SYM(lnb, g_lnb);
    SYM(kv, g_kv);         SYM(q0, g_q0);         SYM(o0, g_o0);
    SYM(x1, g_x1);         SYM(ln2, g_ln2);       SYM(ffh, g_ffh);
    SYM(ffout, g_ffout);   SYM(feat0, g_feat0);   SYM(detf, g_detf);
    SYM(x, g_x);           SYM(hh, g_hh);         SYM(src, g_src);
    SYM(dstT, g_dstT);     SYM(stat, g_stat);     SYM(anum, g_anum);
    SYM(adj, g_adj);       SYM(adjd, g_adjd);     SYM(pos, g_pos);
    SYM(vm, g_vm);         SYM(xq, g_xq);         SYM(xk, g_xk);
    SYM(w2h, g_w2h);       SYM(wqkvh, g_wqkvh);   SYM(woh, g_woh);
    SYM(ff1h, g_ff1h);     SYM(ff2h, g_ff2h);     SYM(gatWh, g_gatWh);
    SYM(dgatWh, g_dgatWh); SYM(clsWqh, g_clsWqh); SYM(clsWkh, g_clsWkh);

    __half* tr_emb = emb;
    __half* det_emb = emb + (size_t)TM * DD;

    // ---- weight fp32 -> fp16, one launch ----
    {
        WPack p;
        p.s[0] = W2;    p.d[0] = w2h;    p.n[0] = 65536;
        p.s[1] = Wqkv;  p.d[1] = wqkvh;  p.n[1] = 196608;
        p.s[2] = Wo;    p.d[2] = woh;    p.n[2] = 65536;
        p.s[3] = ff1;   p.d[3] = ff1h;   p.n[3] = 262144;
        p.s[4] = ff2;   p.d[4] = ff2h;   p.n[4] = 262144;
        p.s[5] = gatW;  p.d[5] = gatWh;  p.n[5] = 131072;
        p.s[6] = dgatW; p.d[6] = dgatWh; p.n[6] = 131072;
        p.s[7] = clsWq; p.d[7] = clsWqh; p.n[7] = 131072;
        p.s[8] = clsWk; p.d[8] = clsWkh; p.n[8] = 131072;
        k_f2h_all<<<dim3(256, 9), 256>>>(p);
    }

    // ---- feature MLP (merged tr+det) ----
    k_feat1<<<(TM + ND) / 4, 256>>>(tracks, dets, W1, b1, h1);
    run_big(h1, 256, 0, w2h, 256, 0, emb, 256, 0,
            TM + ND, 256, 256, 1, b2, nullptr, 0, nullptr, 0, F_BIAS | F_OUT16, false);

    // ---- encoder (only r=0 outputs needed downstream) ----
    k_ln_h<<<TM / 8, 256>>>(tr_emb, lnb);
    run_big(lnb, 256, 0, wqkvh + 256, 768, 0, kv, 512, 0,
            TM, 512, 256, 1, nullptr, nullptr, 0, nullptr, 0, F_OUT16, false);
    run_big(lnb, 2048, 0, wqkvh, 768, 0, q0, 256, 0,
            TT, 256, 256, 1, nullptr, nullptr, 0, nullptr, 0, F_OUT16, false);
    k_attn<<<TT, 256>>>(q0, kv, o0);
    run_big(o0, 256, 0, woh, 256, 0, x1, 256, 0,
            TT, 256, 256, 1, nullptr, tr_emb, 2048, nullptr, 0, F_AUX, false);
    k_ln_f<<<TT / 8, 256>>>(x1, ln2);
    run_big(ln2, 256, 0, ff1h, 1024, 0, ffh, 1024, 0,
            TT, 1024, 256, 1, nullptr, nullptr, 0, nullptr, 0, F_RELU | F_OUT16, false);
    run_big(ffh, 1024, 0, ff2h, 256, 0, ffout, 256, 0,
            TT, 256, 1024, 1, nullptr, nullptr, 0, nullptr, 0, 0, false);
    k_feat0<<<ROWS1, 256>>>(tr_emb, x1, ffout, det_emb, feat0, x, detf);

    // ---- adjacency ----
    k_posvm<<<64, 256>>>(tracks, dets, tmarks, dmarks, pos, vm);
    k_adj<<<dim3(NN1, BB), 256>>>(pos, vm, adj);
    k_adjd<<<dim3(NNd, BB), 128>>>(pos, vm, adjd);

    // ---- main GAT x2 ----
    for (int l = 0; l < 2; l++) {
        run_big(x, 256, 0, gatWh + (size_t)l * 65536, 256, 0, hh, 256, 0,
                ROWS1, 256, 256, 1, nullptr, nullptr, 0, nullptr, 0, F_OUT16, false);
        k_srcdst<<<ROWS1, 256>>>(hh, gata + (size_t)l * 512, src, dstT, NN1);
        k_rowstat<<<dim3(NN1, BB), 128>>>(src, dstT, adj, stat, anum, NN1);
        agg_fused<<<dim3(1, NN1 / 128, BB * HH), 256>>>(anum, stat, hh, feat0, x, NN1);
    }

    // ---- main scores (dual xq/xk) ----
    run_big(x, 256, 0, clsWqh, 256, 0, xq, 256, 0,
            ROWS1, 256, 256, 2, nullptr, nullptr, 0, nullptr, 0, F_OUT16, false,
            clsWkh, xk, 1);
    run_big(xq, 256, (long long)NN1 * 256, xk, 256, (long long)NN1 * 256,
            out_scores, NN1, (long long)NN1 * NN1,
            NN1, NN1, 256, BB, nullptr, nullptr, 0,
            adj, (long long)NN1 * NN1, F_SIG, true);
    k_asso<<<(int)(((size_t)BB * 512 * 512) / 256), 256>>>(out_scores, out_asso);

    // ---- detection GAT x2 ----
    for (int l = 0; l < 2; l++) {
        const __half* xin = (l == 0) ? det_emb : x;
        run_big(xin, 256, 0, dgatWh + (size_t)l * 65536, 256, 0, hh, 256, 0,
                ND, 256, 256, 1, nullptr, nullptr, 0, nullptr, 0, F_OUT16, false);
        k_srcdst<<<ND, 256>>>(hh, dgata + (size_t)l * 512, src, dstT, NNd);
        k_rowstat<<<dim3(NNd, BB), 128>>>(src, dstT, adjd, stat, anum, NNd);
        agg_fused<<<dim3(1, NNd / 128, BB * HH), 256>>>(anum, stat, hh, detf, x, NNd);
    }

    // ---- detection scores (dual xq/xk) ----
    run_big(x, 256, 0, clsWqh + 65536, 256, 0, xq, 256, 0,
            ND, 256, 256, 2, nullptr, nullptr, 0, nullptr, 0, F_OUT16, false,
            clsWkh + 65536, xk, 1);
    run_big(xq, 256, (long long)NNd * 256, xk, 256, (long long)NNd * 256,
            out_det, NNd, (long long)NNd * NNd,
            NNd, NNd, 256, BB, nullptr, nullptr, 0,
            adjd, (long long)NNd * NNd, F_SIG | F_DIAG, true);
}

// round 14
// speedup vs baseline: 1.0481x; 1.0481x over previous
#include <cuda_runtime.h>
#include <cuda_fp16.h>
#include <math.h>
#include <stdint.h>

// ---------------------------------------------------------------------------
// Problem dims
// ---------------------------------------------------------------------------
#define BB 16
#define MM 512
#define NNd 512
#define RR 8
#define DD 256
#define HH 4
#define NN1 1024
#define TM  (BB*MM*RR)    // 65536
#define TT  (BB*MM)       // 8192
#define ND  (BB*NNd)      // 8192
#define ROWS1 (BB*NN1)    // 16384

#define F_BIAS 1
#define F_RELU 2
#define F_AUX  4
#define F_SIG  8
#define F_DIAG 16
#define F_OUT16 32

// ---------------------------------------------------------------------------
// Scratch
// ---------------------------------------------------------------------------
__device__ __half g_h1[(TM+ND)*DD];
__device__ __half g_emb[(TM+ND)*DD];
__device__ __half g_lnb[TM*DD];
__device__ __half g_kv[TM*512];
__device__ __half g_q0[TT*DD];
__device__ __half g_o0[TT*DD];
__device__ float  g_x1[TT*DD];
__device__ __half g_ln2[TT*DD];
__device__ __half g_ffh[TT*1024];
__device__ float  g_ffout[TT*DD];
__device__ float  g_feat0[ROWS1*DD];
__device__ float  g_detf[ND*DD];
__device__ __half g_x[ROWS1*DD];
__device__ __half g_hh[ROWS1*DD];
__device__ float g_src[ROWS1*HH];
__device__ float g_dstT[BB*HH*NN1];
__device__ float2 g_stat[BB*HH*NN1];
__device__ __half g_anum[(size_t)BB*HH*NN1*NN1];
__device__ unsigned char g_adj[(size_t)BB*NN1*NN1];
__device__ unsigned char g_adjd[(size_t)BB*NNd*NNd];
__device__ float g_pos[BB*NN1*2];
__device__ unsigned char g_vm[BB*NN1];
__device__ __half g_xq[ROWS1*DD];
__device__ __half g_xk[ROWS1*DD];
// fp16 weights
__device__ __half g_w2h[256*256];
__device__ __half g_wqkvh[256*768];
__device__ __half g_woh[256*256];
__device__ __half g_ff1h[256*1024];
__device__ __half g_ff2h[1024*256];
__device__ __half g_gatWh[2*256*256];
__device__ __half g_dgatWh[2*256*256];
__device__ __half g_clsWqh[2*256*256];
__device__ __half g_clsWkh[2*256*256];

// ---------------------------------------------------------------------------
// helpers
// ---------------------------------------------------------------------------
__device__ __forceinline__ uint32_t pk(float lo, float hi) {
    __half2 v = __floats2half2_rn(lo, hi);
    return *reinterpret_cast<uint32_t*>(&v);
}
__device__ __forceinline__ void mma_f16(float* c, const uint32_t* a, const uint32_t* b) {
    asm volatile(
        "mma.sync.aligned.m16n8k16.row.col.f32.f16.f16.f32 "
        "{%0,%1,%2,%3}, {%4,%5,%6,%7}, {%8,%9}, {%0,%1,%2,%3};\n"
        : "+f"(c[0]), "+f"(c[1]), "+f"(c[2]), "+f"(c[3])
        : "r"(a[0]), "r"(a[1]), "r"(a[2]), "r"(a[3]), "r"(b[0]), "r"(b[1]));
}
__device__ __forceinline__ void ldm_x4(uint32_t* r, uint32_t addr) {
    asm volatile("ldmatrix.sync.aligned.m8n8.x4.shared.b16 {%0,%1,%2,%3}, [%4];"
        : "=r"(r[0]), "=r"(r[1]), "=r"(r[2]), "=r"(r[3]) : "r"(addr));
}
__device__ __forceinline__ void ldm_x4_t(uint32_t* r, uint32_t addr) {
    asm volatile("ldmatrix.sync.aligned.m8n8.x4.trans.shared.b16 {%0,%1,%2,%3}, [%4];"
        : "=r"(r[0]), "=r"(r[1]), "=r"(r[2]), "=r"(r[3]) : "r"(addr));
}
__device__ __forceinline__ uint32_t cvs(const void* p) {
    return (uint32_t)__cvta_generic_to_shared(p);
}
__device__ __forceinline__ void cp16(uint32_t dst, const void* src) {
    asm volatile("cp.async.cg.shared.global [%0], [%1], 16;" :: "r"(dst), "l"(src));
}
__device__ __forceinline__ void cp8(uint32_t dst, const void* src) {
    asm volatile("cp.async.ca.shared.global [%0], [%1], 8;" :: "r"(dst), "l"(src));
}
__device__ __forceinline__ void cp4(uint32_t dst, const void* src) {
    asm volatile("cp.async.ca.shared.global [%0], [%1], 4;" :: "r"(dst), "l"(src));
}
#define CP_COMMIT() asm volatile("cp.async.commit_group;")
#define CP_WAIT1()  asm volatile("cp.async.wait_group 1;")
#define CP_WAIT0()  asm volatile("cp.async.wait_group 0;")

// combined weight fp32->fp16
struct WPack {
    const float* s[9];
    __half* d[9];
    int n[9];
};
__global__ void k_f2h_all(WPack p)
{
    int g = blockIdx.y;
    int i = (blockIdx.x * 256 + threadIdx.x) * 4;
    if (i >= p.n[g]) return;
    float4 v = *(const float4*)(p.s[g] + i);
    uint2 o;
    o.x = pk(v.x, v.y);
    o.y = pk(v.z, v.w);
    *(uint2*)(p.d[g] + i) = o;
}

// ---------------------------------------------------------------------------
// BIG GEMM (fp16, cp.async 3-stage): CTA 128x128, BK=16, 256 thr, warp 64x32.
// (R12 known-good version)
// ---------------------------------------------------------------------------
template<bool TRANSB, int FLAGS>
__global__ __launch_bounds__(256, 2)
void tgemm_big(const __half* __restrict__ A, int lda, long long sA,
               const __half* __restrict__ B, int ldb, long long sB,
               void* __restrict__ Cv, int ldc, long long sC,
               int K,
               const float* __restrict__ bias,
               const __half* __restrict__ aux, int auxld,
               const unsigned char* __restrict__ adjp, long long sAdj,
               const __half* __restrict__ B2, void* __restrict__ C2v, int dual)
{
    int bz = blockIdx.z;
    if (dual && bz) { B = B2; Cv = C2v; bz = 0; }
    A += (long long)bz * sA;
    B += (long long)bz * sB;
    size_t coff = (size_t)((long long)bz * sC);
    if (FLAGS & F_SIG) adjp += (long long)bz * sAdj;

    int m0 = blockIdx.y * 128, n0 = blockIdx.x * 128;

    __shared__ uint32_t As[3][1536];
    __shared__ uint32_t Bs[3][1536];

    int tid = threadIdx.x;
    int arow = tid >> 1, ahalf = tid & 1;
    const __half* gA = A + (size_t)(m0 + arow) * lda + ahalf * 8;

    const __half* gB;
    int kp = tid >> 5, nq = tid & 31;
    if (!TRANSB) gB = B + (size_t)(2 * kp) * ldb + n0 + nq * 4;
    else         gB = B + (size_t)(n0 + arow) * ldb + ahalf * 8;

    uint32_t aD = cvs(&As[0][arow * 12 + ahalf * 4]);
    uint32_t bD1, bD2;
    if (!TRANSB) {
        int w0 = (2 * kp) * 68 + nq * 2;
        bD1 = cvs(&Bs[0][w0]);
        bD2 = cvs(&Bs[0][w0 + 68]);
    } else {
        bD1 = cvs(&Bs[0][arow * 12 + ahalf * 4]);
        bD2 = 0;
    }

    int w = tid >> 5, l = tid & 31;
    int mbase = (w >> 2) * 64, nbase = (w & 3) * 32;
    int grp = l >> 2, tig = l & 3;

    int lrowA = ((l >> 3) & 1) * 8 + (l & 7);
    int khalf = l >> 4;
    uint32_t aBase[4];
    #pragma unroll
    for (int fm = 0; fm < 4; fm++)
        aBase[fm] = cvs(&As[0][(mbase + fm * 16 + lrowA) * 12 + khalf * 4]);
    uint32_t bBase[2];
    if (!TRANSB) {
        int krow = ((l >> 4) & 1) * 8 + (l & 7);
        int nblk = ((l >> 3) & 1) * 8;
        #pragma unroll
        for (int fp = 0; fp < 2; fp++)
            bBase[fp] = cvs(&Bs[0][krow * 68 + ((nbase + fp * 16 + nblk) >> 1)]);
    } else {
        #pragma unroll
        for (int fp = 0; fp < 2; fp++)
            bBase[fp] = cvs(&Bs[0][(nbase + fp * 16 + lrowA) * 12 + khalf * 4]);
    }

    float acc[4][4][4];
    #pragma unroll
    for (int i = 0; i < 4; i++)
        #pragma unroll
        for (int j = 0; j < 4; j++)
            #pragma unroll
            for (int q = 0; q < 4; q++) acc[i][j][q] = 0.f;

    int nk = K >> 4;

    // prologue: issue stages 0 and 1
    {
        cp16(aD, gA);
        if (!TRANSB) {
            cp8(bD1, gB);
            cp8(bD2, gB + ldb);
        } else {
            cp16(bD1, gB);
        }
        CP_COMMIT();
        if (nk > 1) {
            cp16(aD + 6144, gA + 16);
            if (!TRANSB) {
                cp8(bD1 + 6144, gB + (size_t)16 * ldb);
                cp8(bD2 + 6144, gB + (size_t)17 * ldb);
            } else {
                cp16(bD1 + 6144, gB + 16);
            }
            CP_COMMIT();
        }
    }

    int s = 0;
    for (int i = 0; i < nk; i++) {
        if (i + 1 < nk) CP_WAIT1(); else CP_WAIT0();
        __syncthreads();
        uint32_t soff = (uint32_t)(s * 6144);
        uint32_t af[4][4];
        #pragma unroll
        for (int fm = 0; fm < 4; fm++) ldm_x4(af[fm], aBase[fm] + soff);
        uint32_t bfr[4][2];
        #pragma unroll
        for (int fp = 0; fp < 2; fp++) {
            uint32_t t4[4];
            if (!TRANSB) ldm_x4_t(t4, bBase[fp] + soff);
            else         ldm_x4(t4, bBase[fp] + soff);
            bfr[fp * 2][0] = t4[0]; bfr[fp * 2 + 1][0] = t4[1];
            bfr[fp * 2][1] = t4[2]; bfr[fp * 2 + 1][1] = t4[3];
        }
        #pragma unroll
        for (int fm = 0; fm < 4; fm++)
            #pragma unroll
            for (int fn = 0; fn < 4; fn++)
                mma_f16(acc[fm][fn], af[fm], bfr[fn]);
        if (i + 2 < nk) {
            int st = s >= 1 ? s - 1 : s + 2;   // (s+2)%3
            uint32_t toff = (uint32_t)(st * 6144);
            int k0 = (i + 2) * 16;
            cp16(aD + toff, gA + k0);
            if (!TRANSB) {
                cp8(bD1 + toff, gB + (size_t)k0 * ldb);
                cp8(bD2 + toff, gB + (size_t)(k0 + 1) * ldb);
            } else {
                cp16(bD1 + toff, gB + k0);
            }
            CP_COMMIT();
        }
        s = (s + 1) == 3 ? 0 : s + 1;
    }

    // epilogue
    #pragma unroll
    for (int fm = 0; fm < 4; fm++) {
        int row0 = m0 + mbase + fm * 16 + grp;
        #pragma unroll
        for (int fn = 0; fn < 4; fn++) {
            int col = n0 + nbase + fn * 8 + 2 * tig;
            float v0 = acc[fm][fn][0], v1 = acc[fm][fn][1];
            float v2 = acc[fm][fn][2], v3 = acc[fm][fn][3];
            if (FLAGS & F_BIAS) {
                float bb0 = bias[col], bb1 = bias[col + 1];
                v0 += bb0; v1 += bb1; v2 += bb0; v3 += bb1;
            }
            if (FLAGS & F_RELU) {
                v0 = fmaxf(v0, 0.f); v1 = fmaxf(v1, 0.f);
                v2 = fmaxf(v2, 0.f); v3 = fmaxf(v3, 0.f);
            }
            if (FLAGS & F_AUX) {
                float2 a0 = __half22float2(*(const __half2*)(aux + (size_t)row0 * auxld + col));
                float2 a8 = __half22float2(*(const __half2*)(aux + (size_t)(row0 + 8) * auxld + col));
                v0 += a0.x; v1 += a0.y; v2 += a8.x; v3 += a8.y;
            }
            if (FLAGS & F_SIG) {
                const unsigned char* q0p = adjp + (size_t)row0 * ldc + col;
                const unsigned char* q8p = adjp + (size_t)(row0 + 8) * ldc + col;
                v0 = q0p[0] ? 1.f / (1.f + __expf(-v0 * 0.0625f)) : 0.f;
                v1 = q0p[1] ? 1.f / (1.f + __expf(-v1 * 0.0625f)) : 0.f;
                v2 = q8p[0] ? 1.f / (1.f + __expf(-v2 * 0.0625f)) : 0.f;
                v3 = q8p[1] ? 1.f / (1.f + __expf(-v3 * 0.0625f)) : 0.f;
                if (FLAGS & F_DIAG) {
                    if (row0 == col) v0 = 0.f;
                    if (row0 == col + 1) v1 = 0.f;
                    if (row0 + 8 == col) v2 = 0.f;
                    if (row0 + 8 == col + 1) v3 = 0.f;
                }
            }
            if (FLAGS & F_OUT16) {
                __half* Ch = (__half*)Cv + coff;
                *(uint32_t*)&Ch[(size_t)row0 * ldc + col] = pk(v0, v1);
                *(uint32_t*)&Ch[(size_t)(row0 + 8) * ldc + col] = pk(v2, v3);
            } else {
                float* C = (float*)Cv + coff;
                *(float2*)&C[(size_t)row0 * ldc + col] = make_float2(v0, v1);
                *(float2*)&C[(size_t)(row0 + 8) * ldc + col] = make_float2(v2, v3);
            }
        }
    }
}

// ---------------------------------------------------------------------------
// GAT aggregation (fp16 GEMM, cp.async 3-stage): CTA 128x64, warp 32x32.
// (R12 known-good version)
// ---------------------------------------------------------------------------
__global__ __launch_bounds__(256)
void agg_fused(const __half* __restrict__ anum, const float2* __restrict__ stat,
               const __half* __restrict__ hmat,
               const float* __restrict__ aux, __half* __restrict__ xout, int NN)
{
    int z = blockIdx.z;
    int b = z >> 2, h = z & 3;
    const __half* B = hmat + (size_t)b * NN * 256 + h * 64;
    __half* C = xout + (size_t)b * NN * 256 + h * 64;
    const float* auxp = aux + (size_t)b * NN * 256 + h * 64;
    const float2* statz = stat + (size_t)z * NN;

    int m0 = blockIdx.y * 128;
    __shared__ uint32_t As[3][1536];
    __shared__ uint32_t Bs[3][576];
    int tid = threadIdx.x;

    int arow = tid >> 1, ahalf = tid & 1;
    const __half* gA = anum + ((size_t)z * NN + m0 + arow) * NN + ahalf * 8;

    int kp = tid >> 5, nq = tid & 31;
    const __half* gB = B + (size_t)(2 * kp) * 256 + 2 * nq;

    uint32_t aD = cvs(&As[0][arow * 12 + ahalf * 4]);
    uint32_t bD1 = cvs(&Bs[0][(2 * kp) * 36 + nq]);
    uint32_t bD2 = cvs(&Bs[0][(2 * kp + 1) * 36 + nq]);

    int w = tid >> 5, l = tid & 31;
    int wm = w >> 1, wn = w & 1;
    int mrow = wm * 32, ncol = wn * 32;
    int grp = l >> 2, tig = l & 3;

    int lrowA = ((l >> 3) & 1) * 8 + (l & 7);
    int khalf = l >> 4;
    uint32_t aBase[2];
    #pragma unroll
    for (int fm = 0; fm < 2; fm++)
        aBase[fm] = cvs(&As[0][(mrow + fm * 16 + lrowA) * 12 + khalf * 4]);
    int krow = ((l >> 4) & 1) * 8 + (l & 7);
    int nblk = ((l >> 3) & 1) * 8;
    uint32_t bBase[2];
    #pragma unroll
    for (int fp = 0; fp < 2; fp++)
        bBase[fp] = cvs(&Bs[0][krow * 36 + ((ncol + fp * 16 + nblk) >> 1)]);

    float acc[2][4][4];
    #pragma unroll
    for (int i = 0; i < 2; i++)
        #pragma unroll
        for (int j = 0; j < 4; j++)
            #pragma unroll
            for (int q = 0; q < 4; q++) acc[i][j][q] = 0.f;

    int nk = NN >> 4;

    // prologue
    {
        cp16(aD, gA);
        cp4(bD1, gB);
        cp4(bD2, gB + 256);
        CP_COMMIT();
        if (nk > 1) {
            cp16(aD + 6144, gA + 16);
            cp4(bD1 + 2304, gB + 16 * 256);
            cp4(bD2 + 2304, gB + 17 * 256);
            CP_COMMIT();
        }
    }

    int s = 0;
    for (int i = 0; i < nk; i++) {
        if (i + 1 < nk) CP_WAIT1(); else CP_WAIT0();
        __syncthreads();
        uint32_t sa = (uint32_t)(s * 6144);
        uint32_t sbo = (uint32_t)(s * 2304);
        uint32_t af[2][4];
        #pragma unroll
        for (int fm = 0; fm < 2; fm++) ldm_x4(af[fm], aBase[fm] + sa);
        uint32_t bfr[4][2];
        #pragma unroll
        for (int fp = 0; fp < 2; fp++) {
            uint32_t t4[4];
            ldm_x4_t(t4, bBase[fp] + sbo);
            bfr[fp * 2][0] = t4[0]; bfr[fp * 2 + 1][0] = t4[1];
            bfr[fp * 2][1] = t4[2]; bfr[fp * 2 + 1][1] = t4[3];
        }
        #pragma unroll
        for (int fm = 0; fm < 2; fm++)
            #pragma unroll
            for (int fn = 0; fn < 4; fn++)
                mma_f16(acc[fm][fn], af[fm], bfr[fn]);
        if (i + 2 < nk) {
            int st = s >= 1 ? s - 1 : s + 2;
            int k0 = (i + 2) * 16;
            cp16(aD + st * 6144, gA + k0);
            cp4(bD1 + st * 2304, gB + (size_t)k0 * 256);
            cp4(bD2 + st * 2304, gB + (size_t)(k0 + 1) * 256);
            CP_COMMIT();
        }
        s = (s + 1) == 3 ? 0 : s + 1;
    }

    #pragma unroll
    for (int fm = 0; fm < 2; fm++) {
        int row = m0 + mrow + fm * 16 + grp;
        float inv0 = statz[row].y;
        float inv8 = statz[row + 8].y;
        #pragma unroll
        for (int fn = 0; fn < 4; fn++) {
            int col = ncol + fn * 8 + 2 * tig;
            float v0 = acc[fm][fn][0] * inv0, v1 = acc[fm][fn][1] * inv0;
            float v2 = acc[fm][fn][2] * inv8, v3 = acc[fm][fn][3] * inv8;
            v0 = (v0 > 0.f) ? v0 : expm1f(v0);
            v1 = (v1 > 0.f) ? v1 : expm1f(v1);
            v2 = (v2 > 0.f) ? v2 : expm1f(v2);
            v3 = (v3 > 0.f) ? v3 : expm1f(v3);
            float2 x0 = *(const float2*)&auxp[(size_t)row * 256 + col];
            float2 x1 = *(const float2*)&auxp[(size_t)(row + 8) * 256 + col];
            *(uint32_t*)&C[(size_t)row * 256 + col] =
                pk(0.5f * v0 + 0.5f * x0.x, 0.5f * v1 + 0.5f * x0.y);
            *(uint32_t*)&C[(size_t)(row + 8) * 256 + col] =
                pk(0.5f * v2 + 0.5f * x1.x, 0.5f * v3 + 0.5f * x1.y);
        }
    }
}

// ---------------------------------------------------------------------------
// Small kernels
// ---------------------------------------------------------------------------
// merged tr+det feature layer1
__global__ void k_feat1(const float* __restrict__ tr, const float* __restrict__ de,
                        const float* __restrict__ W1, const float* __restrict__ b1,
                        __half* __restrict__ out)
{
    int tid = threadIdx.x;
    size_t row = (size_t)blockIdx.x * 4 + (tid >> 6);
    int c4 = (tid & 63) * 4;
    const float* xr = (row < TM) ? (tr + row * 4) : (de + (row - TM) * 4);
    const float4 x4 = *(const float4*)xr;
    float4 v = *(const float4*)(b1 + c4);
    float4 w0 = *(const float4*)(W1 + c4);
    float4 w1 = *(const float4*)(W1 + 256 + c4);
    float4 w2 = *(const float4*)(W1 + 512 + c4);
    float4 w3 = *(const float4*)(W1 + 768 + c4);
    v.x += x4.x * w0.x + x4.y * w1.x + x4.z * w2.x + x4.w * w3.x;
    v.y += x4.x * w0.y + x4.y * w1.y + x4.z * w2.y + x4.w * w3.y;
    v.z += x4.x * w0.z + x4.y * w1.z + x4.z * w2.z + x4.w * w3.z;
    v.w += x4.x * w0.w + x4.y * w1.w + x4.z * w2.w + x4.w * w3.w;
    v.x = (v.x > 0.f) ? v.x : (__expf(v.x) - 1.f);
    v.y = (v.y > 0.f) ? v.y : (__expf(v.y) - 1.f);
    v.z = (v.z > 0.f) ? v.z : (__expf(v.z) - 1.f);
    v.w = (v.w > 0.f) ? v.w : (__expf(v.w) - 1.f);
    uint2 p;
    p.x = pk(v.x, v.y);
    p.y = pk(v.z, v.w);
    *(uint2*)(out + row * 256 + c4) = p;
}

__global__ void k_ln_h(const __half* __restrict__ in, __half* __restrict__ out)
{
    int w = threadIdx.x >> 5, lane = threadIdx.x & 31;
    size_t row = (size_t)blockIdx.x * 8 + w;
    const uint4* ip = (const uint4*)(in + row * 256);
    uint4 u = ip[lane];
    float2 f0 = __half22float2(*(__half2*)&u.x);
    float2 f1 = __half22float2(*(__half2*)&u.y);
    float2 f2 = __half22float2(*(__half2*)&u.z);
    float2 f3 = __half22float2(*(__half2*)&u.w);
    float a = f0.x + f0.y + f1.x + f1.y + f2.x + f2.y + f3.x + f3.y;
    float b = f0.x*f0.x + f0.y*f0.y + f1.x*f1.x + f1.y*f1.y
            + f2.x*f2.x + f2.y*f2.y + f3.x*f3.x + f3.y*f3.y;
    #pragma unroll
    for (int o = 16; o; o >>= 1) {
        a += __shfl_xor_sync(0xffffffff, a, o);
        b += __shfl_xor_sync(0xffffffff, b, o);
    }
    float mean = a * (1.f / 256.f);
    float var = b * (1.f / 256.f) - mean * mean;
    float rstd = rsqrtf(var + 1e-5f);
    uint4 r;
    r.x = pk((f0.x - mean) * rstd, (f0.y - mean) * rstd);
    r.y = pk((f1.x - mean) * rstd, (f1.y - mean) * rstd);
    r.z = pk((f2.x - mean) * rstd, (f2.y - mean) * rstd);
    r.w = pk((f3.x - mean) * rstd, (f3.y - mean) * rstd);
    ((uint4*)(out + row * 256))[lane] = r;
}

__global__ void k_ln_f(const float* __restrict__ in, __half* __restrict__ out)
{
    int w = threadIdx.x >> 5, lane = threadIdx.x & 31;
    size_t row = (size_t)blockIdx.x * 8 + w;
    const float4* ip = (const float4*)(in + row * 256);
    float4 v0 = ip[lane], v1 = ip[lane + 32];
    float a = v0.x + v0.y + v0.z + v0.w + v1.x + v1.y + v1.z + v1.w;
    float b = v0.x*v0.x + v0.y*v0.y + v0.z*v0.z + v0.w*v0.w
            + v1.x*v1.x + v1.y*v1.y + v1.z*v1.z + v1.w*v1.w;
    #pragma unroll
    for (int o = 16; o; o >>= 1) {
        a += __shfl_xor_sync(0xffffffff, a, o);
        b += __shfl_xor_sync(0xffffffff, b, o);
    }
    float mean = a * (1.f / 256.f);
    float var = b * (1.f / 256.f) - mean * mean;
    float rstd = rsqrtf(var + 1e-5f);
    uint2 p0, p1;
    p0.x = pk((v0.x - mean) * rstd, (v0.y - mean) * rstd);
    p0.y = pk((v0.z - mean) * rstd, (v0.w - mean) * rstd);
    p1.x = pk((v1.x - mean) * rstd, (v1.y - mean) * rstd);
    p1.y = pk((v1.z - mean) * rstd, (v1.w - mean) * rstd);
    *(uint2*)(out + row * 256 + lane * 4) = p0;
    *(uint2*)(out + row * 256 + 128 + lane * 4) = p1;
}

__global__ void k_attn(const __half* __restrict__ q0, const __half* __restrict__ kv,
                       __half* __restrict__ o0)
{
    size_t t = blockIdx.x;
    int d = threadIdx.x;
    int w = d >> 5, lane = d & 31, h = d >> 6;
    __shared__ float red[8][8];
    const __half* kvb = kv + t * 8 * 512;
    float qd = __half2float(q0[t * 256 + d]);
    #pragma unroll
    for (int s = 0; s < 8; s++) {
        float v = qd * __half2float(kvb[s * 512 + d]);
        #pragma unroll
        for (int o = 16; o; o >>= 1) v += __shfl_xor_sync(0xffffffff, v, o);
        if (lane == 0) red[w][s] = v;
    }
    __syncthreads();
    float lg[8];
    float m = -1e30f;
    #pragma unroll
    for (int s = 0; s < 8; s++) {
        lg[s] = (red[2 * h][s] + red[2 * h + 1][s]) * 0.125f;
        m = fmaxf(m, lg[s]);
    }
    float sum = 0.f;
    #pragma unroll
    for (int s = 0; s < 8; s++) { lg[s] = __expf(lg[s] - m); sum += lg[s]; }
    float inv = 1.f / sum;
    float o = 0.f;
    #pragma unroll
    for (int s = 0; s < 8; s++) o += lg[s] * inv * __half2float(kvb[s * 512 + 256 + d]);
    o0[t * 256 + d] = __float2half(o);
}

// feat0 vectorized: 4 rows/block, 4 cols/thread
__global__ void k_feat0(const __half* __restrict__ tr_emb, const float* __restrict__ x1,
                        const float* __restrict__ ffout, const __half* __restrict__ det_emb,
                        float* __restrict__ feat0, __half* __restrict__ x,
                        float* __restrict__ detf)
{
    int tid = threadIdx.x;
    size_t row = (size_t)blockIdx.x * 4 + (tid >> 6);
    int c4 = (tid & 63) * 4;
    int i = (int)(row & 1023);
    int b = (int)(row >> 10);
    float4 v;
    if (i < 512) {
        size_t t = (size_t)b * 512 + i;
        uint2 te = *(const uint2*)(tr_emb + t * 2048 + c4);
        float2 e01 = __half22float2(*(__half2*)&te.x);
        float2 e23 = __half22float2(*(__half2*)&te.y);
        float4 a = *(const float4*)(x1 + t * 256 + c4);
        float4 f = *(const float4*)(ffout + t * 256 + c4);
        v.x = e01.x + 0.9f * (a.x + f.x);
        v.y = e01.y + 0.9f * (a.y + f.y);
        v.z = e23.x + 0.9f * (a.z + f.z);
        v.w = e23.y + 0.9f * (a.w + f.w);
    } else {
        size_t t = (size_t)b * 512 + (i - 512);
        uint2 de = *(const uint2*)(det_emb + t * 256 + c4);
        float2 e01 = __half22float2(*(__half2*)&de.x);
        float2 e23 = __half22float2(*(__half2*)&de.y);
        v = make_float4(e01.x, e01.y, e23.x, e23.y);
        *(float4*)(detf + t * 256 + c4) = v;
    }
    *(float4*)(feat0 + row * 256 + c4) = v;
    uint2 p;
    p.x = pk(v.x, v.y);
    p.y = pk(v.z, v.w);
    *(uint2*)(x + row * 256 + c4) = p;
}

__global__ void k_posvm(const float* __restrict__ tracks, const float* __restrict__ dets,
                        const int* __restrict__ tmarks, const int* __restrict__ dmarks,
                        float* __restrict__ pos, unsigned char* __restrict__ vm)
{
    int idx = blockIdx.x * 256 + threadIdx.x;
    if (idx >= BB * NN1) return;
    int b = idx >> 10, i = idx & 1023;
    float x, y; unsigned char v;
    if (i < 512) {
        const float* p = tracks + ((size_t)(b * 512 + i)) * 8 * 4;
        x = p[0]; y = p[1];
        v = (i < tmarks[b]);
    } else {
        int n = i - 512;
        const float* p = dets + ((size_t)(b * 512 + n)) * 4;
        x = p[0]; y = p[1];
        v = (n < dmarks[b]);
    }
    pos[idx * 2] = x; pos[idx * 2 + 1] = y; vm[idx] = v;
}

__global__ void k_adj(const float* __restrict__ pos, const unsigned char* __restrict__ vm,
                      unsigned char* __restrict__ adj)
{
    int i = blockIdx.x, b = blockIdx.y;
    size_t base = (size_t)b * NN1;
    const float2* p2 = (const float2*)pos;
    float2 pi = p2[base + i];
    unsigned char vi = vm[base + i];
    int j0 = threadIdx.x * 4;
    uchar4 r;
    unsigned char* rp = &r.x;
    #pragma unroll
    for (int u = 0; u < 4; u++) {
        int j = j0 + u;
        float2 pj = p2[base + j];
        float dx = pi.x - pj.x, dy = pi.y - pj.y;
        rp[u] = (unsigned char)((dx * dx + dy * dy < 4.0f) && vi && vm[base + j]);
    }
    ((uchar4*)(adj + ((size_t)b * NN1 + i) * NN1))[threadIdx.x] = r;
}

__global__ void k_adjd(const float* __restrict__ pos, const unsigned char* __restrict__ vm,
                       unsigned char* __restrict__ adjd)
{
    int i = blockIdx.x, b = blockIdx.y;
    size_t base = (size_t)b * NN1 + 512;
    const float2* p2 = (const float2*)pos;
    float2 pi = p2[base + i];
    unsigned char vi = vm[base + i];
    int j0 = threadIdx.x * 4;
    uchar4 r;
    unsigned char* rp = &r.x;
    #pragma unroll
    for (int u = 0; u < 4; u++) {
        int j = j0 + u;
        float2 pj = p2[base + j];
        float dx = pi.x - pj.x, dy = pi.y - pj.y;
        rp[u] = (unsigned char)((dx * dx + dy * dy < 4.0f) && vi && vm[base + j]);
    }
    ((uchar4*)(adjd + ((size_t)b * NNd + i) * NNd))[threadIdx.x] = r;
}

// src/dst projections: warp per row, 8 rows/block. Head h = lanes 8h..8h+7.
__global__ void k_srcdst(const __half* __restrict__ Hm, const float* __restrict__ a0,
                         float* __restrict__ src, float* __restrict__ dstT, int NN)
{
    int w = threadIdx.x >> 5, lane = threadIdx.x & 31;
    size_t row = (size_t)blockIdx.x * 8 + w;
    uint4 u = ((const uint4*)(Hm + row * 256))[lane];   // 8 halves: dims 8*lane..+7
    float2 f0 = __half22float2(*(__half2*)&u.x);
    float2 f1 = __half22float2(*(__half2*)&u.y);
    float2 f2 = __half22float2(*(__half2*)&u.z);
    float2 f3 = __half22float2(*(__half2*)&u.w);
    const float4* s0p = (const float4*)(a0 + lane * 8);
    const float4* s1p = (const float4*)(a0 + 256 + lane * 8);
    float4 sa = s0p[0], sb = s0p[1];
    float4 ta = s1p[0], tb = s1p[1];
    float s = f0.x * sa.x + f0.y * sa.y + f1.x * sa.z + f1.y * sa.w
            + f2.x * sb.x + f2.y * sb.y + f3.x * sb.z + f3.y * sb.w;
    float t = f0.x * ta.x + f0.y * ta.y + f1.x * ta.z + f1.y * ta.w
            + f2.x * tb.x + f2.y * tb.y + f3.x * tb.z + f3.y * tb.w;
    #pragma unroll
    for (int o = 4; o; o >>= 1) {
        s += __shfl_xor_sync(0xffffffff, s, o);
        t += __shfl_xor_sync(0xffffffff, t, o);
    }
    if ((lane & 7) == 0) {
        int h = lane >> 3;
        int b = (int)(row / NN);
        int i = (int)(row - (size_t)b * NN);
        src[row * 4 + h] = s;
        dstT[((size_t)b * 4 + h) * NN + i] = t;
    }
}

__global__ void k_rowstat(const float* __restrict__ src, const float* __restrict__ dstT,
                          const unsigned char* __restrict__ adj, float2* __restrict__ stat,
                          __half* __restrict__ anum, int NN)
{
    int i = blockIdx.x, b = blockIdx.y;
    int h = threadIdx.x >> 5, lane = threadIdx.x & 31;
    int z = b * 4 + h;
    float s = src[((size_t)b * NN + i) * 4 + h];
    const uchar4* adjrow = (const uchar4*)(adj + ((size_t)b * NN + i) * NN);
    const float4* dsth = (const float4*)(dstT + ((size_t)z) * NN);
    __half* arow = anum + ((size_t)z * NN + i) * NN;
    int nq = NN >> 2;
    float mx = -1e30f;
    for (int jq = lane; jq < nq; jq += 32) {
        uchar4 a4 = adjrow[jq];
        float4 d4 = dsth[jq];
        float e0 = s + d4.x; e0 = e0 > 0.f ? e0 : 0.2f * e0; e0 = a4.x ? e0 : -1e9f;
        float e1 = s + d4.y; e1 = e1 > 0.f ? e1 : 0.2f * e1; e1 = a4.y ? e1 : -1e9f;
        float e2 = s + d4.z; e2 = e2 > 0.f ? e2 : 0.2f * e2; e2 = a4.z ? e2 : -1e9f;
        float e3 = s + d4.w; e3 = e3 > 0.f ? e3 : 0.2f * e3; e3 = a4.w ? e3 : -1e9f;
        mx = fmaxf(mx, fmaxf(fmaxf(e0, e1), fmaxf(e2, e3)));
    }
    #pragma unroll
    for (int o = 16; o; o >>= 1) mx = fmaxf(mx, __shfl_xor_sync(0xffffffff, mx, o));
    float sum = 0.f;
    for (int jq = lane; jq < nq; jq += 32) {
        uchar4 a4 = adjrow[jq];
        float4 d4 = dsth[jq];
        float e0 = s + d4.x; e0 = e0 > 0.f ? e0 : 0.2f * e0; e0 = a4.x ? e0 : -1e9f;
        float e1 = s + d4.y; e1 = e1 > 0.f ? e1 : 0.2f * e1; e1 = a4.y ? e1 : -1e9f;
        float e2 = s + d4.z; e2 = e2 > 0.f ? e2 : 0.2f * e2; e2 = a4.z ? e2 : -1e9f;
        float e3 = s + d4.w; e3 = e3 > 0.f ? e3 : 0.2f * e3; e3 = a4.w ? e3 : -1e9f;
        float n0 = __expf(e0 - mx), n1 = __expf(e1 - mx);
        float n2 = __expf(e2 - mx), n3 = __expf(e3 - mx);
        sum += n0 + n1 + n2 + n3;
        uint2 pkd;
        pkd.x = pk(n0, n1);
        pkd.y = pk(n2, n3);
        *(uint2*)(arow + jq * 4) = pkd;
    }
    #pragma unroll
    for (int o = 16; o; o >>= 1) sum += __shfl_xor_sync(0xffffffff, sum, o);
    if (lane == 0)
        stat[(size_t)z * NN + i] = make_float2(mx, 1.f / sum);
}

// asso gather, float4
__global__ void k_asso(const float* __restrict__ scores, float* __restrict__ out)
{
    size_t q = (size_t)blockIdx.x * 256 + threadIdx.x;
    int j4 = (int)(q & 127) * 4;
    size_t r = q >> 7;
    int m = (int)(r & 511);
    int b = (int)(r >> 9);
    float4 v = *(const float4*)&scores[(((size_t)b * 1024 + m) * 1024) + 512 + j4];
    *(float4*)&out[r * 512 + j4] = v;
}

// ---------------------------------------------------------------------------
// Host side
// ---------------------------------------------------------------------------
static void run_big(const __half* A, int lda, long long sA,
                    const __half* B, int ldb, long long sB,
                    void* C, int ldc, long long sC,
                    int M, int N, int K, int batch,
                    const float* bias, const __half* aux, int auxld,
                    const unsigned char* adjp, long long sAdj,
                    int flags, bool transb,
                    const __half* B2 = nullptr, void* C2 = nullptr, int dual = 0)
{
    dim3 g(N / 128, M / 128, batch);
#define CALLBIG(T, F) tgemm_big<T, F><<<g, 256>>>(A, lda, sA, B, ldb, sB, \
        C, ldc, sC, K, bias, aux, auxld, adjp, sAdj, B2, C2, dual)
    if (!transb) {
        if (flags == (F_BIAS | F_OUT16))      CALLBIG(false, F_BIAS | F_OUT16);
        else if (flags == F_OUT16)            CALLBIG(false, F_OUT16);
        else if (flags == F_AUX)              CALLBIG(false, F_AUX);
        else if (flags == (F_RELU | F_OUT16)) CALLBIG(false, F_RELU | F_OUT16);
        else                                  CALLBIG(false, 0);
    } else {
        if (flags == F_SIG)                   CALLBIG(true, F_SIG);
        else                                  CALLBIG(true, F_SIG | F_DIAG);
    }
#undef CALLBIG
}

#define SYM(p, s) cudaGetSymbolAddress((void**)&p, s)

extern "C" void kernel_launch(void* const* d_in, const int* in_sizes, int n_in,
                              void* d_out, int out_size)
{
    (void)in_sizes; (void)n_in; (void)out_size;
    const float* tracks = (const float*)d_in[0];
    const float* dets   = (const float*)d_in[1];
    const int* tmarks   = (const int*)d_in[2];
    const int* dmarks   = (const int*)d_in[3];
    const float* W1     = (const float*)d_in[4];
    const float* b1     = (const float*)d_in[5];
    const float* W2     = (const float*)d_in[6];
    const float* b2     = (const float*)d_in[7];
    const float* Wqkv   = (const float*)d_in[8];
    const float* Wo     = (const float*)d_in[9];
    const float* ff1    = (const float*)d_in[10];
    const float* ff2    = (const float*)d_in[11];
    const float* gatW   = (const float*)d_in[12];
    const float* gata   = (const float*)d_in[13];
    const float* dgatW  = (const float*)d_in[14];
    const float* dgata  = (const float*)d_in[15];
    const float* clsWq  = (const float*)d_in[16];
    const float* clsWk  = (const float*)d_in[17];

    float* out = (float*)d_out;
    float* out_scores = out;
    float* out_det    = out + (size_t)BB * NN1 * NN1;
    float* out_asso   = out_det + (size_t)BB * NNd * NNd;

    __half *h1, *emb, *lnb, *kv, *q0, *o0, *ln2, *ffh, *x, *hh, *xq, *xk, *anum;
    __half *w2h, *wqkvh, *woh, *ff1h, *ff2h, *gatWh, *dgatWh, *clsWqh, *clsWkh;
    float *x1, *ffout, *feat0, *detf, *src, *dstT, *pos;
    float2* stat;
    unsigned char *adj, *adjd, *vm;
    SYM(h1, g_h1);         SYM(emb, g_emb);       SYM(lnb, g_lnb);
    SYM(kv, g_kv);         SYM(q0, g_q0);         SYM(o0, g_o0);
    SYM(x1, g_x1);         SYM(ln2, g_ln2);       SYM(ffh, g_ffh);
    SYM(ffout, g_ffout);   SYM(feat0, g_feat0);   SYM(detf, g_detf);
    SYM(x, g_x);           SYM(hh, g_hh);         SYM(src, g_src);
    SYM(dstT, g_dstT);     SYM(stat, g_stat);     SYM(anum, g_anum);
    SYM(adj, g_adj);       SYM(adjd, g_adjd);     SYM(pos, g_pos);
    SYM(vm, g_vm);         SYM(xq, g_xq);         SYM(xk, g_xk);
    SYM(w2h, g_w2h);       SYM(wqkvh, g_wqkvh);   SYM(woh, g_woh);
    SYM(ff1h, g_ff1h);     SYM(ff2h, g_ff2h);     SYM(gatWh, g_gatWh);
    SYM(dgatWh, g_dgatWh); SYM(clsWqh, g_clsWqh); SYM(clsWkh, g_clsWkh);

    __half* tr_emb = emb;
    __half* det_emb = emb + (size_t)TM * DD;

    // ---- weight fp32 -> fp16, one launch ----
    {
        WPack p;
        p.s[0] = W2;    p.d[0] = w2h;    p.n[0] = 65536;
        p.s[1] = Wqkv;  p.d[1] = wqkvh;  p.n[1] = 196608;
        p.s[2] = Wo;    p.d[2] = woh;    p.n[2] = 65536;
        p.s[3] = ff1;   p.d[3] = ff1h;   p.n[3] = 262144;
        p.s[4] = ff2;   p.d[4] = ff2h;   p.n[4] = 262144;
        p.s[5] = gatW;  p.d[5] = gatWh;  p.n[5] = 131072;
        p.s[6] = dgatW; p.d[6] = dgatWh; p.n[6] = 131072;
        p.s[7] = clsWq; p.d[7] = clsWqh; p.n[7] = 131072;
        p.s[8] = clsWk; p.d[8] = clsWkh; p.n[8] = 131072;
        k_f2h_all<<<dim3(256, 9), 256>>>(p);
    }

    // ---- feature MLP (merged tr+det) ----
    k_feat1<<<(TM + ND) / 4, 256>>>(tracks, dets, W1, b1, h1);
    run_big(h1, 256, 0, w2h, 256, 0, emb, 256, 0,
            TM + ND, 256, 256, 1, b2, nullptr, 0, nullptr, 0, F_BIAS | F_OUT16, false);

    // ---- encoder (only r=0 outputs needed downstream) ----
    k_ln_h<<<TM / 8, 256>>>(tr_emb, lnb);
    run_big(lnb, 256, 0, wqkvh + 256, 768, 0, kv, 512, 0,
            TM, 512, 256, 1, nullptr, nullptr, 0, nullptr, 0, F_OUT16, false);
    run_big(lnb, 2048, 0, wqkvh, 768, 0, q0, 256, 0,
            TT, 256, 256, 1, nullptr, nullptr, 0, nullptr, 0, F_OUT16, false);
    k_attn<<<TT, 256>>>(q0, kv, o0);
    run_big(o0, 256, 0, woh, 256, 0, x1, 256, 0,
            TT, 256, 256, 1, nullptr, tr_emb, 2048, nullptr, 0, F_AUX, false);
    k_ln_f<<<TT / 8, 256>>>(x1, ln2);
    run_big(ln2, 256, 0, ff1h, 1024, 0, ffh, 1024, 0,
            TT, 1024, 256, 1, nullptr, nullptr, 0, nullptr, 0, F_RELU | F_OUT16, false);
    run_big(ffh, 1024, 0, ff2h, 256, 0, ffout, 256, 0,
            TT, 256, 1024, 1, nullptr, nullptr, 0, nullptr, 0, 0, false);
    k_feat0<<<ROWS1 / 4, 256>>>(tr_emb, x1, ffout, det_emb, feat0, x, detf);

    // ---- adjacency ----
    k_posvm<<<64, 256>>>(tracks, dets, tmarks, dmarks, pos, vm);
    k_adj<<<dim3(NN1, BB), 256>>>(pos, vm, adj);
    k_adjd<<<dim3(NNd, BB), 128>>>(pos, vm, adjd);

    // ---- main GAT x2 ----
    for (int l = 0; l < 2; l++) {
        run_big(x, 256, 0, gatWh + (size_t)l * 65536, 256, 0, hh, 256, 0,
                ROWS1, 256, 256, 1, nullptr, nullptr, 0, nullptr, 0, F_OUT16, false);
        k_srcdst<<<ROWS1 / 8, 256>>>(hh, gata + (size_t)l * 512, src, dstT, NN1);
        k_rowstat<<<dim3(NN1, BB), 128>>>(src, dstT, adj, stat, anum, NN1);
        agg_fused<<<dim3(1, NN1 / 128, BB * HH), 256>>>(anum, stat, hh, feat0, x, NN1);
    }

    // ---- main scores (dual xq/xk) ----
    run_big(x, 256, 0, clsWqh, 256, 0, xq, 256, 0,
            ROWS1, 256, 256, 2, nullptr, nullptr, 0, nullptr, 0, F_OUT16, false,
            clsWkh, xk, 1);
    run_big(xq, 256, (long long)NN1 * 256, xk, 256, (long long)NN1 * 256,
            out_scores, NN1, (long long)NN1 * NN1,
            NN1, NN1, 256, BB, nullptr, nullptr, 0,
            adj, (long long)NN1 * NN1, F_SIG, true);
    k_asso<<<(int)(((size_t)BB * 512 * 512) / 1024), 256>>>(out_scores, out_asso);

    // ---- detection GAT x2 ----
    for (int l = 0; l < 2; l++) {
        const __half* xin = (l == 0) ? det_emb : x;
        run_big(xin, 256, 0, dgatWh + (size_t)l * 65536, 256, 0, hh, 256, 0,
                ND, 256, 256, 1, nullptr, nullptr, 0, nullptr, 0, F_OUT16, false);
        k_srcdst<<<ND / 8, 256>>>(hh, dgata + (size_t)l * 512, src, dstT, NNd);
        k_rowstat<<<dim3(NNd, BB), 128>>>(src, dstT, adjd, stat, anum, NNd);
        agg_fused<<<dim3(1, NNd / 128, BB * HH), 256>>>(anum, stat, hh, detf, x, NNd);
    }

    // ---- detection scores (dual xq/xk) ----
    run_big(x, 256, 0, clsWqh + 65536, 256, 0, xq, 256, 0,
            ND, 256, 256, 2, nullptr, nullptr, 0, nullptr, 0, F_OUT16, false,
            clsWkh + 65536, xk, 1);
    run_big(xq, 256, (long long)NNd * 256, xk, 256, (long long)NNd * 256,
            out_det, NNd, (long long)NNd * NNd,
            NNd, NNd, 256, BB, nullptr, nullptr, 0,
            adjd, (long long)NNd * NNd, F_SIG | F_DIAG, true);
}

// round 15
// speedup vs baseline: 1.0612x; 1.0125x over previous
#include <cuda_runtime.h>
#include <cuda_fp16.h>
#include <math.h>
#include <stdint.h>

// ---------------------------------------------------------------------------
// Problem dims
// ---------------------------------------------------------------------------
#define BB 16
#define MM 512
#define NNd 512
#define RR 8
#define DD 256
#define HH 4
#define NN1 1024
#define TM  (BB*MM*RR)    // 65536
#define TT  (BB*MM)       // 8192
#define ND  (BB*NNd)      // 8192
#define ROWS1 (BB*NN1)    // 16384

#define F_BIAS 1
#define F_RELU 2
#define F_AUX  4
#define F_SIG  8
#define F_DIAG 16
#define F_OUT16 32
#define F_ASSO 64

// ---------------------------------------------------------------------------
// Scratch
// ---------------------------------------------------------------------------
__device__ __half g_h1[(TM+ND)*DD];
__device__ __half g_emb[(TM+ND)*DD];
__device__ __half g_lnb[TM*DD];
__device__ __half g_kv[TM*512];
__device__ __half g_q0[TT*DD];
__device__ __half g_o0[TT*DD];
__device__ float  g_x1[TT*DD];
__device__ __half g_ln2[TT*DD];
__device__ __half g_ffh[TT*1024];
__device__ float  g_ffout[TT*DD];
__device__ float  g_feat0[ROWS1*DD];
__device__ __half g_x[ROWS1*DD];
__device__ __half g_hh[ROWS1*DD];
__device__ float g_src[ROWS1*HH];
__device__ float g_dstT[BB*HH*NN1];
__device__ float2 g_stat[BB*HH*NN1];
__device__ __half g_anum[(size_t)BB*HH*NN1*NN1];
__device__ unsigned char g_adj[(size_t)BB*NN1*NN1];
__device__ unsigned char g_adjd[(size_t)BB*NNd*NNd];
__device__ float g_pos[BB*NN1*2];
__device__ unsigned char g_vm[BB*NN1];
__device__ __half g_xq[ROWS1*DD];
__device__ __half g_xk[ROWS1*DD];
// fp16 weights
__device__ __half g_w2h[256*256];
__device__ __half g_wqkvh[256*768];
__device__ __half g_woh[256*256];
__device__ __half g_ff1h[256*1024];
__device__ __half g_ff2h[1024*256];
__device__ __half g_gatWh[2*256*256];
__device__ __half g_dgatWh[2*256*256];
__device__ __half g_clsWqh[2*256*256];
__device__ __half g_clsWkh[2*256*256];

// ---------------------------------------------------------------------------
// helpers
// ---------------------------------------------------------------------------
__device__ __forceinline__ uint32_t pk(float lo, float hi) {
    __half2 v = __floats2half2_rn(lo, hi);
    return *reinterpret_cast<uint32_t*>(&v);
}
__device__ __forceinline__ void mma_f16(float* c, const uint32_t* a, const uint32_t* b) {
    asm volatile(
        "mma.sync.aligned.m16n8k16.row.col.f32.f16.f16.f32 "
        "{%0,%1,%2,%3}, {%4,%5,%6,%7}, {%8,%9}, {%0,%1,%2,%3};\n"
        : "+f"(c[0]), "+f"(c[1]), "+f"(c[2]), "+f"(c[3])
        : "r"(a[0]), "r"(a[1]), "r"(a[2]), "r"(a[3]), "r"(b[0]), "r"(b[1]));
}
__device__ __forceinline__ void ldm_x4(uint32_t* r, uint32_t addr) {
    asm volatile("ldmatrix.sync.aligned.m8n8.x4.shared.b16 {%0,%1,%2,%3}, [%4];"
        : "=r"(r[0]), "=r"(r[1]), "=r"(r[2]), "=r"(r[3]) : "r"(addr));
}
__device__ __forceinline__ void ldm_x4_t(uint32_t* r, uint32_t addr) {
    asm volatile("ldmatrix.sync.aligned.m8n8.x4.trans.shared.b16 {%0,%1,%2,%3}, [%4];"
        : "=r"(r[0]), "=r"(r[1]), "=r"(r[2]), "=r"(r[3]) : "r"(addr));
}
__device__ __forceinline__ uint32_t cvs(const void* p) {
    return (uint32_t)__cvta_generic_to_shared(p);
}
__device__ __forceinline__ void cp16(uint32_t dst, const void* src) {
    asm volatile("cp.async.cg.shared.global [%0], [%1], 16;" :: "r"(dst), "l"(src));
}
__device__ __forceinline__ void cp8(uint32_t dst, const void* src) {
    asm volatile("cp.async.ca.shared.global [%0], [%1], 8;" :: "r"(dst), "l"(src));
}
__device__ __forceinline__ void cp4(uint32_t dst, const void* src) {
    asm volatile("cp.async.ca.shared.global [%0], [%1], 4;" :: "r"(dst), "l"(src));
}
#define CP_COMMIT() asm volatile("cp.async.commit_group;")
#define CP_WAIT1()  asm volatile("cp.async.wait_group 1;")
#define CP_WAIT0()  asm volatile("cp.async.wait_group 0;")

// combined weight fp32->fp16
struct WPack {
    const float* s[9];
    __half* d[9];
    int n[9];
};
__global__ void k_f2h_all(WPack p)
{
    int g = blockIdx.y;
    int i = (blockIdx.x * 256 + threadIdx.x) * 4;
    if (i >= p.n[g]) return;
    float4 v = *(const float4*)(p.s[g] + i);
    uint2 o;
    o.x = pk(v.x, v.y);
    o.y = pk(v.z, v.w);
    *(uint2*)(p.d[g] + i) = o;
}

// ---------------------------------------------------------------------------
// BIG GEMM (fp16, cp.async 3-stage, BK=32): CTA 128x128, 256 thr, warp 64x32.
// Dynamic smem: A region 9216 words (3 stages x 2 chunks x 1536),
//               B region 9216 words at word 9216. Total 73728 bytes.
// ---------------------------------------------------------------------------
#define STG_B   12288u   // bytes per stage (2 chunks x 6144)
#define CHK_B   6144u
#define BREG    9216     // word offset of B region
template<bool TRANSB, int FLAGS>
__global__ __launch_bounds__(256, 2)
void tgemm_big(const __half* __restrict__ A, int lda, long long sA,
               const __half* __restrict__ B, int ldb, long long sB,
               void* __restrict__ Cv, int ldc, long long sC,
               int K,
               const float* __restrict__ bias,
               const __half* __restrict__ aux, int auxld,
               const unsigned char* __restrict__ adjp, long long sAdj,
               const __half* __restrict__ B2, void* __restrict__ C2v, int dual,
               float* __restrict__ asso)
{
    extern __shared__ uint32_t dsm[];
    int bz = blockIdx.z;
    int bzA = bz;
    if (dual && bz) { B = B2; Cv = C2v; bz = 0; }
    A += (long long)bz * sA;
    B += (long long)bz * sB;
    size_t coff = (size_t)((long long)bz * sC);
    if (FLAGS & F_SIG) adjp += (long long)bz * sAdj;

    int m0 = blockIdx.y * 128, n0 = blockIdx.x * 128;

    int tid = threadIdx.x;
    int arow = tid >> 1, ahalf = tid & 1;
    const __half* gA = A + (size_t)(m0 + arow) * lda + ahalf * 8;

    const __half* gB;
    int kp = tid >> 5, nq = tid & 31;
    if (!TRANSB) gB = B + (size_t)(2 * kp) * ldb + n0 + nq * 4;
    else         gB = B + (size_t)(n0 + arow) * ldb + ahalf * 8;

    uint32_t aD = cvs(&dsm[arow * 12 + ahalf * 4]);
    uint32_t bD1, bD2;
    if (!TRANSB) {
        int w0 = (2 * kp) * 68 + nq * 2;
        bD1 = cvs(&dsm[BREG + w0]);
        bD2 = cvs(&dsm[BREG + w0 + 68]);
    } else {
        bD1 = cvs(&dsm[BREG + arow * 12 + ahalf * 4]);
        bD2 = 0;
    }

    int w = tid >> 5, l = tid & 31;
    int mbase = (w >> 2) * 64, nbase = (w & 3) * 32;
    int grp = l >> 2, tig = l & 3;

    int lrowA = ((l >> 3) & 1) * 8 + (l & 7);
    int khalf = l >> 4;
    uint32_t aBase[4];
    #pragma unroll
    for (int fm = 0; fm < 4; fm++)
        aBase[fm] = cvs(&dsm[(mbase + fm * 16 + lrowA) * 12 + khalf * 4]);
    uint32_t bBase[2];
    if (!TRANSB) {
        int krow = ((l >> 4) & 1) * 8 + (l & 7);
        int nblk = ((l >> 3) & 1) * 8;
        #pragma unroll
        for (int fp = 0; fp < 2; fp++)
            bBase[fp] = cvs(&dsm[BREG + krow * 68 + ((nbase + fp * 16 + nblk) >> 1)]);
    } else {
        #pragma unroll
        for (int fp = 0; fp < 2; fp++)
            bBase[fp] = cvs(&dsm[BREG + (nbase + fp * 16 + lrowA) * 12 + khalf * 4]);
    }

    float acc[4][4][4];
    #pragma unroll
    for (int i = 0; i < 4; i++)
        #pragma unroll
        for (int j = 0; j < 4; j++)
            #pragma unroll
            for (int q = 0; q < 4; q++) acc[i][j][q] = 0.f;

    int nk = K >> 5;   // 32-k stages

    // prologue: issue stages 0 and 1
    #pragma unroll
    for (int p = 0; p < 2; p++) {
        if (p < nk) {
            #pragma unroll
            for (int c = 0; c < 2; c++) {
                uint32_t off = p * STG_B + c * CHK_B;
                int k0 = p * 32 + c * 16;
                cp16(aD + off, gA + k0);
                if (!TRANSB) {
                    cp8(bD1 + off, gB + (size_t)k0 * ldb);
                    cp8(bD2 + off, gB + (size_t)(k0 + 1) * ldb);
                } else {
                    cp16(bD1 + off, gB + k0);
                }
            }
            CP_COMMIT();
        }
    }

    int s = 0;
    for (int i = 0; i < nk; i++) {
        if (i + 1 < nk) CP_WAIT1(); else CP_WAIT0();
        __syncthreads();
        #pragma unroll
        for (int c = 0; c < 2; c++) {
            uint32_t soff = (uint32_t)s * STG_B + c * CHK_B;
            uint32_t af[4][4];
            #pragma unroll
            for (int fm = 0; fm < 4; fm++) ldm_x4(af[fm], aBase[fm] + soff);
            uint32_t bfr[4][2];
            #pragma unroll
            for (int fp = 0; fp < 2; fp++) {
                uint32_t t4[4];
                if (!TRANSB) ldm_x4_t(t4, bBase[fp] + soff);
                else         ldm_x4(t4, bBase[fp] + soff);
                bfr[fp * 2][0] = t4[0]; bfr[fp * 2 + 1][0] = t4[1];
                bfr[fp * 2][1] = t4[2]; bfr[fp * 2 + 1][1] = t4[3];
            }
            #pragma unroll
            for (int fm = 0; fm < 4; fm++)
                #pragma unroll
                for (int fn = 0; fn < 4; fn++)
                    mma_f16(acc[fm][fn], af[fm], bfr[fn]);
        }
        if (i + 2 < nk) {
            int st = s >= 1 ? s - 1 : s + 2;   // (s+2)%3
            #pragma unroll
            for (int c = 0; c < 2; c++) {
                uint32_t off = (uint32_t)st * STG_B + c * CHK_B;
                int k0 = (i + 2) * 32 + c * 16;
                cp16(aD + off, gA + k0);
                if (!TRANSB) {
                    cp8(bD1 + off, gB + (size_t)k0 * ldb);
                    cp8(bD2 + off, gB + (size_t)(k0 + 1) * ldb);
                } else {
                    cp16(bD1 + off, gB + k0);
                }
            }
            CP_COMMIT();
        }
        s = (s + 1) == 3 ? 0 : s + 1;
    }

    // epilogue
    #pragma unroll
    for (int fm = 0; fm < 4; fm++) {
        int row0 = m0 + mbase + fm * 16 + grp;
        #pragma unroll
        for (int fn = 0; fn < 4; fn++) {
            int col = n0 + nbase + fn * 8 + 2 * tig;
            float v0 = acc[fm][fn][0], v1 = acc[fm][fn][1];
            float v2 = acc[fm][fn][2], v3 = acc[fm][fn][3];
            if (FLAGS & F_BIAS) {
                float bb0 = bias[col], bb1 = bias[col + 1];
                v0 += bb0; v1 += bb1; v2 += bb0; v3 += bb1;
            }
            if (FLAGS & F_RELU) {
                v0 = fmaxf(v0, 0.f); v1 = fmaxf(v1, 0.f);
                v2 = fmaxf(v2, 0.f); v3 = fmaxf(v3, 0.f);
            }
            if (FLAGS & F_AUX) {
                float2 a0 = __half22float2(*(const __half2*)(aux + (size_t)row0 * auxld + col));
                float2 a8 = __half22float2(*(const __half2*)(aux + (size_t)(row0 + 8) * auxld + col));
                v0 += a0.x; v1 += a0.y; v2 += a8.x; v3 += a8.y;
            }
            if (FLAGS & F_SIG) {
                const unsigned char* q0p = adjp + (size_t)row0 * ldc + col;
                const unsigned char* q8p = adjp + (size_t)(row0 + 8) * ldc + col;
                v0 = q0p[0] ? 1.f / (1.f + __expf(-v0 * 0.0625f)) : 0.f;
                v1 = q0p[1] ? 1.f / (1.f + __expf(-v1 * 0.0625f)) : 0.f;
                v2 = q8p[0] ? 1.f / (1.f + __expf(-v2 * 0.0625f)) : 0.f;
                v3 = q8p[1] ? 1.f / (1.f + __expf(-v3 * 0.0625f)) : 0.f;
                if (FLAGS & F_DIAG) {
                    if (row0 == col) v0 = 0.f;
                    if (row0 == col + 1) v1 = 0.f;
                    if (row0 + 8 == col) v2 = 0.f;
                    if (row0 + 8 == col + 1) v3 = 0.f;
                }
            }
            if (FLAGS & F_OUT16) {
                __half* Ch = (__half*)Cv + coff;
                *(uint32_t*)&Ch[(size_t)row0 * ldc + col] = pk(v0, v1);
                *(uint32_t*)&Ch[(size_t)(row0 + 8) * ldc + col] = pk(v2, v3);
            } else {
                float* C = (float*)Cv + coff;
                *(float2*)&C[(size_t)row0 * ldc + col] = make_float2(v0, v1);
                *(float2*)&C[(size_t)(row0 + 8) * ldc + col] = make_float2(v2, v3);
            }
            if (FLAGS & F_ASSO) {
                // asso = scores[b, m<512, 512+j]
                if (col >= 512) {
                    int jc = col - 512;
                    if (row0 < 512)
                        *(float2*)&asso[((size_t)bzA * 512 + row0) * 512 + jc] = make_float2(v0, v1);
                    if (row0 + 8 < 512)
                        *(float2*)&asso[((size_t)bzA * 512 + row0 + 8) * 512 + jc] = make_float2(v2, v3);
                }
            }
        }
    }
}

// ---------------------------------------------------------------------------
// GAT aggregation (fp16 GEMM, cp.async 3-stage): CTA 128x64, warp 32x32.
// AUX16: aux is fp16 (det branch) vs fp32 (main branch).
// ---------------------------------------------------------------------------
template<bool AUX16>
__global__ __launch_bounds__(256)
void agg_fused(const __half* __restrict__ anum, const float2* __restrict__ stat,
               const __half* __restrict__ hmat,
               const void* __restrict__ auxv, __half* __restrict__ xout, int NN)
{
    int z = blockIdx.z;
    int b = z >> 2, h = z & 3;
    const __half* B = hmat + (size_t)b * NN * 256 + h * 64;
    __half* C = xout + (size_t)b * NN * 256 + h * 64;
    size_t auxbase = (size_t)b * NN * 256 + h * 64;
    const float* auxf = (const float*)auxv + auxbase;
    const __half* auxh = (const __half*)auxv + auxbase;
    const float2* statz = stat + (size_t)z * NN;

    int m0 = blockIdx.y * 128;
    __shared__ uint32_t As[3][1536];
    __shared__ uint32_t Bs[3][576];
    int tid = threadIdx.x;

    int arow = tid >> 1, ahalf = tid & 1;
    const __half* gA = anum + ((size_t)z * NN + m0 + arow) * NN + ahalf * 8;

    int kp = tid >> 5, nq = tid & 31;
    const __half* gB = B + (size_t)(2 * kp) * 256 + 2 * nq;

    uint32_t aD = cvs(&As[0][arow * 12 + ahalf * 4]);
    uint32_t bD1 = cvs(&Bs[0][(2 * kp) * 36 + nq]);
    uint32_t bD2 = cvs(&Bs[0][(2 * kp + 1) * 36 + nq]);

    int w = tid >> 5, l = tid & 31;
    int wm = w >> 1, wn = w & 1;
    int mrow = wm * 32, ncol = wn * 32;
    int grp = l >> 2, tig = l & 3;

    int lrowA = ((l >> 3) & 1) * 8 + (l & 7);
    int khalf = l >> 4;
    uint32_t aBase[2];
    #pragma unroll
    for (int fm = 0; fm < 2; fm++)
        aBase[fm] = cvs(&As[0][(mrow + fm * 16 + lrowA) * 12 + khalf * 4]);
    int krow = ((l >> 4) & 1) * 8 + (l & 7);
    int nblk = ((l >> 3) & 1) * 8;
    uint32_t bBase[2];
    #pragma unroll
    for (int fp = 0; fp < 2; fp++)
        bBase[fp] = cvs(&Bs[0][krow * 36 + ((ncol + fp * 16 + nblk) >> 1)]);

    float acc[2][4][4];
    #pragma unroll
    for (int i = 0; i < 2; i++)
        #pragma unroll
        for (int j = 0; j < 4; j++)
            #pragma unroll
            for (int q = 0; q < 4; q++) acc[i][j][q] = 0.f;

    int nk = NN >> 4;

    // prologue
    {
        cp16(aD, gA);
        cp4(bD1, gB);
        cp4(bD2, gB + 256);
        CP_COMMIT();
        if (nk > 1) {
            cp16(aD + 6144, gA + 16);
            cp4(bD1 + 2304, gB + 16 * 256);
            cp4(bD2 + 2304, gB + 17 * 256);
            CP_COMMIT();
        }
    }

    int s = 0;
    for (int i = 0; i < nk; i++) {
        if (i + 1 < nk) CP_WAIT1(); else CP_WAIT0();
        __syncthreads();
        uint32_t sa = (uint32_t)(s * 6144);
        uint32_t sbo = (uint32_t)(s * 2304);
        uint32_t af[2][4];
        #pragma unroll
        for (int fm = 0; fm < 2; fm++) ldm_x4(af[fm], aBase[fm] + sa);
        uint32_t bfr[4][2];
        #pragma unroll
        for (int fp = 0; fp < 2; fp++) {
            uint32_t t4[4];
            ldm_x4_t(t4, bBase[fp] + sbo);
            bfr[fp * 2][0] = t4[0]; bfr[fp * 2 + 1][0] = t4[1];
            bfr[fp * 2][1] = t4[2]; bfr[fp * 2 + 1][1] = t4[3];
        }
        #pragma unroll
        for (int fm = 0; fm < 2; fm++)
            #pragma unroll
            for (int fn = 0; fn < 4; fn++)
                mma_f16(acc[fm][fn], af[fm], bfr[fn]);
        if (i + 2 < nk) {
            int st = s >= 1 ? s - 1 : s + 2;
            int k0 = (i + 2) * 16;
            cp16(aD + st * 6144, gA + k0);
            cp4(bD1 + st * 2304, gB + (size_t)k0 * 256);
            cp4(bD2 + st * 2304, gB + (size_t)(k0 + 1) * 256);
            CP_COMMIT();
        }
        s = (s + 1) == 3 ? 0 : s + 1;
    }

    #pragma unroll
    for (int fm = 0; fm < 2; fm++) {
        int row = m0 + mrow + fm * 16 + grp;
        float inv0 = statz[row].y;
        float inv8 = statz[row + 8].y;
        #pragma unroll
        for (int fn = 0; fn < 4; fn++) {
            int col = ncol + fn * 8 + 2 * tig;
            float v0 = acc[fm][fn][0] * inv0, v1 = acc[fm][fn][1] * inv0;
            float v2 = acc[fm][fn][2] * inv8, v3 = acc[fm][fn][3] * inv8;
            v0 = (v0 > 0.f) ? v0 : expm1f(v0);
            v1 = (v1 > 0.f) ? v1 : expm1f(v1);
            v2 = (v2 > 0.f) ? v2 : expm1f(v2);
            v3 = (v3 > 0.f) ? v3 : expm1f(v3);
            float2 x0, x1;
            if (AUX16) {
                x0 = __half22float2(*(const __half2*)&auxh[(size_t)row * 256 + col]);
                x1 = __half22float2(*(const __half2*)&auxh[(size_t)(row + 8) * 256 + col]);
            } else {
                x0 = *(const float2*)&auxf[(size_t)row * 256 + col];
                x1 = *(const float2*)&auxf[(size_t)(row + 8) * 256 + col];
            }
            *(uint32_t*)&C[(size_t)row * 256 + col] =
                pk(0.5f * v0 + 0.5f * x0.x, 0.5f * v1 + 0.5f * x0.y);
            *(uint32_t*)&C[(size_t)(row + 8) * 256 + col] =
                pk(0.5f * v2 + 0.5f * x1.x, 0.5f * v3 + 0.5f * x1.y);
        }
    }
}

// ---------------------------------------------------------------------------
// Small kernels
// ---------------------------------------------------------------------------
__global__ void k_feat1(const float* __restrict__ tr, const float* __restrict__ de,
                        const float* __restrict__ W1, const float* __restrict__ b1,
                        __half* __restrict__ out)
{
    int tid = threadIdx.x;
    size_t row = (size_t)blockIdx.x * 4 + (tid >> 6);
    int c4 = (tid & 63) * 4;
    const float* xr = (row < TM) ? (tr + row * 4) : (de + (row - TM) * 4);
    const float4 x4 = *(const float4*)xr;
    float4 v = *(const float4*)(b1 + c4);
    float4 w0 = *(const float4*)(W1 + c4);
    float4 w1 = *(const float4*)(W1 + 256 + c4);
    float4 w2 = *(const float4*)(W1 + 512 + c4);
    float4 w3 = *(const float4*)(W1 + 768 + c4);
    v.x += x4.x * w0.x + x4.y * w1.x + x4.z * w2.x + x4.w * w3.x;
    v.y += x4.x * w0.y + x4.y * w1.y + x4.z * w2.y + x4.w * w3.y;
    v.z += x4.x * w0.z + x4.y * w1.z + x4.z * w2.z + x4.w * w3.z;
    v.w += x4.x * w0.w + x4.y * w1.w + x4.z * w2.w + x4.w * w3.w;
    v.x = (v.x > 0.f) ? v.x : (__expf(v.x) - 1.f);
    v.y = (v.y > 0.f) ? v.y : (__expf(v.y) - 1.f);
    v.z = (v.z > 0.f) ? v.z : (__expf(v.z) - 1.f);
    v.w = (v.w > 0.f) ? v.w : (__expf(v.w) - 1.f);
    uint2 p;
    p.x = pk(v.x, v.y);
    p.y = pk(v.z, v.w);
    *(uint2*)(out + row * 256 + c4) = p;
}

__global__ void k_ln_h(const __half* __restrict__ in, __half* __restrict__ out)
{
    int w = threadIdx.x >> 5, lane = threadIdx.x & 31;
    size_t row = (size_t)blockIdx.x * 8 + w;
    const uint4* ip = (const uint4*)(in + row * 256);
    uint4 u = ip[lane];
    float2 f0 = __half22float2(*(__half2*)&u.x);
    float2 f1 = __half22float2(*(__half2*)&u.y);
    float2 f2 = __half22float2(*(__half2*)&u.z);
    float2 f3 = __half22float2(*(__half2*)&u.w);
    float a = f0.x + f0.y + f1.x + f1.y + f2.x + f2.y + f3.x + f3.y;
    float b = f0.x*f0.x + f0.y*f0.y + f1.x*f1.x + f1.y*f1.y
            + f2.x*f2.x + f2.y*f2.y + f3.x*f3.x + f3.y*f3.y;
    #pragma unroll
    for (int o = 16; o; o >>= 1) {
        a += __shfl_xor_sync(0xffffffff, a, o);
        b += __shfl_xor_sync(0xffffffff, b, o);
    }
    float mean = a * (1.f / 256.f);
    float var = b * (1.f / 256.f) - mean * mean;
    float rstd = rsqrtf(var + 1e-5f);
    uint4 r;
    r.x = pk((f0.x - mean) * rstd, (f0.y - mean) * rstd);
    r.y = pk((f1.x - mean) * rstd, (f1.y - mean) * rstd);
    r.z = pk((f2.x - mean) * rstd, (f2.y - mean) * rstd);
    r.w = pk((f3.x - mean) * rstd, (f3.y - mean) * rstd);
    ((uint4*)(out + row * 256))[lane] = r;
}

__global__ void k_ln_f(const float* __restrict__ in, __half* __restrict__ out)
{
    int w = threadIdx.x >> 5, lane = threadIdx.x & 31;
    size_t row = (size_t)blockIdx.x * 8 + w;
    const float4* ip = (const float4*)(in + row * 256);
    float4 v0 = ip[lane], v1 = ip[lane + 32];
    float a = v0.x + v0.y + v0.z + v0.w + v1.x + v1.y + v1.z + v1.w;
    float b = v0.x*v0.x + v0.y*v0.y + v0.z*v0.z + v0.w*v0.w
            + v1.x*v1.x + v1.y*v1.y + v1.z*v1.z + v1.w*v1.w;
    #pragma unroll
    for (int o = 16; o; o >>= 1) {
        a += __shfl_xor_sync(0xffffffff, a, o);
        b += __shfl_xor_sync(0xffffffff, b, o);
    }
    float mean = a * (1.f / 256.f);
    float var = b * (1.f / 256.f) - mean * mean;
    float rstd = rsqrtf(var + 1e-5f);
    uint2 p0, p1;
    p0.x = pk((v0.x - mean) * rstd, (v0.y - mean) * rstd);
    p0.y = pk((v0.z - mean) * rstd, (v0.w - mean) * rstd);
    p1.x = pk((v1.x - mean) * rstd, (v1.y - mean) * rstd);
    p1.y = pk((v1.z - mean) * rstd, (v1.w - mean) * rstd);
    *(uint2*)(out + row * 256 + lane * 4) = p0;
    *(uint2*)(out + row * 256 + 128 + lane * 4) = p1;
}

__global__ void k_attn(const __half* __restrict__ q0, const __half* __restrict__ kv,
                       __half* __restrict__ o0)
{
    size_t t = blockIdx.x;
    int d = threadIdx.x;
    int w = d >> 5, lane = d & 31, h = d >> 6;
    __shared__ float red[8][8];
    const __half* kvb = kv + t * 8 * 512;
    float qd = __half2float(q0[t * 256 + d]);
    #pragma unroll
    for (int s = 0; s < 8; s++) {
        float v = qd * __half2float(kvb[s * 512 + d]);
        #pragma unroll
        for (int o = 16; o; o >>= 1) v += __shfl_xor_sync(0xffffffff, v, o);
        if (lane == 0) red[w][s] = v;
    }
    __syncthreads();
    float lg[8];
    float m = -1e30f;
    #pragma unroll
    for (int s = 0; s < 8; s++) {
        lg[s] = (red[2 * h][s] + red[2 * h + 1][s]) * 0.125f;
        m = fmaxf(m, lg[s]);
    }
    float sum = 0.f;
    #pragma unroll
    for (int s = 0; s < 8; s++) { lg[s] = __expf(lg[s] - m); sum += lg[s]; }
    float inv = 1.f / sum;
    float o = 0.f;
    #pragma unroll
    for (int s = 0; s < 8; s++) o += lg[s] * inv * __half2float(kvb[s * 512 + 256 + d]);
    o0[t * 256 + d] = __float2half(o);
}

// feat0 vectorized: 4 rows/block, 4 cols/thread
__global__ void k_feat0(const __half* __restrict__ tr_emb, const float* __restrict__ x1,
                        const float* __restrict__ ffout, const __half* __restrict__ det_emb,
                        float* __restrict__ feat0, __half* __restrict__ x)
{
    int tid = threadIdx.x;
    size_t row = (size_t)blockIdx.x * 4 + (tid >> 6);
    int c4 = (tid & 63) * 4;
    int i = (int)(row & 1023);
    int b = (int)(row >> 10);
    float4 v;
    if (i < 512) {
        size_t t = (size_t)b * 512 + i;
        uint2 te = *(const uint2*)(tr_emb + t * 2048 + c4);
        float2 e01 = __half22float2(*(__half2*)&te.x);
        float2 e23 = __half22float2(*(__half2*)&te.y);
        float4 a = *(const float4*)(x1 + t * 256 + c4);
        float4 f = *(const float4*)(ffout + t * 256 + c4);
        v.x = e01.x + 0.9f * (a.x + f.x);
        v.y = e01.y + 0.9f * (a.y + f.y);
        v.z = e23.x + 0.9f * (a.z + f.z);
        v.w = e23.y + 0.9f * (a.w + f.w);
    } else {
        size_t t = (size_t)b * 512 + (i - 512);
        uint2 de = *(const uint2*)(det_emb + t * 256 + c4);
        float2 e01 = __half22float2(*(__half2*)&de.x);
        float2 e23 = __half22float2(*(__half2*)&de.y);
        v = make_float4(e01.x, e01.y, e23.x, e23.y);
    }
    *(float4*)(feat0 + row * 256 + c4) = v;
    uint2 p;
    p.x = pk(v.x, v.y);
    p.y = pk(v.z, v.w);
    *(uint2*)(x + row * 256 + c4) = p;
}

__global__ void k_posvm(const float* __restrict__ tracks, const float* __restrict__ dets,
                        const int* __restrict__ tmarks, const int* __restrict__ dmarks,
                        float* __restrict__ pos, unsigned char* __restrict__ vm)
{
    int idx = blockIdx.x * 256 + threadIdx.x;
    if (idx >= BB * NN1) return;
    int b = idx >> 10, i = idx & 1023;
    float x, y; unsigned char v;
    if (i < 512) {
        const float* p = tracks + ((size_t)(b * 512 + i)) * 8 * 4;
        x = p[0]; y = p[1];
        v = (i < tmarks[b]);
    } else {
        int n = i - 512;
        const float* p = dets + ((size_t)(b * 512 + n)) * 4;
        x = p[0]; y = p[1];
        v = (n < dmarks[b]);
    }
    pos[idx * 2] = x; pos[idx * 2 + 1] = y; vm[idx] = v;
}

__global__ void k_adj(const float* __restrict__ pos, const unsigned char* __restrict__ vm,
                      unsigned char* __restrict__ adj)
{
    int i = blockIdx.x, b = blockIdx.y;
    size_t base = (size_t)b * NN1;
    const float2* p2 = (const float2*)pos;
    float2 pi = p2[base + i];
    unsigned char vi = vm[base + i];
    int j0 = threadIdx.x * 4;
    uchar4 r;
    unsigned char* rp = &r.x;
    #pragma unroll
    for (int u = 0; u < 4; u++) {
        int j = j0 + u;
        float2 pj = p2[base + j];
        float dx = pi.x - pj.x, dy = pi.y - pj.y;
        rp[u] = (unsigned char)((dx * dx + dy * dy < 4.0f) && vi && vm[base + j]);
    }
    ((uchar4*)(adj + ((size_t)b * NN1 + i) * NN1))[threadIdx.x] = r;
}

__global__ void k_adjd(const float* __restrict__ pos, const unsigned char* __restrict__ vm,
                       unsigned char* __restrict__ adjd)
{
    int i = blockIdx.x, b = blockIdx.y;
    size_t base = (size_t)b * NN1 + 512;
    const float2* p2 = (const float2*)pos;
    float2 pi = p2[base + i];
    unsigned char vi = vm[base + i];
    int j0 = threadIdx.x * 4;
    uchar4 r;
    unsigned char* rp = &r.x;
    #pragma unroll
    for (int u = 0; u < 4; u++) {
        int j = j0 + u;
        float2 pj = p2[base + j];
        float dx = pi.x - pj.x, dy = pi.y - pj.y;
        rp[u] = (unsigned char)((dx * dx + dy * dy < 4.0f) && vi && vm[base + j]);
    }
    ((uchar4*)(adjd + ((size_t)b * NNd + i) * NNd))[threadIdx.x] = r;
}

// src/dst projections: warp per row, 8 rows/block.
__global__ void k_srcdst(const __half* __restrict__ Hm, const float* __restrict__ a0,
                         float* __restrict__ src, float* __restrict__ dstT, int NN)
{
    int w = threadIdx.x >> 5, lane = threadIdx.x & 31;
    size_t row = (size_t)blockIdx.x * 8 + w;
    uint4 u = ((const uint4*)(Hm + row * 256))[lane];
    float2 f0 = __half22float2(*(__half2*)&u.x);
    float2 f1 = __half22float2(*(__half2*)&u.y);
    float2 f2 = __half22float2(*(__half2*)&u.z);
    float2 f3 = __half22float2(*(__half2*)&u.w);
    const float4* s0p = (const float4*)(a0 + lane * 8);
    const float4* s1p = (const float4*)(a0 + 256 + lane * 8);
    float4 sa = s0p[0], sb = s0p[1];
    float4 ta = s1p[0], tb = s1p[1];
    float s = f0.x * sa.x + f0.y * sa.y + f1.x * sa.z + f1.y * sa.w
            + f2.x * sb.x + f2.y * sb.y + f3.x * sb.z + f3.y * sb.w;
    float t = f0.x * ta.x + f0.y * ta.y + f1.x * ta.z + f1.y * ta.w
            + f2.x * tb.x + f2.y * tb.y + f3.x * tb.z + f3.y * tb.w;
    #pragma unroll
    for (int o = 4; o; o >>= 1) {
        s += __shfl_xor_sync(0xffffffff, s, o);
        t += __shfl_xor_sync(0xffffffff, t, o);
    }
    if ((lane & 7) == 0) {
        int h = lane >> 3;
        int b = (int)(row / NN);
        int i = (int)(row - (size_t)b * NN);
        src[row * 4 + h] = s;
        dstT[((size_t)b * 4 + h) * NN + i] = t;
    }
}

__global__ void k_rowstat(const float* __restrict__ src, const float* __restrict__ dstT,
                          const unsigned char* __restrict__ adj, float2* __restrict__ stat,
                          __half* __restrict__ anum, int NN)
{
    int i = blockIdx.x, b = blockIdx.y;
    int h = threadIdx.x >> 5, lane = threadIdx.x & 31;
    int z = b * 4 + h;
    float s = src[((size_t)b * NN + i) * 4 + h];
    const uchar4* adjrow = (const uchar4*)(adj + ((size_t)b * NN + i) * NN);
    const float4* dsth = (const float4*)(dstT + ((size_t)z) * NN);
    __half* arow = anum + ((size_t)z * NN + i) * NN;
    int nq = NN >> 2;
    float mx = -1e30f;
    for (int jq = lane; jq < nq; jq += 32) {
        uchar4 a4 = adjrow[jq];
        float4 d4 = dsth[jq];
        float e0 = s + d4.x; e0 = e0 > 0.f ? e0 : 0.2f * e0; e0 = a4.x ? e0 : -1e9f;
        float e1 = s + d4.y; e1 = e1 > 0.f ? e1 : 0.2f * e1; e1 = a4.y ? e1 : -1e9f;
        float e2 = s + d4.z; e2 = e2 > 0.f ? e2 : 0.2f * e2; e2 = a4.z ? e2 : -1e9f;
        float e3 = s + d4.w; e3 = e3 > 0.f ? e3 : 0.2f * e3; e3 = a4.w ? e3 : -1e9f;
        mx = fmaxf(mx, fmaxf(fmaxf(e0, e1), fmaxf(e2, e3)));
    }
    #pragma unroll
    for (int o = 16; o; o >>= 1) mx = fmaxf(mx, __shfl_xor_sync(0xffffffff, mx, o));
    float sum = 0.f;
    for (int jq = lane; jq < nq; jq += 32) {
        uchar4 a4 = adjrow[jq];
        float4 d4 = dsth[jq];
        float e0 = s + d4.x; e0 = e0 > 0.f ? e0 : 0.2f * e0; e0 = a4.x ? e0 : -1e9f;
        float e1 = s + d4.y; e1 = e1 > 0.f ? e1 : 0.2f * e1; e1 = a4.y ? e1 : -1e9f;
        float e2 = s + d4.z; e2 = e2 > 0.f ? e2 : 0.2f * e2; e2 = a4.z ? e2 : -1e9f;
        float e3 = s + d4.w; e3 = e3 > 0.f ? e3 : 0.2f * e3; e3 = a4.w ? e3 : -1e9f;
        float n0 = __expf(e0 - mx), n1 = __expf(e1 - mx);
        float n2 = __expf(e2 - mx), n3 = __expf(e3 - mx);
        sum += n0 + n1 + n2 + n3;
        uint2 pkd;
        pkd.x = pk(n0, n1);
        pkd.y = pk(n2, n3);
        *(uint2*)(arow + jq * 4) = pkd;
    }
    #pragma unroll
    for (int o = 16; o; o >>= 1) sum += __shfl_xor_sync(0xffffffff, sum, o);
    if (lane == 0)
        stat[(size_t)z * NN + i] = make_float2(mx, 1.f / sum);
}

// ---------------------------------------------------------------------------
// Host side
// ---------------------------------------------------------------------------
#define TG_DSMEM 73728

static void run_big(const __half* A, int lda, long long sA,
                    const __half* B, int ldb, long long sB,
                    void* C, int ldc, long long sC,
                    int M, int N, int K, int batch,
                    const float* bias, const __half* aux, int auxld,
                    const unsigned char* adjp, long long sAdj,
                    int flags, bool transb,
                    const __half* B2 = nullptr, void* C2 = nullptr, int dual = 0,
                    float* asso = nullptr)
{
    dim3 g(N / 128, M / 128, batch);
#define CALLBIG(T, F) do { \
        cudaFuncSetAttribute(tgemm_big<T, F>, cudaFuncAttributeMaxDynamicSharedMemorySize, TG_DSMEM); \
        tgemm_big<T, F><<<g, 256, TG_DSMEM>>>(A, lda, sA, B, ldb, sB, \
            C, ldc, sC, K, bias, aux, auxld, adjp, sAdj, B2, C2, dual, asso); \
    } while (0)
    if (!transb) {
        if (flags == (F_BIAS | F_OUT16))      CALLBIG(false, F_BIAS | F_OUT16);
        else if (flags == F_OUT16)            CALLBIG(false, F_OUT16);
        else if (flags == F_AUX)              CALLBIG(false, F_AUX);
        else if (flags == (F_RELU | F_OUT16)) CALLBIG(false, F_RELU | F_OUT16);
        else                                  CALLBIG(false, 0);
    } else {
        if (flags == (F_SIG | F_ASSO))        CALLBIG(true, F_SIG | F_ASSO);
        else                                  CALLBIG(true, F_SIG | F_DIAG);
    }
#undef CALLBIG
}

#define SYM(p, s) cudaGetSymbolAddress((void**)&p, s)

extern "C" void kernel_launch(void* const* d_in, const int* in_sizes, int n_in,
                              void* d_out, int out_size)
{
    (void)in_sizes; (void)n_in; (void)out_size;
    const float* tracks = (const float*)d_in[0];
    const float* dets   = (const float*)d_in[1];
    const int* tmarks   = (const int*)d_in[2];
    const int* dmarks   = (const int*)d_in[3];
    const float* W1     = (const float*)d_in[4];
    const float* b1     = (const float*)d_in[5];
    const float* W2     = (const float*)d_in[6];
    const float* b2     = (const float*)d_in[7];
    const float* Wqkv   = (const float*)d_in[8];
    const float* Wo     = (const float*)d_in[9];
    const float* ff1    = (const float*)d_in[10];
    const float* ff2    = (const float*)d_in[11];
    const float* gatW   = (const float*)d_in[12];
    const float* gata   = (const float*)d_in[13];
    const float* dgatW  = (const float*)d_in[14];
    const float* dgata  = (const float*)d_in[15];
    const float* clsWq  = (const float*)d_in[16];
    const float* clsWk  = (const float*)d_in[17];

    float* out = (float*)d_out;
    float* out_scores = out;
    float* out_det    = out + (size_t)BB * NN1 * NN1;
    float* out_asso   = out_det + (size_t)BB * NNd * NNd;

    __half *h1, *emb, *lnb, *kv, *q0, *o0, *ln2, *ffh, *x, *hh, *xq, *xk, *anum;
    __half *w2h, *wqkvh, *woh, *ff1h, *ff2h, *gatWh, *dgatWh, *clsWqh, *clsWkh;
    float *x1, *ffout, *feat0, *src, *dstT, *pos;
    float2* stat;
    unsigned char *adj, *adjd, *vm;
    SYM(h1, g_h1);         SYM(emb, g_emb);       SYM(lnb, g_lnb);
    SYM(kv, g_kv);         SYM(q0, g_q0);         SYM(o0, g_o0);
    SYM(x1, g_x1);         SYM(ln2, g_ln2);       SYM(ffh, g_ffh);
    SYM(ffout, g_ffout);   SYM(feat0, g_feat0);
    SYM(x, g_x);           SYM(hh, g_hh);         SYM(src, g_src);
    SYM(dstT, g_dstT);     SYM(stat, g_stat);     SYM(anum, g_anum);
    SYM(adj, g_adj);       SYM(adjd, g_adjd);     SYM(pos, g_pos);
    SYM(vm, g_vm);         SYM(xq, g_xq);         SYM(xk, g_xk);
    SYM(w2h, g_w2h);       SYM(wqkvh, g_wqkvh);   SYM(woh, g_woh);
    SYM(ff1h, g_ff1h);     SYM(ff2h, g_ff2h);     SYM(gatWh, g_gatWh);
    SYM(dgatWh, g_dgatWh); SYM(clsWqh, g_clsWqh); SYM(clsWkh, g_clsWkh);

    __half* tr_emb = emb;
    __half* det_emb = emb + (size_t)TM * DD;

    // ---- weight fp32 -> fp16, one launch ----
    {
        WPack p;
        p.s[0] = W2;    p.d[0] = w2h;    p.n[0] = 65536;
        p.s[1] = Wqkv;  p.d[1] = wqkvh;  p.n[1] = 196608;
        p.s[2] = Wo;    p.d[2] = woh;    p.n[2] = 65536;
        p.s[3] = ff1;   p.d[3] = ff1h;   p.n[3] = 262144;
        p.s[4] = ff2;   p.d[4] = ff2h;   p.n[4] = 262144;
        p.s[5] = gatW;  p.d[5] = gatWh;  p.n[5] = 131072;
        p.s[6] = dgatW; p.d[6] = dgatWh; p.n[6] = 131072;
        p.s[7] = clsWq; p.d[7] = clsWqh; p.n[7] = 131072;
        p.s[8] = clsWk; p.d[8] = clsWkh; p.n[8] = 131072;
        k_f2h_all<<<dim3(256, 9), 256>>>(p);
    }

    // ---- feature MLP (merged tr+det) ----
    k_feat1<<<(TM + ND) / 4, 256>>>(tracks, dets, W1, b1, h1);
    run_big(h1, 256, 0, w2h, 256, 0, emb, 256, 0,
            TM + ND, 256, 256, 1, b2, nullptr, 0, nullptr, 0, F_BIAS | F_OUT16, false);

    // ---- encoder (only r=0 outputs needed downstream) ----
    k_ln_h<<<TM / 8, 256>>>(tr_emb, lnb);
    run_big(lnb, 256, 0, wqkvh + 256, 768, 0, kv, 512, 0,
            TM, 512, 256, 1, nullptr, nullptr, 0, nullptr, 0, F_OUT16, false);
    run_big(lnb, 2048, 0, wqkvh, 768, 0, q0, 256, 0,
            TT, 256, 256, 1, nullptr, nullptr, 0, nullptr, 0, F_OUT16, false);
    k_attn<<<TT, 256>>>(q0, kv, o0);
    run_big(o0, 256, 0, woh, 256, 0, x1, 256, 0,
            TT, 256, 256, 1, nullptr, tr_emb, 2048, nullptr, 0, F_AUX, false);
    k_ln_f<<<TT / 8, 256>>>(x1, ln2);
    run_big(ln2, 256, 0, ff1h, 1024, 0, ffh, 1024, 0,
            TT, 1024, 256, 1, nullptr, nullptr, 0, nullptr, 0, F_RELU | F_OUT16, false);
    run_big(ffh, 1024, 0, ff2h, 256, 0, ffout, 256, 0,
            TT, 256, 1024, 1, nullptr, nullptr, 0, nullptr, 0, 0, false);
    k_feat0<<<ROWS1 / 4, 256>>>(tr_emb, x1, ffout, det_emb, feat0, x);

    // ---- adjacency ----
    k_posvm<<<64, 256>>>(tracks, dets, tmarks, dmarks, pos, vm);
    k_adj<<<dim3(NN1, BB), 256>>>(pos, vm, adj);
    k_adjd<<<dim3(NNd, BB), 128>>>(pos, vm, adjd);

    // ---- main GAT x2 ----
    for (int l = 0; l < 2; l++) {
        run_big(x, 256, 0, gatWh + (size_t)l * 65536, 256, 0, hh, 256, 0,
                ROWS1, 256, 256, 1, nullptr, nullptr, 0, nullptr, 0, F_OUT16, false);
        k_srcdst<<<ROWS1 / 8, 256>>>(hh, gata + (size_t)l * 512, src, dstT, NN1);
        k_rowstat<<<dim3(NN1, BB), 128>>>(src, dstT, adj, stat, anum, NN1);
        agg_fused<false><<<dim3(1, NN1 / 128, BB * HH), 256>>>(anum, stat, hh, feat0, x, NN1);
    }

    // ---- main scores (dual xq/xk; asso fused into epilogue) ----
    run_big(x, 256, 0, clsWqh, 256, 0, xq, 256, 0,
            ROWS1, 256, 256, 2, nullptr, nullptr, 0, nullptr, 0, F_OUT16, false,
            clsWkh, xk, 1);
    run_big(xq, 256, (long long)NN1 * 256, xk, 256, (long long)NN1 * 256,
            out_scores, NN1, (long long)NN1 * NN1,
            NN1, NN1, 256, BB, nullptr, nullptr, 0,
            adj, (long long)NN1 * NN1, F_SIG | F_ASSO, true,
            nullptr, nullptr, 0, out_asso);

    // ---- detection GAT x2 (aux = fp16 det_emb directly) ----
    for (int l = 0; l < 2; l++) {
        const __half* xin = (l == 0) ? det_emb : x;
        run_big(xin, 256, 0, dgatWh + (size_t)l * 65536, 256, 0, hh, 256, 0,
                ND, 256, 256, 1, nullptr, nullptr, 0, nullptr, 0, F_OUT16, false);
        k_srcdst<<<ND / 8, 256>>>(hh, dgata + (size_t)l * 512, src, dstT, NNd);
        k_rowstat<<<dim3(NNd, BB), 128>>>(src, dstT, adjd, stat, anum, NNd);
        agg_fused<true><<<dim3(1, NNd / 128, BB * HH), 256>>>(anum, stat, hh, det_emb, x, NNd);
    }

    // ---- detection scores (dual xq/xk) ----
    run_big(x, 256, 0, clsWqh + 65536, 256, 0, xq, 256, 0,
            ND, 256, 256, 2, nullptr, nullptr, 0, nullptr, 0, F_OUT16, false,
            clsWkh + 65536, xk, 1);
    run_big(xq, 256, (long long)NNd * 256, xk, 256, (long long)NNd * 256,
            out_det, NNd, (long long)NNd * NNd,
            NNd, NNd, 256, BB, nullptr, nullptr, 0,
            adjd, (long long)NNd * NNd, F_SIG | F_DIAG, true);
}

// round 16
// speedup vs baseline: 1.0621x; 1.0008x over previous
#include <cuda_runtime.h>
#include <cuda_fp16.h>
#include <math.h>
#include <stdint.h>

// ---------------------------------------------------------------------------
// Problem dims
// ---------------------------------------------------------------------------
#define BB 16
#define MM 512
#define NNd 512
#define RR 8
#define DD 256
#define HH 4
#define NN1 1024
#define TM  (BB*MM*RR)    // 65536
#define TT  (BB*MM)       // 8192
#define ND  (BB*NNd)      // 8192
#define ROWS1 (BB*NN1)    // 16384

#define F_BIAS 1
#define F_RELU 2
#define F_AUX  4
#define F_SIG  8
#define F_DIAG 16
#define F_OUT16 32
#define F_ASSO 64

// ---------------------------------------------------------------------------
// Scratch
// ---------------------------------------------------------------------------
__device__ __half g_h1[(TM+ND)*DD];
__device__ __half g_emb[(TM+ND)*DD];
__device__ __half g_lnb[TM*DD];
__device__ __half g_kv[TM*512];
__device__ __half g_q0[TT*DD];
__device__ __half g_o0[TT*DD];
__device__ float  g_x1[TT*DD];
__device__ __half g_ln2[TT*DD];
__device__ __half g_ffh[TT*1024];
__device__ float  g_ffout[TT*DD];
__device__ float  g_feat0[ROWS1*DD];
__device__ __half g_x[ROWS1*DD];
__device__ __half g_hh[ROWS1*DD];
__device__ float g_src[ROWS1*HH];
__device__ float g_dstT[BB*HH*NN1];
__device__ float2 g_stat[BB*HH*NN1];
__device__ __half g_anum[(size_t)BB*HH*NN1*NN1];
__device__ unsigned char g_adj[(size_t)BB*NN1*NN1];
__device__ unsigned char g_adjd[(size_t)BB*NNd*NNd];
__device__ float g_pos[BB*NN1*2];
__device__ unsigned char g_vm[BB*NN1];
__device__ __half g_xq[ROWS1*DD];
__device__ __half g_xk[ROWS1*DD];
// fp16 weights
__device__ __half g_w2h[256*256];
__device__ __half g_wqkvh[256*768];
__device__ __half g_woh[256*256];
__device__ __half g_ff1h[256*1024];
__device__ __half g_ff2h[1024*256];
__device__ __half g_gatWh[2*256*256];
__device__ __half g_dgatWh[2*256*256];
__device__ __half g_clsWqh[2*256*256];
__device__ __half g_clsWkh[2*256*256];

// ---------------------------------------------------------------------------
// helpers
// ---------------------------------------------------------------------------
__device__ __forceinline__ uint32_t pk(float lo, float hi) {
    __half2 v = __floats2half2_rn(lo, hi);
    return *reinterpret_cast<uint32_t*>(&v);
}
__device__ __forceinline__ void mma_f16(float* c, const uint32_t* a, const uint32_t* b) {
    asm volatile(
        "mma.sync.aligned.m16n8k16.row.col.f32.f16.f16.f32 "
        "{%0,%1,%2,%3}, {%4,%5,%6,%7}, {%8,%9}, {%0,%1,%2,%3};\n"
        : "+f"(c[0]), "+f"(c[1]), "+f"(c[2]), "+f"(c[3])
        : "r"(a[0]), "r"(a[1]), "r"(a[2]), "r"(a[3]), "r"(b[0]), "r"(b[1]));
}
__device__ __forceinline__ void ldm_x4(uint32_t* r, uint32_t addr) {
    asm volatile("ldmatrix.sync.aligned.m8n8.x4.shared.b16 {%0,%1,%2,%3}, [%4];"
        : "=r"(r[0]), "=r"(r[1]), "=r"(r[2]), "=r"(r[3]) : "r"(addr));
}
__device__ __forceinline__ void ldm_x4_t(uint32_t* r, uint32_t addr) {
    asm volatile("ldmatrix.sync.aligned.m8n8.x4.trans.shared.b16 {%0,%1,%2,%3}, [%4];"
        : "=r"(r[0]), "=r"(r[1]), "=r"(r[2]), "=r"(r[3]) : "r"(addr));
}
__device__ __forceinline__ uint32_t cvs(const void* p) {
    return (uint32_t)__cvta_generic_to_shared(p);
}
__device__ __forceinline__ void cp16(uint32_t dst, const void* src) {
    asm volatile("cp.async.cg.shared.global [%0], [%1], 16;" :: "r"(dst), "l"(src));
}
__device__ __forceinline__ void cp8(uint32_t dst, const void* src) {
    asm volatile("cp.async.ca.shared.global [%0], [%1], 8;" :: "r"(dst), "l"(src));
}
__device__ __forceinline__ void cp4(uint32_t dst, const void* src) {
    asm volatile("cp.async.ca.shared.global [%0], [%1], 4;" :: "r"(dst), "l"(src));
}
#define CP_COMMIT() asm volatile("cp.async.commit_group;")
#define CP_WAIT1()  asm volatile("cp.async.wait_group 1;")
#define CP_WAIT0()  asm volatile("cp.async.wait_group 0;")

// combined weight fp32->fp16
struct WPack {
    const float* s[9];
    __half* d[9];
    int n[9];
};
__global__ void k_f2h_all(WPack p)
{
    int g = blockIdx.y;
    int i = (blockIdx.x * 256 + threadIdx.x) * 4;
    if (i >= p.n[g]) return;
    float4 v = *(const float4*)(p.s[g] + i);
    uint2 o;
    o.x = pk(v.x, v.y);
    o.y = pk(v.z, v.w);
    *(uint2*)(p.d[g] + i) = o;
}

// ---------------------------------------------------------------------------
// BIG GEMM (fp16, cp.async 3-stage, BK=32): CTA MTx128, 256 thr.
// MT=128: warp tile 64x32. MT=64: warp tile 32x32 (doubles grid for small M).
// Dynamic smem layout: A region (3 stages x 2 chunks x MT*48B), B at word 9216.
// ---------------------------------------------------------------------------
#define BREG    9216     // word offset of B region
#define BSTG    12288u   // B stage stride bytes
#define BCHK    6144u    // B chunk stride bytes
template<int MT, bool TRANSB, int FLAGS>
__global__ __launch_bounds__(256, 2)
void tgemm_big(const __half* __restrict__ A, int lda, long long sA,
               const __half* __restrict__ B, int ldb, long long sB,
               void* __restrict__ Cv, int ldc, long long sC,
               int K,
               const float* __restrict__ bias,
               const __half* __restrict__ aux, int auxld,
               const unsigned char* __restrict__ adjp, long long sAdj,
               const __half* __restrict__ B2, void* __restrict__ C2v, int dual,
               float* __restrict__ asso)
{
    extern __shared__ uint32_t dsm[];
    const uint32_t A_CHK = MT * 48u;      // bytes per 16-k chunk of A
    const uint32_t A_STG = 2u * A_CHK;    // bytes per stage of A
    const int FM = MT / 32;               // m-fragments per warp

    int bz = blockIdx.z;
    int bzA = bz;
    if (dual && bz) { B = B2; Cv = C2v; bz = 0; }
    A += (long long)bz * sA;
    B += (long long)bz * sB;
    size_t coff = (size_t)((long long)bz * sC);
    if (FLAGS & F_SIG) adjp += (long long)bz * sAdj;

    int m0 = blockIdx.y * MT, n0 = blockIdx.x * 128;

    int tid = threadIdx.x;

    // A staging
    const __half* gA;
    uint32_t aD;
    if (MT == 128) {
        int arow = tid >> 1, ah = tid & 1;
        gA = A + (size_t)(m0 + arow) * lda + ah * 8;
        aD = cvs(dsm) + (arow * 12 + ah * 4) * 4;
    } else {
        int arow = tid >> 2, q = tid & 3;
        int cc = q >> 1, h = q & 1;
        gA = A + (size_t)(m0 + arow) * lda + q * 8;
        aD = cvs(dsm) + cc * A_CHK + (arow * 12 + h * 4) * 4;
    }

    // B staging
    const __half* gB;
    int kp = tid >> 5, nq = tid & 31;
    int brow = tid >> 1, bh = tid & 1;
    if (!TRANSB) gB = B + (size_t)(2 * kp) * ldb + n0 + nq * 4;
    else         gB = B + (size_t)(n0 + brow) * ldb + bh * 8;

    uint32_t bD1, bD2;
    if (!TRANSB) {
        int w0 = (2 * kp) * 68 + nq * 2;
        bD1 = cvs(&dsm[BREG + w0]);
        bD2 = cvs(&dsm[BREG + w0 + 68]);
    } else {
        bD1 = cvs(&dsm[BREG + brow * 12 + bh * 4]);
        bD2 = 0;
    }

    int w = tid >> 5, l = tid & 31;
    int mbase = (w >> 2) * (MT / 2), nbase = (w & 3) * 32;
    int grp = l >> 2, tig = l & 3;

    int lrowA = ((l >> 3) & 1) * 8 + (l & 7);
    int khalf = l >> 4;
    uint32_t aBase[FM];
    #pragma unroll
    for (int fm = 0; fm < FM; fm++)
        aBase[fm] = cvs(&dsm[(mbase + fm * 16 + lrowA) * 12 + khalf * 4]);
    uint32_t bBase[2];
    if (!TRANSB) {
        int krow = ((l >> 4) & 1) * 8 + (l & 7);
        int nblk = ((l >> 3) & 1) * 8;
        #pragma unroll
        for (int fp = 0; fp < 2; fp++)
            bBase[fp] = cvs(&dsm[BREG + krow * 68 + ((nbase + fp * 16 + nblk) >> 1)]);
    } else {
        #pragma unroll
        for (int fp = 0; fp < 2; fp++)
            bBase[fp] = cvs(&dsm[BREG + (nbase + fp * 16 + lrowA) * 12 + khalf * 4]);
    }

    float acc[FM][4][4];
    #pragma unroll
    for (int i = 0; i < FM; i++)
        #pragma unroll
        for (int j = 0; j < 4; j++)
            #pragma unroll
            for (int q = 0; q < 4; q++) acc[i][j][q] = 0.f;

    int nk = K >> 5;   // 32-k stages

    // prologue: issue stages 0 and 1
    #pragma unroll
    for (int p = 0; p < 2; p++) {
        if (p < nk) {
            if (MT == 128) {
                #pragma unroll
                for (int c = 0; c < 2; c++)
                    cp16(aD + p * A_STG + c * A_CHK, gA + p * 32 + c * 16);
            } else {
                cp16(aD + p * A_STG, gA + p * 32);
            }
            #pragma unroll
            for (int c = 0; c < 2; c++) {
                uint32_t off = p * BSTG + c * BCHK;
                int k0 = p * 32 + c * 16;
                if (!TRANSB) {
                    cp8(bD1 + off, gB + (size_t)k0 * ldb);
                    cp8(bD2 + off, gB + (size_t)(k0 + 1) * ldb);
                } else {
                    cp16(bD1 + off, gB + k0);
                }
            }
            CP_COMMIT();
        }
    }

    int s = 0;
    for (int i = 0; i < nk; i++) {
        if (i + 1 < nk) CP_WAIT1(); else CP_WAIT0();
        __syncthreads();
        #pragma unroll
        for (int c = 0; c < 2; c++) {
            uint32_t aoff = (uint32_t)s * A_STG + c * A_CHK;
            uint32_t boff = (uint32_t)s * BSTG + c * BCHK;
            uint32_t af[FM][4];
            #pragma unroll
            for (int fm = 0; fm < FM; fm++) ldm_x4(af[fm], aBase[fm] + aoff);
            uint32_t bfr[4][2];
            #pragma unroll
            for (int fp = 0; fp < 2; fp++) {
                uint32_t t4[4];
                if (!TRANSB) ldm_x4_t(t4, bBase[fp] + boff);
                else         ldm_x4(t4, bBase[fp] + boff);
                bfr[fp * 2][0] = t4[0]; bfr[fp * 2 + 1][0] = t4[1];
                bfr[fp * 2][1] = t4[2]; bfr[fp * 2 + 1][1] = t4[3];
            }
            #pragma unroll
            for (int fm = 0; fm < FM; fm++)
                #pragma unroll
                for (int fn = 0; fn < 4; fn++)
                    mma_f16(acc[fm][fn], af[fm], bfr[fn]);
        }
        if (i + 2 < nk) {
            int st = s >= 1 ? s - 1 : s + 2;   // (s+2)%3
            int kb = (i + 2) * 32;
            if (MT == 128) {
                #pragma unroll
                for (int c = 0; c < 2; c++)
                    cp16(aD + (uint32_t)st * A_STG + c * A_CHK, gA + kb + c * 16);
            } else {
                cp16(aD + (uint32_t)st * A_STG, gA + kb);
            }
            #pragma unroll
            for (int c = 0; c < 2; c++) {
                uint32_t off = (uint32_t)st * BSTG + c * BCHK;
                int k0 = kb + c * 16;
                if (!TRANSB) {
                    cp8(bD1 + off, gB + (size_t)k0 * ldb);
                    cp8(bD2 + off, gB + (size_t)(k0 + 1) * ldb);
                } else {
                    cp16(bD1 + off, gB + k0);
                }
            }
            CP_COMMIT();
        }
        s = (s + 1) == 3 ? 0 : s + 1;
    }

    // epilogue
    #pragma unroll
    for (int fm = 0; fm < FM; fm++) {
        int row0 = m0 + mbase + fm * 16 + grp;
        #pragma unroll
        for (int fn = 0; fn < 4; fn++) {
            int col = n0 + nbase + fn * 8 + 2 * tig;
            float v0 = acc[fm][fn][0], v1 = acc[fm][fn][1];
            float v2 = acc[fm][fn][2], v3 = acc[fm][fn][3];
            if (FLAGS & F_BIAS) {
                float bb0 = bias[col], bb1 = bias[col + 1];
                v0 += bb0; v1 += bb1; v2 += bb0; v3 += bb1;
            }
            if (FLAGS & F_RELU) {
                v0 = fmaxf(v0, 0.f); v1 = fmaxf(v1, 0.f);
                v2 = fmaxf(v2, 0.f); v3 = fmaxf(v3, 0.f);
            }
            if (FLAGS & F_AUX) {
                float2 a0 = __half22float2(*(const __half2*)(aux + (size_t)row0 * auxld + col));
                float2 a8 = __half22float2(*(const __half2*)(aux + (size_t)(row0 + 8) * auxld + col));
                v0 += a0.x; v1 += a0.y; v2 += a8.x; v3 += a8.y;
            }
            if (FLAGS & F_SIG) {
                const unsigned char* q0p = adjp + (size_t)row0 * ldc + col;
                const unsigned char* q8p = adjp + (size_t)(row0 + 8) * ldc + col;
                v0 = q0p[0] ? 1.f / (1.f + __expf(-v0 * 0.0625f)) : 0.f;
                v1 = q0p[1] ? 1.f / (1.f + __expf(-v1 * 0.0625f)) : 0.f;
                v2 = q8p[0] ? 1.f / (1.f + __expf(-v2 * 0.0625f)) : 0.f;
                v3 = q8p[1] ? 1.f / (1.f + __expf(-v3 * 0.0625f)) : 0.f;
                if (FLAGS & F_DIAG) {
                    if (row0 == col) v0 = 0.f;
                    if (row0 == col + 1) v1 = 0.f;
                    if (row0 + 8 == col) v2 = 0.f;
                    if (row0 + 8 == col + 1) v3 = 0.f;
                }
            }
            if (FLAGS & F_OUT16) {
                __half* Ch = (__half*)Cv + coff;
                *(uint32_t*)&Ch[(size_t)row0 * ldc + col] = pk(v0, v1);
                *(uint32_t*)&Ch[(size_t)(row0 + 8) * ldc + col] = pk(v2, v3);
            } else {
                float* C = (float*)Cv + coff;
                *(float2*)&C[(size_t)row0 * ldc + col] = make_float2(v0, v1);
                *(float2*)&C[(size_t)(row0 + 8) * ldc + col] = make_float2(v2, v3);
            }
            if (FLAGS & F_ASSO) {
                if (col >= 512) {
                    int jc = col - 512;
                    if (row0 < 512)
                        *(float2*)&asso[((size_t)bzA * 512 + row0) * 512 + jc] = make_float2(v0, v1);
                    if (row0 + 8 < 512)
                        *(float2*)&asso[((size_t)bzA * 512 + row0 + 8) * 512 + jc] = make_float2(v2, v3);
                }
            }
        }
    }
}

// ---------------------------------------------------------------------------
// GAT aggregation (fp16 GEMM, cp.async 3-stage): CTA 128x64, warp 32x32.
// ---------------------------------------------------------------------------
template<bool AUX16>
__global__ __launch_bounds__(256)
void agg_fused(const __half* __restrict__ anum, const float2* __restrict__ stat,
               const __half* __restrict__ hmat,
               const void* __restrict__ auxv, __half* __restrict__ xout, int NN)
{
    int z = blockIdx.z;
    int b = z >> 2, h = z & 3;
    const __half* B = hmat + (size_t)b * NN * 256 + h * 64;
    __half* C = xout + (size_t)b * NN * 256 + h * 64;
    size_t auxbase = (size_t)b * NN * 256 + h * 64;
    const float* auxf = (const float*)auxv + auxbase;
    const __half* auxh = (const __half*)auxv + auxbase;
    const float2* statz = stat + (size_t)z * NN;

    int m0 = blockIdx.y * 128;
    __shared__ uint32_t As[3][1536];
    __shared__ uint32_t Bs[3][576];
    int tid = threadIdx.x;

    int arow = tid >> 1, ahalf = tid & 1;
    const __half* gA = anum + ((size_t)z * NN + m0 + arow) * NN + ahalf * 8;

    int kp = tid >> 5, nq = tid & 31;
    const __half* gB = B + (size_t)(2 * kp) * 256 + 2 * nq;

    uint32_t aD = cvs(&As[0][arow * 12 + ahalf * 4]);
    uint32_t bD1 = cvs(&Bs[0][(2 * kp) * 36 + nq]);
    uint32_t bD2 = cvs(&Bs[0][(2 * kp + 1) * 36 + nq]);

    int w = tid >> 5, l = tid & 31;
    int wm = w >> 1, wn = w & 1;
    int mrow = wm * 32, ncol = wn * 32;
    int grp = l >> 2, tig = l & 3;

    int lrowA = ((l >> 3) & 1) * 8 + (l & 7);
    int khalf = l >> 4;
    uint32_t aBase[2];
    #pragma unroll
    for (int fm = 0; fm < 2; fm++)
        aBase[fm] = cvs(&As[0][(mrow + fm * 16 + lrowA) * 12 + khalf * 4]);
    int krow = ((l >> 4) & 1) * 8 + (l & 7);
    int nblk = ((l >> 3) & 1) * 8;
    uint32_t bBase[2];
    #pragma unroll
    for (int fp = 0; fp < 2; fp++)
        bBase[fp] = cvs(&Bs[0][krow * 36 + ((ncol + fp * 16 + nblk) >> 1)]);

    float acc[2][4][4];
    #pragma unroll
    for (int i = 0; i < 2; i++)
        #pragma unroll
        for (int j = 0; j < 4; j++)
            #pragma unroll
            for (int q = 0; q < 4; q++) acc[i][j][q] = 0.f;

    int nk = NN >> 4;

    {
        cp16(aD, gA);
        cp4(bD1, gB);
        cp4(bD2, gB + 256);
        CP_COMMIT();
        if (nk > 1) {
            cp16(aD + 6144, gA + 16);
            cp4(bD1 + 2304, gB + 16 * 256);
            cp4(bD2 + 2304, gB + 17 * 256);
            CP_COMMIT();
        }
    }

    int s = 0;
    for (int i = 0; i < nk; i++) {
        if (i + 1 < nk) CP_WAIT1(); else CP_WAIT0();
        __syncthreads();
        uint32_t sa = (uint32_t)(s * 6144);
        uint32_t sbo = (uint32_t)(s * 2304);
        uint32_t af[2][4];
        #pragma unroll
        for (int fm = 0; fm < 2; fm++) ldm_x4(af[fm], aBase[fm] + sa);
        uint32_t bfr[4][2];
        #pragma unroll
        for (int fp = 0; fp < 2; fp++) {
            uint32_t t4[4];
            ldm_x4_t(t4, bBase[fp] + sbo);
            bfr[fp * 2][0] = t4[0]; bfr[fp * 2 + 1][0] = t4[1];
            bfr[fp * 2][1] = t4[2]; bfr[fp * 2 + 1][1] = t4[3];
        }
        #pragma unroll
        for (int fm = 0; fm < 2; fm++)
            #pragma unroll
            for (int fn = 0; fn < 4; fn++)
                mma_f16(acc[fm][fn], af[fm], bfr[fn]);
        if (i + 2 < nk) {
            int st = s >= 1 ? s - 1 : s + 2;
            int k0 = (i + 2) * 16;
            cp16(aD + st * 6144, gA + k0);
            cp4(bD1 + st * 2304, gB + (size_t)k0 * 256);
            cp4(bD2 + st * 2304, gB + (size_t)(k0 + 1) * 256);
            CP_COMMIT();
        }
        s = (s + 1) == 3 ? 0 : s + 1;
    }

    #pragma unroll
    for (int fm = 0; fm < 2; fm++) {
        int row = m0 + mrow + fm * 16 + grp;
        float inv0 = statz[row].y;
        float inv8 = statz[row + 8].y;
        #pragma unroll
        for (int fn = 0; fn < 4; fn++) {
            int col = ncol + fn * 8 + 2 * tig;
            float v0 = acc[fm][fn][0] * inv0, v1 = acc[fm][fn][1] * inv0;
            float v2 = acc[fm][fn][2] * inv8, v3 = acc[fm][fn][3] * inv8;
            v0 = (v0 > 0.f) ? v0 : expm1f(v0);
            v1 = (v1 > 0.f) ? v1 : expm1f(v1);
            v2 = (v2 > 0.f) ? v2 : expm1f(v2);
            v3 = (v3 > 0.f) ? v3 : expm1f(v3);
            float2 x0, x1;
            if (AUX16) {
                x0 = __half22float2(*(const __half2*)&auxh[(size_t)row * 256 + col]);
                x1 = __half22float2(*(const __half2*)&auxh[(size_t)(row + 8) * 256 + col]);
            } else {
                x0 = *(const float2*)&auxf[(size_t)row * 256 + col];
                x1 = *(const float2*)&auxf[(size_t)(row + 8) * 256 + col];
            }
            *(uint32_t*)&C[(size_t)row * 256 + col] =
                pk(0.5f * v0 + 0.5f * x0.x, 0.5f * v1 + 0.5f * x0.y);
            *(uint32_t*)&C[(size_t)(row + 8) * 256 + col] =
                pk(0.5f * v2 + 0.5f * x1.x, 0.5f * v3 + 0.5f * x1.y);
        }
    }
}

// ---------------------------------------------------------------------------
// Small kernels
// ---------------------------------------------------------------------------
__global__ void k_feat1(const float* __restrict__ tr, const float* __restrict__ de,
                        const float* __restrict__ W1, const float* __restrict__ b1,
                        __half* __restrict__ out)
{
    int tid = threadIdx.x;
    size_t row = (size_t)blockIdx.x * 4 + (tid >> 6);
    int c4 = (tid & 63) * 4;
    const float* xr = (row < TM) ? (tr + row * 4) : (de + (row - TM) * 4);
    const float4 x4 = *(const float4*)xr;
    float4 v = *(const float4*)(b1 + c4);
    float4 w0 = *(const float4*)(W1 + c4);
    float4 w1 = *(const float4*)(W1 + 256 + c4);
    float4 w2 = *(const float4*)(W1 + 512 + c4);
    float4 w3 = *(const float4*)(W1 + 768 + c4);
    v.x += x4.x * w0.x + x4.y * w1.x + x4.z * w2.x + x4.w * w3.x;
    v.y += x4.x * w0.y + x4.y * w1.y + x4.z * w2.y + x4.w * w3.y;
    v.z += x4.x * w0.z + x4.y * w1.z + x4.z * w2.z + x4.w * w3.z;
    v.w += x4.x * w0.w + x4.y * w1.w + x4.z * w2.w + x4.w * w3.w;
    v.x = (v.x > 0.f) ? v.x : (__expf(v.x) - 1.f);
    v.y = (v.y > 0.f) ? v.y : (__expf(v.y) - 1.f);
    v.z = (v.z > 0.f) ? v.z : (__expf(v.z) - 1.f);
    v.w = (v.w > 0.f) ? v.w : (__expf(v.w) - 1.f);
    uint2 p;
    p.x = pk(v.x, v.y);
    p.y = pk(v.z, v.w);
    *(uint2*)(out + row * 256 + c4) = p;
}

__global__ void k_ln_h(const __half* __restrict__ in, __half* __restrict__ out)
{
    int w = threadIdx.x >> 5, lane = threadIdx.x & 31;
    size_t row = (size_t)blockIdx.x * 8 + w;
    const uint4* ip = (const uint4*)(in + row * 256);
    uint4 u = ip[lane];
    float2 f0 = __half22float2(*(__half2*)&u.x);
    float2 f1 = __half22float2(*(__half2*)&u.y);
    float2 f2 = __half22float2(*(__half2*)&u.z);
    float2 f3 = __half22float2(*(__half2*)&u.w);
    float a = f0.x + f0.y + f1.x + f1.y + f2.x + f2.y + f3.x + f3.y;
    float b = f0.x*f0.x + f0.y*f0.y + f1.x*f1.x + f1.y*f1.y
            + f2.x*f2.x + f2.y*f2.y + f3.x*f3.x + f3.y*f3.y;
    #pragma unroll
    for (int o = 16; o; o >>= 1) {
        a += __shfl_xor_sync(0xffffffff, a, o);
        b += __shfl_xor_sync(0xffffffff, b, o);
    }
    float mean = a * (1.f / 256.f);
    float var = b * (1.f / 256.f) - mean * mean;
    float rstd = rsqrtf(var + 1e-5f);
    uint4 r;
    r.x = pk((f0.x - mean) * rstd, (f0.y - mean) * rstd);
    r.y = pk((f1.x - mean) * rstd, (f1.y - mean) * rstd);
    r.z = pk((f2.x - mean) * rstd, (f2.y - mean) * rstd);
    r.w = pk((f3.x - mean) * rstd, (f3.y - mean) * rstd);
    ((uint4*)(out + row * 256))[lane] = r;
}

__global__ void k_ln_f(const float* __restrict__ in, __half* __restrict__ out)
{
    int w = threadIdx.x >> 5, lane = threadIdx.x & 31;
    size_t row = (size_t)blockIdx.x * 8 + w;
    const float4* ip = (const float4*)(in + row * 256);
    float4 v0 = ip[lane], v1 = ip[lane + 32];
    float a = v0.x + v0.y + v0.z + v0.w + v1.x + v1.y + v1.z + v1.w;
    float b = v0.x*v0.x + v0.y*v0.y + v0.z*v0.z + v0.w*v0.w
            + v1.x*v1.x + v1.y*v1.y + v1.z*v1.z + v1.w*v1.w;
    #pragma unroll
    for (int o = 16; o; o >>= 1) {
        a += __shfl_xor_sync(0xffffffff, a, o);
        b += __shfl_xor_sync(0xffffffff, b, o);
    }
    float mean = a * (1.f / 256.f);
    float var = b * (1.f / 256.f) - mean * mean;
    float rstd = rsqrtf(var + 1e-5f);
    uint2 p0, p1;
    p0.x = pk((v0.x - mean) * rstd, (v0.y - mean) * rstd);
    p0.y = pk((v0.z - mean) * rstd, (v0.w - mean) * rstd);
    p1.x = pk((v1.x - mean) * rstd, (v1.y - mean) * rstd);
    p1.y = pk((v1.z - mean) * rstd, (v1.w - mean) * rstd);
    *(uint2*)(out + row * 256 + lane * 4) = p0;
    *(uint2*)(out + row * 256 + 128 + lane * 4) = p1;
}

__global__ void k_attn(const __half* __restrict__ q0, const __half* __restrict__ kv,
                       __half* __restrict__ o0)
{
    size_t t = blockIdx.x;
    int d = threadIdx.x;
    int w = d >> 5, lane = d & 31, h = d >> 6;
    __shared__ float red[8][8];
    const __half* kvb = kv + t * 8 * 512;
    float qd = __half2float(q0[t * 256 + d]);
    #pragma unroll
    for (int s = 0; s < 8; s++) {
        float v = qd * __half2float(kvb[s * 512 + d]);
        #pragma unroll
        for (int o = 16; o; o >>= 1) v += __shfl_xor_sync(0xffffffff, v, o);
        if (lane == 0) red[w][s] = v;
    }
    __syncthreads();
    float lg[8];
    float m = -1e30f;
    #pragma unroll
    for (int s = 0; s < 8; s++) {
        lg[s] = (red[2 * h][s] + red[2 * h + 1][s]) * 0.125f;
        m = fmaxf(m, lg[s]);
    }
    float sum = 0.f;
    #pragma unroll
    for (int s = 0; s < 8; s++) { lg[s] = __expf(lg[s] - m); sum += lg[s]; }
    float inv = 1.f / sum;
    float o = 0.f;
    #pragma unroll
    for (int s = 0; s < 8; s++) o += lg[s] * inv * __half2float(kvb[s * 512 + 256 + d]);
    o0[t * 256 + d] = __float2half(o);
}

__global__ void k_feat0(const __half* __restrict__ tr_emb, const float* __restrict__ x1,
                        const float* __restrict__ ffout, const __half* __restrict__ det_emb,
                        float* __restrict__ feat0, __half* __restrict__ x)
{
    int tid = threadIdx.x;
    size_t row = (size_t)blockIdx.x * 4 + (tid >> 6);
    int c4 = (tid & 63) * 4;
    int i = (int)(row & 1023);
    int b = (int)(row >> 10);
    float4 v;
    if (i < 512) {
        size_t t = (size_t)b * 512 + i;
        uint2 te = *(const uint2*)(tr_emb + t * 2048 + c4);
        float2 e01 = __half22float2(*(__half2*)&te.x);
        float2 e23 = __half22float2(*(__half2*)&te.y);
        float4 a = *(const float4*)(x1 + t * 256 + c4);
        float4 f = *(const float4*)(ffout + t * 256 + c4);
        v.x = e01.x + 0.9f * (a.x + f.x);
        v.y = e01.y + 0.9f * (a.y + f.y);
        v.z = e23.x + 0.9f * (a.z + f.z);
        v.w = e23.y + 0.9f * (a.w + f.w);
    } else {
        size_t t = (size_t)b * 512 + (i - 512);
        uint2 de = *(const uint2*)(det_emb + t * 256 + c4);
        float2 e01 = __half22float2(*(__half2*)&de.x);
        float2 e23 = __half22float2(*(__half2*)&de.y);
        v = make_float4(e01.x, e01.y, e23.x, e23.y);
    }
    *(float4*)(feat0 + row * 256 + c4) = v;
    uint2 p;
    p.x = pk(v.x, v.y);
    p.y = pk(v.z, v.w);
    *(uint2*)(x + row * 256 + c4) = p;
}

__global__ void k_posvm(const float* __restrict__ tracks, const float* __restrict__ dets,
                        const int* __restrict__ tmarks, const int* __restrict__ dmarks,
                        float* __restrict__ pos, unsigned char* __restrict__ vm)
{
    int idx = blockIdx.x * 256 + threadIdx.x;
    if (idx >= BB * NN1) return;
    int b = idx >> 10, i = idx & 1023;
    float x, y; unsigned char v;
    if (i < 512) {
        const float* p = tracks + ((size_t)(b * 512 + i)) * 8 * 4;
        x = p[0]; y = p[1];
        v = (i < tmarks[b]);
    } else {
        int n = i - 512;
        const float* p = dets + ((size_t)(b * 512 + n)) * 4;
        x = p[0]; y = p[1];
        v = (n < dmarks[b]);
    }
    pos[idx * 2] = x; pos[idx * 2 + 1] = y; vm[idx] = v;
}

__global__ void k_adj(const float* __restrict__ pos, const unsigned char* __restrict__ vm,
                      unsigned char* __restrict__ adj)
{
    int i = blockIdx.x, b = blockIdx.y;
    size_t base = (size_t)b * NN1;
    const float2* p2 = (const float2*)pos;
    float2 pi = p2[base + i];
    unsigned char vi = vm[base + i];
    int j0 = threadIdx.x * 4;
    uchar4 r;
    unsigned char* rp = &r.x;
    #pragma unroll
    for (int u = 0; u < 4; u++) {
        int j = j0 + u;
        float2 pj = p2[base + j];
        float dx = pi.x - pj.x, dy = pi.y - pj.y;
        rp[u] = (unsigned char)((dx * dx + dy * dy < 4.0f) && vi && vm[base + j]);
    }
    ((uchar4*)(adj + ((size_t)b * NN1 + i) * NN1))[threadIdx.x] = r;
}

__global__ void k_adjd(const float* __restrict__ pos, const unsigned char* __restrict__ vm,
                       unsigned char* __restrict__ adjd)
{
    int i = blockIdx.x, b = blockIdx.y;
    size_t base = (size_t)b * NN1 + 512;
    const float2* p2 = (const float2*)pos;
    float2 pi = p2[base + i];
    unsigned char vi = vm[base + i];
    int j0 = threadIdx.x * 4;
    uchar4 r;
    unsigned char* rp = &r.x;
    #pragma unroll
    for (int u = 0; u < 4; u++) {
        int j = j0 + u;
        float2 pj = p2[base + j];
        float dx = pi.x - pj.x, dy = pi.y - pj.y;
        rp[u] = (unsigned char)((dx * dx + dy * dy < 4.0f) && vi && vm[base + j]);
    }
    ((uchar4*)(adjd + ((size_t)b * NNd + i) * NNd))[threadIdx.x] = r;
}

// src/dst projections: warp per row, 8 rows/block.
__global__ void k_srcdst(const __half* __restrict__ Hm, const float* __restrict__ a0,
                         float* __restrict__ src, float* __restrict__ dstT, int NN)
{
    int w = threadIdx.x >> 5, lane = threadIdx.x & 31;
    size_t row = (size_t)blockIdx.x * 8 + w;
    uint4 u = ((const uint4*)(Hm + row * 256))[lane];
    float2 f0 = __half22float2(*(__half2*)&u.x);
    float2 f1 = __half22float2(*(__half2*)&u.y);
    float2 f2 = __half22float2(*(__half2*)&u.z);
    float2 f3 = __half22float2(*(__half2*)&u.w);
    const float4* s0p = (const float4*)(a0 + lane * 8);
    const float4* s1p = (const float4*)(a0 + 256 + lane * 8);
    float4 sa = s0p[0], sb = s0p[1];
    float4 ta = s1p[0], tb = s1p[1];
    float s = f0.x * sa.x + f0.y * sa.y + f1.x * sa.z + f1.y * sa.w
            + f2.x * sb.x + f2.y * sb.y + f3.x * sb.z + f3.y * sb.w;
    float t = f0.x * ta.x + f0.y * ta.y + f1.x * ta.z + f1.y * ta.w
            + f2.x * tb.x + f2.y * tb.y + f3.x * tb.z + f3.y * tb.w;
    #pragma unroll
    for (int o = 4; o; o >>= 1) {
        s += __shfl_xor_sync(0xffffffff, s, o);
        t += __shfl_xor_sync(0xffffffff, t, o);
    }
    if ((lane & 7) == 0) {
        int h = lane >> 3;
        int b = (int)(row / NN);
        int i = (int)(row - (size_t)b * NN);
        src[row * 4 + h] = s;
        dstT[((size_t)b * 4 + h) * NN + i] = t;
    }
}

__global__ void k_rowstat(const float* __restrict__ src, const float* __restrict__ dstT,
                          const unsigned char* __restrict__ adj, float2* __restrict__ stat,
                          __half* __restrict__ anum, int NN)
{
    int i = blockIdx.x, b = blockIdx.y;
    int h = threadIdx.x >> 5, lane = threadIdx.x & 31;
    int z = b * 4 + h;
    float s = src[((size_t)b * NN + i) * 4 + h];
    const uchar4* adjrow = (const uchar4*)(adj + ((size_t)b * NN + i) * NN);
    const float4* dsth = (const float4*)(dstT + ((size_t)z) * NN);
    __half* arow = anum + ((size_t)z * NN + i) * NN;
    int nq = NN >> 2;
    float mx = -1e30f;
    for (int jq = lane; jq < nq; jq += 32) {
        uchar4 a4 = adjrow[jq];
        float4 d4 = dsth[jq];
        float e0 = s + d4.x; e0 = e0 > 0.f ? e0 : 0.2f * e0; e0 = a4.x ? e0 : -1e9f;
        float e1 = s + d4.y; e1 = e1 > 0.f ? e1 : 0.2f * e1; e1 = a4.y ? e1 : -1e9f;
        float e2 = s + d4.z; e2 = e2 > 0.f ? e2 : 0.2f * e2; e2 = a4.z ? e2 : -1e9f;
        float e3 = s + d4.w; e3 = e3 > 0.f ? e3 : 0.2f * e3; e3 = a4.w ? e3 : -1e9f;
        mx = fmaxf(mx, fmaxf(fmaxf(e0, e1), fmaxf(e2, e3)));
    }
    #pragma unroll
    for (int o = 16; o; o >>= 1) mx = fmaxf(mx, __shfl_xor_sync(0xffffffff, mx, o));
    float sum = 0.f;
    for (int jq = lane; jq < nq; jq += 32) {
        uchar4 a4 = adjrow[jq];
        float4 d4 = dsth[jq];
        float e0 = s + d4.x; e0 = e0 > 0.f ? e0 : 0.2f * e0; e0 = a4.x ? e0 : -1e9f;
        float e1 = s + d4.y; e1 = e1 > 0.f ? e1 : 0.2f * e1; e1 = a4.y ? e1 : -1e9f;
        float e2 = s + d4.z; e2 = e2 > 0.f ? e2 : 0.2f * e2; e2 = a4.z ? e2 : -1e9f;
        float e3 = s + d4.w; e3 = e3 > 0.f ? e3 : 0.2f * e3; e3 = a4.w ? e3 : -1e9f;
        float n0 = __expf(e0 - mx), n1 = __expf(e1 - mx);
        float n2 = __expf(e2 - mx), n3 = __expf(e3 - mx);
        sum += n0 + n1 + n2 + n3;
        uint2 pkd;
        pkd.x = pk(n0, n1);
        pkd.y = pk(n2, n3);
        *(uint2*)(arow + jq * 4) = pkd;
    }
    #pragma unroll
    for (int o = 16; o; o >>= 1) sum += __shfl_xor_sync(0xffffffff, sum, o);
    if (lane == 0)
        stat[(size_t)z * NN + i] = make_float2(mx, 1.f / sum);
}

// ---------------------------------------------------------------------------
// Host side
// ---------------------------------------------------------------------------
#define TG_DSMEM 73728

static void run_big(const __half* A, int lda, long long sA,
                    const __half* B, int ldb, long long sB,
                    void* C, int ldc, long long sC,
                    int M, int N, int K, int batch,
                    const float* bias, const __half* aux, int auxld,
                    const unsigned char* adjp, long long sAdj,
                    int flags, bool transb, int mt = 128,
                    const __half* B2 = nullptr, void* C2 = nullptr, int dual = 0,
                    float* asso = nullptr)
{
    dim3 g(N / 128, M / mt, batch);
#define CALLBIG(MTV, T, F) do { \
        cudaFuncSetAttribute(tgemm_big<MTV, T, F>, cudaFuncAttributeMaxDynamicSharedMemorySize, TG_DSMEM); \
        tgemm_big<MTV, T, F><<<g, 256, TG_DSMEM>>>(A, lda, sA, B, ldb, sB, \
            C, ldc, sC, K, bias, aux, auxld, adjp, sAdj, B2, C2, dual, asso); \
    } while (0)
    if (mt == 64) {
        if (flags == F_OUT16)                 CALLBIG(64, false, F_OUT16);
        else if (flags == F_AUX)              CALLBIG(64, false, F_AUX);
        else                                  CALLBIG(64, false, 0);
    } else if (!transb) {
        if (flags == (F_BIAS | F_OUT16))      CALLBIG(128, false, F_BIAS | F_OUT16);
        else if (flags == F_OUT16)            CALLBIG(128, false, F_OUT16);
        else if (flags == F_AUX)              CALLBIG(128, false, F_AUX);
        else if (flags == (F_RELU | F_OUT16)) CALLBIG(128, false, F_RELU | F_OUT16);
        else                                  CALLBIG(128, false, 0);
    } else {
        if (flags == (F_SIG | F_ASSO))        CALLBIG(128, true, F_SIG | F_ASSO);
        else                                  CALLBIG(128, true, F_SIG | F_DIAG);
    }
#undef CALLBIG
}

#define SYM(p, s) cudaGetSymbolAddress((void**)&p, s)

extern "C" void kernel_launch(void* const* d_in, const int* in_sizes, int n_in,
                              void* d_out, int out_size)
{
    (void)in_sizes; (void)n_in; (void)out_size;
    const float* tracks = (const float*)d_in[0];
    const float* dets   = (const float*)d_in[1];
    const int* tmarks   = (const int*)d_in[2];
    const int* dmarks   = (const int*)d_in[3];
    const float* W1     = (const float*)d_in[4];
    const float* b1     = (const float*)d_in[5];
    const float* W2     = (const float*)d_in[6];
    const float* b2     = (const float*)d_in[7];
    const float* Wqkv   = (const float*)d_in[8];
    const float* Wo     = (const float*)d_in[9];
    const float* ff1    = (const float*)d_in[10];
    const float* ff2    = (const float*)d_in[11];
    const float* gatW   = (const float*)d_in[12];
    const float* gata   = (const float*)d_in[13];
    const float* dgatW  = (const float*)d_in[14];
    const float* dgata  = (const float*)d_in[15];
    const float* clsWq  = (const float*)d_in[16];
    const float* clsWk  = (const float*)d_in[17];

    float* out = (float*)d_out;
    float* out_scores = out;
    float* out_det    = out + (size_t)BB * NN1 * NN1;
    float* out_asso   = out_det + (size_t)BB * NNd * NNd;

    __half *h1, *emb, *lnb, *kv, *q0, *o0, *ln2, *ffh, *x, *hh, *xq, *xk, *anum;
    __half *w2h, *wqkvh, *woh, *ff1h, *ff2h, *gatWh, *dgatWh, *clsWqh, *clsWkh;
    float *x1, *ffout, *feat0, *src, *dstT, *pos;
    float2* stat;
    unsigned char *adj, *adjd, *vm;
    SYM(h1, g_h1);         SYM(emb, g_emb);       SYM(lnb, g_lnb);
    SYM(kv, g_kv);         SYM(q0, g_q0);         SYM(o0, g_o0);
    SYM(x1, g_x1);         SYM(ln2, g_ln2);       SYM(ffh, g_ffh);
    SYM(ffout, g_ffout);   SYM(feat0, g_feat0);
    SYM(x, g_x);           SYM(hh, g_hh);         SYM(src, g_src);
    SYM(dstT, g_dstT);     SYM(stat, g_stat);     SYM(anum, g_anum);
    SYM(adj, g_adj);       SYM(adjd, g_adjd);     SYM(pos, g_pos);
    SYM(vm, g_vm);         SYM(xq, g_xq);         SYM(xk, g_xk);
    SYM(w2h, g_w2h);       SYM(wqkvh, g_wqkvh);   SYM(woh, g_woh);
    SYM(ff1h, g_ff1h);     SYM(ff2h, g_ff2h);     SYM(gatWh, g_gatWh);
    SYM(dgatWh, g_dgatWh); SYM(clsWqh, g_clsWqh); SYM(clsWkh, g_clsWkh);

    __half* tr_emb = emb;
    __half* det_emb = emb + (size_t)TM * DD;

    // ---- weight fp32 -> fp16, one launch ----
    {
        WPack p;
        p.s[0] = W2;    p.d[0] = w2h;    p.n[0] = 65536;
        p.s[1] = Wqkv;  p.d[1] = wqkvh;  p.n[1] = 196608;
        p.s[2] = Wo;    p.d[2] = woh;    p.n[2] = 65536;
        p.s[3] = ff1;   p.d[3] = ff1h;   p.n[3] = 262144;
        p.s[4] = ff2;   p.d[4] = ff2h;   p.n[4] = 262144;
        p.s[5] = gatW;  p.d[5] = gatWh;  p.n[5] = 131072;
        p.s[6] = dgatW; p.d[6] = dgatWh; p.n[6] = 131072;
        p.s[7] = clsWq; p.d[7] = clsWqh; p.n[7] = 131072;
        p.s[8] = clsWk; p.d[8] = clsWkh; p.n[8] = 131072;
        k_f2h_all<<<dim3(256, 9), 256>>>(p);
    }

    // ---- feature MLP (merged tr+det) ----
    k_feat1<<<(TM + ND) / 4, 256>>>(tracks, dets, W1, b1, h1);
    run_big(h1, 256, 0, w2h, 256, 0, emb, 256, 0,
            TM + ND, 256, 256, 1, b2, nullptr, 0, nullptr, 0, F_BIAS | F_OUT16, false);

    // ---- encoder (only r=0 outputs needed downstream) ----
    k_ln_h<<<TM / 8, 256>>>(tr_emb, lnb);
    run_big(lnb, 256, 0, wqkvh + 256, 768, 0, kv, 512, 0,
            TM, 512, 256, 1, nullptr, nullptr, 0, nullptr, 0, F_OUT16, false);
    run_big(lnb, 2048, 0, wqkvh, 768, 0, q0, 256, 0,
            TT, 256, 256, 1, nullptr, nullptr, 0, nullptr, 0, F_OUT16, false, 64);
    k_attn<<<TT, 256>>>(q0, kv, o0);
    run_big(o0, 256, 0, woh, 256, 0, x1, 256, 0,
            TT, 256, 256, 1, nullptr, tr_emb, 2048, nullptr, 0, F_AUX, false, 64);
    k_ln_f<<<TT / 8, 256>>>(x1, ln2);
    run_big(ln2, 256, 0, ff1h, 1024, 0, ffh, 1024, 0,
            TT, 1024, 256, 1, nullptr, nullptr, 0, nullptr, 0, F_RELU | F_OUT16, false);
    run_big(ffh, 1024, 0, ff2h, 256, 0, ffout, 256, 0,
            TT, 256, 1024, 1, nullptr, nullptr, 0, nullptr, 0, 0, false, 64);
    k_feat0<<<ROWS1 / 4, 256>>>(tr_emb, x1, ffout, det_emb, feat0, x);

    // ---- adjacency ----
    k_posvm<<<64, 256>>>(tracks, dets, tmarks, dmarks, pos, vm);
    k_adj<<<dim3(NN1, BB), 256>>>(pos, vm, adj);
    k_adjd<<<dim3(NNd, BB), 128>>>(pos, vm, adjd);

    // ---- main GAT x2 ----
    for (int l = 0; l < 2; l++) {
        run_big(x, 256, 0, gatWh + (size_t)l * 65536, 256, 0, hh, 256, 0,
                ROWS1, 256, 256, 1, nullptr, nullptr, 0, nullptr, 0, F_OUT16, false);
        k_srcdst<<<ROWS1 / 8, 256>>>(hh, gata + (size_t)l * 512, src, dstT, NN1);
        k_rowstat<<<dim3(NN1, BB), 128>>>(src, dstT, adj, stat, anum, NN1);
        agg_fused<false><<<dim3(1, NN1 / 128, BB * HH), 256>>>(anum, stat, hh, feat0, x, NN1);
    }

    // ---- main scores (dual xq/xk; asso fused into epilogue) ----
    run_big(x, 256, 0, clsWqh, 256, 0, xq, 256, 0,
            ROWS1, 256, 256, 2, nullptr, nullptr, 0, nullptr, 0, F_OUT16, false, 128,
            clsWkh, xk, 1);
    run_big(xq, 256, (long long)NN1 * 256, xk, 256, (long long)NN1 * 256,
            out_scores, NN1, (long long)NN1 * NN1,
            NN1, NN1, 256, BB, nullptr, nullptr, 0,
            adj, (long long)NN1 * NN1, F_SIG | F_ASSO, true, 128,
            nullptr, nullptr, 0, out_asso);

    // ---- detection GAT x2 (aux = fp16 det_emb directly) ----
    for (int l = 0; l < 2; l++) {
        const __half* xin = (l == 0) ? det_emb : x;
        run_big(xin, 256, 0, dgatWh + (size_t)l * 65536, 256, 0, hh, 256, 0,
                ND, 256, 256, 1, nullptr, nullptr, 0, nullptr, 0, F_OUT16, false, 64);
        k_srcdst<<<ND / 8, 256>>>(hh, dgata + (size_t)l * 512, src, dstT, NNd);
        k_rowstat<<<dim3(NNd, BB), 128>>>(src, dstT, adjd, stat, anum, NNd);
        agg_fused<true><<<dim3(1, NNd / 128, BB * HH), 256>>>(anum, stat, hh, det_emb, x, NNd);
    }

    // ---- detection scores (dual xq/xk) ----
    run_big(x, 256, 0, clsWqh + 65536, 256, 0, xq, 256, 0,
            ND, 256, 256, 2, nullptr, nullptr, 0, nullptr, 0, F_OUT16, false, 128,
            clsWkh + 65536, xk, 1);
    run_big(xq, 256, (long long)NNd * 256, xk, 256, (long long)NNd * 256,
            out_det, NNd, (long long)NNd * NNd,
            NNd, NNd, 256, BB, nullptr, nullptr, 0,
            adjd, (long long)NNd * NNd, F_SIG | F_DIAG, true);
}

// round 17
// speedup vs baseline: 1.1009x; 1.0366x over previous
#include <cuda_runtime.h>
#include <cuda_fp16.h>
#include <math.h>
#include <stdint.h>

// ---------------------------------------------------------------------------
// Problem dims
// ---------------------------------------------------------------------------
#define BB 16
#define MM 512
#define NNd 512
#define RR 8
#define DD 256
#define HH 4
#define NN1 1024
#define TM  (BB*MM*RR)    // 65536
#define TT  (BB*MM)       // 8192
#define ND  (BB*NNd)      // 8192
#define ROWS1 (BB*NN1)    // 16384

#define F_BIAS 1
#define F_RELU 2
#define F_AUX  4
#define F_SIG  8
#define F_DIAG 16
#define F_OUT16 32
#define F_ASSO 64

// ---------------------------------------------------------------------------
// Scratch (main chain)
// ---------------------------------------------------------------------------
__device__ __half g_h1[(TM+ND)*DD];
__device__ __half g_emb[(TM+ND)*DD];
__device__ __half g_lnb[TM*DD];
__device__ __half g_kv[TM*512];
__device__ __half g_q0[TT*DD];
__device__ __half g_o0[TT*DD];
__device__ float  g_x1[TT*DD];
__device__ __half g_ln2[TT*DD];
__device__ __half g_ffh[TT*1024];
__device__ float  g_ffout[TT*DD];
__device__ float  g_feat0[ROWS1*DD];
__device__ __half g_x[ROWS1*DD];
__device__ __half g_hh[ROWS1*DD];
__device__ float g_src[ROWS1*HH];
__device__ float g_dstT[BB*HH*NN1];
__device__ float2 g_stat[BB*HH*NN1];
__device__ __half g_anum[(size_t)BB*HH*NN1*NN1];
__device__ unsigned char g_adj[(size_t)BB*NN1*NN1];
__device__ float g_pos[BB*NN1*2];
__device__ unsigned char g_vm[BB*NN1];
__device__ __half g_xq[ROWS1*DD];
__device__ __half g_xk[ROWS1*DD];
// ---- det branch private scratch (runs on second stream) ----
__device__ unsigned char g_adjd[(size_t)BB*NNd*NNd];
__device__ float g_pos_d[BB*NN1*2];
__device__ unsigned char g_vm_d[BB*NN1];
__device__ __half g_hh_d[ND*DD];
__device__ float g_src_d[ND*HH];
__device__ float g_dstT_d[BB*HH*NNd];
__device__ float2 g_stat_d[BB*HH*NNd];
__device__ __half g_anum_d[(size_t)BB*HH*NNd*NNd];
__device__ __half g_x_d[ND*DD];
__device__ __half g_xq_d[ND*DD];
__device__ __half g_xk_d[ND*DD];
// fp16 weights
__device__ __half g_w2h[256*256];
__device__ __half g_wqkvh[256*768];
__device__ __half g_woh[256*256];
__device__ __half g_ff1h[256*1024];
__device__ __half g_ff2h[1024*256];
__device__ __half g_gatWh[2*256*256];
__device__ __half g_dgatWh[2*256*256];
__device__ __half g_clsWqh[2*256*256];
__device__ __half g_clsWkh[2*256*256];

// ---------------------------------------------------------------------------
// helpers
// ---------------------------------------------------------------------------
__device__ __forceinline__ uint32_t pk(float lo, float hi) {
    __half2 v = __floats2half2_rn(lo, hi);
    return *reinterpret_cast<uint32_t*>(&v);
}
__device__ __forceinline__ void mma_f16(float* c, const uint32_t* a, const uint32_t* b) {
    asm volatile(
        "mma.sync.aligned.m16n8k16.row.col.f32.f16.f16.f32 "
        "{%0,%1,%2,%3}, {%4,%5,%6,%7}, {%8,%9}, {%0,%1,%2,%3};\n"
        : "+f"(c[0]), "+f"(c[1]), "+f"(c[2]), "+f"(c[3])
        : "r"(a[0]), "r"(a[1]), "r"(a[2]), "r"(a[3]), "r"(b[0]), "r"(b[1]));
}
__device__ __forceinline__ void ldm_x4(uint32_t* r, uint32_t addr) {
    asm volatile("ldmatrix.sync.aligned.m8n8.x4.shared.b16 {%0,%1,%2,%3}, [%4];"
        : "=r"(r[0]), "=r"(r[1]), "=r"(r[2]), "=r"(r[3]) : "r"(addr));
}
__device__ __forceinline__ void ldm_x4_t(uint32_t* r, uint32_t addr) {
    asm volatile("ldmatrix.sync.aligned.m8n8.x4.trans.shared.b16 {%0,%1,%2,%3}, [%4];"
        : "=r"(r[0]), "=r"(r[1]), "=r"(r[2]), "=r"(r[3]) : "r"(addr));
}
__device__ __forceinline__ uint32_t cvs(const void* p) {
    return (uint32_t)__cvta_generic_to_shared(p);
}
__device__ __forceinline__ void cp16(uint32_t dst, const void* src) {
    asm volatile("cp.async.cg.shared.global [%0], [%1], 16;" :: "r"(dst), "l"(src));
}
__device__ __forceinline__ void cp8(uint32_t dst, const void* src) {
    asm volatile("cp.async.ca.shared.global [%0], [%1], 8;" :: "r"(dst), "l"(src));
}
__device__ __forceinline__ void cp4(uint32_t dst, const void* src) {
    asm volatile("cp.async.ca.shared.global [%0], [%1], 4;" :: "r"(dst), "l"(src));
}
#define CP_COMMIT() asm volatile("cp.async.commit_group;")
#define CP_WAIT1()  asm volatile("cp.async.wait_group 1;")
#define CP_WAIT0()  asm volatile("cp.async.wait_group 0;")

// combined weight fp32->fp16
struct WPack {
    const float* s[9];
    __half* d[9];
    int n[9];
};
__global__ void k_f2h_all(WPack p)
{
    int g = blockIdx.y;
    int i = (blockIdx.x * 256 + threadIdx.x) * 4;
    if (i >= p.n[g]) return;
    float4 v = *(const float4*)(p.s[g] + i);
    uint2 o;
    o.x = pk(v.x, v.y);
    o.y = pk(v.z, v.w);
    *(uint2*)(p.d[g] + i) = o;
}

// ---------------------------------------------------------------------------
// BIG GEMM (fp16, cp.async 3-stage, BK=32): CTA MTx128, 256 thr.
// ---------------------------------------------------------------------------
#define BREG    9216
#define BSTG    12288u
#define BCHK    6144u
template<int MT, bool TRANSB, int FLAGS>
__global__ __launch_bounds__(256, 2)
void tgemm_big(const __half* __restrict__ A, int lda, long long sA,
               const __half* __restrict__ B, int ldb, long long sB,
               void* __restrict__ Cv, int ldc, long long sC,
               int K,
               const float* __restrict__ bias,
               const __half* __restrict__ aux, int auxld,
               const unsigned char* __restrict__ adjp, long long sAdj,
               const __half* __restrict__ B2, void* __restrict__ C2v, int dual,
               float* __restrict__ asso)
{
    extern __shared__ uint32_t dsm[];
    const uint32_t A_CHK = MT * 48u;
    const uint32_t A_STG = 2u * A_CHK;
    const int FM = MT / 32;

    int bz = blockIdx.z;
    int bzA = bz;
    if (dual && bz) { B = B2; Cv = C2v; bz = 0; }
    A += (long long)bz * sA;
    B += (long long)bz * sB;
    size_t coff = (size_t)((long long)bz * sC);
    if (FLAGS & F_SIG) adjp += (long long)bz * sAdj;

    int m0 = blockIdx.y * MT, n0 = blockIdx.x * 128;

    int tid = threadIdx.x;

    const __half* gA;
    uint32_t aD;
    if (MT == 128) {
        int arow = tid >> 1, ah = tid & 1;
        gA = A + (size_t)(m0 + arow) * lda + ah * 8;
        aD = cvs(dsm) + (arow * 12 + ah * 4) * 4;
    } else {
        int arow = tid >> 2, q = tid & 3;
        int cc = q >> 1, h = q & 1;
        gA = A + (size_t)(m0 + arow) * lda + q * 8;
        aD = cvs(dsm) + cc * A_CHK + (arow * 12 + h * 4) * 4;
    }

    const __half* gB;
    int kp = tid >> 5, nq = tid & 31;
    int brow = tid >> 1, bh = tid & 1;
    if (!TRANSB) gB = B + (size_t)(2 * kp) * ldb + n0 + nq * 4;
    else         gB = B + (size_t)(n0 + brow) * ldb + bh * 8;

    uint32_t bD1, bD2;
    if (!TRANSB) {
        int w0 = (2 * kp) * 68 + nq * 2;
        bD1 = cvs(&dsm[BREG + w0]);
        bD2 = cvs(&dsm[BREG + w0 + 68]);
    } else {
        bD1 = cvs(&dsm[BREG + brow * 12 + bh * 4]);
        bD2 = 0;
    }

    int w = tid >> 5, l = tid & 31;
    int mbase = (w >> 2) * (MT / 2), nbase = (w & 3) * 32;
    int grp = l >> 2, tig = l & 3;

    int lrowA = ((l >> 3) & 1) * 8 + (l & 7);
    int khalf = l >> 4;
    uint32_t aBase[FM];
    #pragma unroll
    for (int fm = 0; fm < FM; fm++)
        aBase[fm] = cvs(&dsm[(mbase + fm * 16 + lrowA) * 12 + khalf * 4]);
    uint32_t bBase[2];
    if (!TRANSB) {
        int krow = ((l >> 4) & 1) * 8 + (l & 7);
        int nblk = ((l >> 3) & 1) * 8;
        #pragma unroll
        for (int fp = 0; fp < 2; fp++)
            bBase[fp] = cvs(&dsm[BREG + krow * 68 + ((nbase + fp * 16 + nblk) >> 1)]);
    } else {
        #pragma unroll
        for (int fp = 0; fp < 2; fp++)
            bBase[fp] = cvs(&dsm[BREG + (nbase + fp * 16 + lrowA) * 12 + khalf * 4]);
    }

    float acc[FM][4][4];
    #pragma unroll
    for (int i = 0; i < FM; i++)
        #pragma unroll
        for (int j = 0; j < 4; j++)
            #pragma unroll
            for (int q = 0; q < 4; q++) acc[i][j][q] = 0.f;

    int nk = K >> 5;

    #pragma unroll
    for (int p = 0; p < 2; p++) {
        if (p < nk) {
            if (MT == 128) {
                #pragma unroll
                for (int c = 0; c < 2; c++)
                    cp16(aD + p * A_STG + c * A_CHK, gA + p * 32 + c * 16);
            } else {
                cp16(aD + p * A_STG, gA + p * 32);
            }
            #pragma unroll
            for (int c = 0; c < 2; c++) {
                uint32_t off = p * BSTG + c * BCHK;
                int k0 = p * 32 + c * 16;
                if (!TRANSB) {
                    cp8(bD1 + off, gB + (size_t)k0 * ldb);
                    cp8(bD2 + off, gB + (size_t)(k0 + 1) * ldb);
                } else {
                    cp16(bD1 + off, gB + k0);
                }
            }
            CP_COMMIT();
        }
    }

    int s = 0;
    for (int i = 0; i < nk; i++) {
        if (i + 1 < nk) CP_WAIT1(); else CP_WAIT0();
        __syncthreads();
        #pragma unroll
        for (int c = 0; c < 2; c++) {
            uint32_t aoff = (uint32_t)s * A_STG + c * A_CHK;
            uint32_t boff = (uint32_t)s * BSTG + c * BCHK;
            uint32_t af[FM][4];
            #pragma unroll
            for (int fm = 0; fm < FM; fm++) ldm_x4(af[fm], aBase[fm] + aoff);
            uint32_t bfr[4][2];
            #pragma unroll
            for (int fp = 0; fp < 2; fp++) {
                uint32_t t4[4];
                if (!TRANSB) ldm_x4_t(t4, bBase[fp] + boff);
                else         ldm_x4(t4, bBase[fp] + boff);
                bfr[fp * 2][0] = t4[0]; bfr[fp * 2 + 1][0] = t4[1];
                bfr[fp * 2][1] = t4[2]; bfr[fp * 2 + 1][1] = t4[3];
            }
            #pragma unroll
            for (int fm = 0; fm < FM; fm++)
                #pragma unroll
                for (int fn = 0; fn < 4; fn++)
                    mma_f16(acc[fm][fn], af[fm], bfr[fn]);
        }
        if (i + 2 < nk) {
            int st = s >= 1 ? s - 1 : s + 2;
            int kb = (i + 2) * 32;
            if (MT == 128) {
                #pragma unroll
                for (int c = 0; c < 2; c++)
                    cp16(aD + (uint32_t)st * A_STG + c * A_CHK, gA + kb + c * 16);
            } else {
                cp16(aD + (uint32_t)st * A_STG, gA + kb);
            }
            #pragma unroll
            for (int c = 0; c < 2; c++) {
                uint32_t off = (uint32_t)st * BSTG + c * BCHK;
                int k0 = kb + c * 16;
                if (!TRANSB) {
                    cp8(bD1 + off, gB + (size_t)k0 * ldb);
                    cp8(bD2 + off, gB + (size_t)(k0 + 1) * ldb);
                } else {
                    cp16(bD1 + off, gB + k0);
                }
            }
            CP_COMMIT();
        }
        s = (s + 1) == 3 ? 0 : s + 1;
    }

    #pragma unroll
    for (int fm = 0; fm < FM; fm++) {
        int row0 = m0 + mbase + fm * 16 + grp;
        #pragma unroll
        for (int fn = 0; fn < 4; fn++) {
            int col = n0 + nbase + fn * 8 + 2 * tig;
            float v0 = acc[fm][fn][0], v1 = acc[fm][fn][1];
            float v2 = acc[fm][fn][2], v3 = acc[fm][fn][3];
            if (FLAGS & F_BIAS) {
                float bb0 = bias[col], bb1 = bias[col + 1];
                v0 += bb0; v1 += bb1; v2 += bb0; v3 += bb1;
            }
            if (FLAGS & F_RELU) {
                v0 = fmaxf(v0, 0.f); v1 = fmaxf(v1, 0.f);
                v2 = fmaxf(v2, 0.f); v3 = fmaxf(v3, 0.f);
            }
            if (FLAGS & F_AUX) {
                float2 a0 = __half22float2(*(const __half2*)(aux + (size_t)row0 * auxld + col));
                float2 a8 = __half22float2(*(const __half2*)(aux + (size_t)(row0 + 8) * auxld + col));
                v0 += a0.x; v1 += a0.y; v2 += a8.x; v3 += a8.y;
            }
            if (FLAGS & F_SIG) {
                const unsigned char* q0p = adjp + (size_t)row0 * ldc + col;
                const unsigned char* q8p = adjp + (size_t)(row0 + 8) * ldc + col;
                v0 = q0p[0] ? 1.f / (1.f + __expf(-v0 * 0.0625f)) : 0.f;
                v1 = q0p[1] ? 1.f / (1.f + __expf(-v1 * 0.0625f)) : 0.f;
                v2 = q8p[0] ? 1.f / (1.f + __expf(-v2 * 0.0625f)) : 0.f;
                v3 = q8p[1] ? 1.f / (1.f + __expf(-v3 * 0.0625f)) : 0.f;
                if (FLAGS & F_DIAG) {
                    if (row0 == col) v0 = 0.f;
                    if (row0 == col + 1) v1 = 0.f;
                    if (row0 + 8 == col) v2 = 0.f;
                    if (row0 + 8 == col + 1) v3 = 0.f;
                }
            }
            if (FLAGS & F_OUT16) {
                __half* Ch = (__half*)Cv + coff;
                *(uint32_t*)&Ch[(size_t)row0 * ldc + col] = pk(v0, v1);
                *(uint32_t*)&Ch[(size_t)(row0 + 8) * ldc + col] = pk(v2, v3);
            } else {
                float* C = (float*)Cv + coff;
                *(float2*)&C[(size_t)row0 * ldc + col] = make_float2(v0, v1);
                *(float2*)&C[(size_t)(row0 + 8) * ldc + col] = make_float2(v2, v3);
            }
            if (FLAGS & F_ASSO) {
                if (col >= 512) {
                    int jc = col - 512;
                    if (row0 < 512)
                        *(float2*)&asso[((size_t)bzA * 512 + row0) * 512 + jc] = make_float2(v0, v1);
                    if (row0 + 8 < 512)
                        *(float2*)&asso[((size_t)bzA * 512 + row0 + 8) * 512 + jc] = make_float2(v2, v3);
                }
            }
        }
    }
}

// ---------------------------------------------------------------------------
// GAT aggregation (fp16 GEMM, cp.async 3-stage): CTA 128x64, warp 32x32.
// ---------------------------------------------------------------------------
template<bool AUX16>
__global__ __launch_bounds__(256)
void agg_fused(const __half* __restrict__ anum, const float2* __restrict__ stat,
               const __half* __restrict__ hmat,
               const void* __restrict__ auxv, __half* __restrict__ xout, int NN)
{
    int z = blockIdx.z;
    int b = z >> 2, h = z & 3;
    const __half* B = hmat + (size_t)b * NN * 256 + h * 64;
    __half* C = xout + (size_t)b * NN * 256 + h * 64;
    size_t auxbase = (size_t)b * NN * 256 + h * 64;
    const float* auxf = (const float*)auxv + auxbase;
    const __half* auxh = (const __half*)auxv + auxbase;
    const float2* statz = stat + (size_t)z * NN;

    int m0 = blockIdx.y * 128;
    __shared__ uint32_t As[3][1536];
    __shared__ uint32_t Bs[3][576];
    int tid = threadIdx.x;

    int arow = tid >> 1, ahalf = tid & 1;
    const __half* gA = anum + ((size_t)z * NN + m0 + arow) * NN + ahalf * 8;

    int kp = tid >> 5, nq = tid & 31;
    const __half* gB = B + (size_t)(2 * kp) * 256 + 2 * nq;

    uint32_t aD = cvs(&As[0][arow * 12 + ahalf * 4]);
    uint32_t bD1 = cvs(&Bs[0][(2 * kp) * 36 + nq]);
    uint32_t bD2 = cvs(&Bs[0][(2 * kp + 1) * 36 + nq]);

    int w = tid >> 5, l = tid & 31;
    int wm = w >> 1, wn = w & 1;
    int mrow = wm * 32, ncol = wn * 32;
    int grp = l >> 2, tig = l & 3;

    int lrowA = ((l >> 3) & 1) * 8 + (l & 7);
    int khalf = l >> 4;
    uint32_t aBase[2];
    #pragma unroll
    for (int fm = 0; fm < 2; fm++)
        aBase[fm] = cvs(&As[0][(mrow + fm * 16 + lrowA) * 12 + khalf * 4]);
    int krow = ((l >> 4) & 1) * 8 + (l & 7);
    int nblk = ((l >> 3) & 1) * 8;
    uint32_t bBase[2];
    #pragma unroll
    for (int fp = 0; fp < 2; fp++)
        bBase[fp] = cvs(&Bs[0][krow * 36 + ((ncol + fp * 16 + nblk) >> 1)]);

    float acc[2][4][4];
    #pragma unroll
    for (int i = 0; i < 2; i++)
        #pragma unroll
        for (int j = 0; j < 4; j++)
            #pragma unroll
            for (int q = 0; q < 4; q++) acc[i][j][q] = 0.f;

    int nk = NN >> 4;

    {
        cp16(aD, gA);
        cp4(bD1, gB);
        cp4(bD2, gB + 256);
        CP_COMMIT();
        if (nk > 1) {
            cp16(aD + 6144, gA + 16);
            cp4(bD1 + 2304, gB + 16 * 256);
            cp4(bD2 + 2304, gB + 17 * 256);
            CP_COMMIT();
        }
    }

    int s = 0;
    for (int i = 0; i < nk; i++) {
        if (i + 1 < nk) CP_WAIT1(); else CP_WAIT0();
        __syncthreads();
        uint32_t sa = (uint32_t)(s * 6144);
        uint32_t sbo = (uint32_t)(s * 2304);
        uint32_t af[2][4];
        #pragma unroll
        for (int fm = 0; fm < 2; fm++) ldm_x4(af[fm], aBase[fm] + sa);
        uint32_t bfr[4][2];
        #pragma unroll
        for (int fp = 0; fp < 2; fp++) {
            uint32_t t4[4];
            ldm_x4_t(t4, bBase[fp] + sbo);
            bfr[fp * 2][0] = t4[0]; bfr[fp * 2 + 1][0] = t4[1];
            bfr[fp * 2][1] = t4[2]; bfr[fp * 2 + 1][1] = t4[3];
        }
        #pragma unroll
        for (int fm = 0; fm < 2; fm++)
            #pragma unroll
            for (int fn = 0; fn < 4; fn++)
                mma_f16(acc[fm][fn], af[fm], bfr[fn]);
        if (i + 2 < nk) {
            int st = s >= 1 ? s - 1 : s + 2;
            int k0 = (i + 2) * 16;
            cp16(aD + st * 6144, gA + k0);
            cp4(bD1 + st * 2304, gB + (size_t)k0 * 256);
            cp4(bD2 + st * 2304, gB + (size_t)(k0 + 1) * 256);
            CP_COMMIT();
        }
        s = (s + 1) == 3 ? 0 : s + 1;
    }

    #pragma unroll
    for (int fm = 0; fm < 2; fm++) {
        int row = m0 + mrow + fm * 16 + grp;
        float inv0 = statz[row].y;
        float inv8 = statz[row + 8].y;
        #pragma unroll
        for (int fn = 0; fn < 4; fn++) {
            int col = ncol + fn * 8 + 2 * tig;
            float v0 = acc[fm][fn][0] * inv0, v1 = acc[fm][fn][1] * inv0;
            float v2 = acc[fm][fn][2] * inv8, v3 = acc[fm][fn][3] * inv8;
            v0 = (v0 > 0.f) ? v0 : expm1f(v0);
            v1 = (v1 > 0.f) ? v1 : expm1f(v1);
            v2 = (v2 > 0.f) ? v2 : expm1f(v2);
            v3 = (v3 > 0.f) ? v3 : expm1f(v3);
            float2 x0, x1;
            if (AUX16) {
                x0 = __half22float2(*(const __half2*)&auxh[(size_t)row * 256 + col]);
                x1 = __half22float2(*(const __half2*)&auxh[(size_t)(row + 8) * 256 + col]);
            } else {
                x0 = *(const float2*)&auxf[(size_t)row * 256 + col];
                x1 = *(const float2*)&auxf[(size_t)(row + 8) * 256 + col];
            }
            *(uint32_t*)&C[(size_t)row * 256 + col] =
                pk(0.5f * v0 + 0.5f * x0.x, 0.5f * v1 + 0.5f * x0.y);
            *(uint32_t*)&C[(size_t)(row + 8) * 256 + col] =
                pk(0.5f * v2 + 0.5f * x1.x, 0.5f * v3 + 0.5f * x1.y);
        }
    }
}

// ---------------------------------------------------------------------------
// Small kernels
// ---------------------------------------------------------------------------
__global__ void k_feat1(const float* __restrict__ tr, const float* __restrict__ de,
                        const float* __restrict__ W1, const float* __restrict__ b1,
                        __half* __restrict__ out)
{
    int tid = threadIdx.x;
    size_t row = (size_t)blockIdx.x * 4 + (tid >> 6);
    int c4 = (tid & 63) * 4;
    const float* xr = (row < TM) ? (tr + row * 4) : (de + (row - TM) * 4);
    const float4 x4 = *(const float4*)xr;
    float4 v = *(const float4*)(b1 + c4);
    float4 w0 = *(const float4*)(W1 + c4);
    float4 w1 = *(const float4*)(W1 + 256 + c4);
    float4 w2 = *(const float4*)(W1 + 512 + c4);
    float4 w3 = *(const float4*)(W1 + 768 + c4);
    v.x += x4.x * w0.x + x4.y * w1.x + x4.z * w2.x + x4.w * w3.x;
    v.y += x4.x * w0.y + x4.y * w1.y + x4.z * w2.y + x4.w * w3.y;
    v.z += x4.x * w0.z + x4.y * w1.z + x4.z * w2.z + x4.w * w3.z;
    v.w += x4.x * w0.w + x4.y * w1.w + x4.z * w2.w + x4.w * w3.w;
    v.x = (v.x > 0.f) ? v.x : (__expf(v.x) - 1.f);
    v.y = (v.y > 0.f) ? v.y : (__expf(v.y) - 1.f);
    v.z = (v.z > 0.f) ? v.z : (__expf(v.z) - 1.f);
    v.w = (v.w > 0.f) ? v.w : (__expf(v.w) - 1.f);
    uint2 p;
    p.x = pk(v.x, v.y);
    p.y = pk(v.z, v.w);
    *(uint2*)(out + row * 256 + c4) = p;
}

__global__ void k_ln_h(const __half* __restrict__ in, __half* __restrict__ out)
{
    int w = threadIdx.x >> 5, lane = threadIdx.x & 31;
    size_t row = (size_t)blockIdx.x * 8 + w;
    const uint4* ip = (const uint4*)(in + row * 256);
    uint4 u = ip[lane];
    float2 f0 = __half22float2(*(__half2*)&u.x);
    float2 f1 = __half22float2(*(__half2*)&u.y);
    float2 f2 = __half22float2(*(__half2*)&u.z);
    float2 f3 = __half22float2(*(__half2*)&u.w);
    float a = f0.x + f0.y + f1.x + f1.y + f2.x + f2.y + f3.x + f3.y;
    float b = f0.x*f0.x + f0.y*f0.y + f1.x*f1.x + f1.y*f1.y
            + f2.x*f2.x + f2.y*f2.y + f3.x*f3.x + f3.y*f3.y;
    #pragma unroll
    for (int o = 16; o; o >>= 1) {
        a += __shfl_xor_sync(0xffffffff, a, o);
        b += __shfl_xor_sync(0xffffffff, b, o);
    }
    float mean = a * (1.f / 256.f);
    float var = b * (1.f / 256.f) - mean * mean;
    float rstd = rsqrtf(var + 1e-5f);
    uint4 r;
    r.x = pk((f0.x - mean) * rstd, (f0.y - mean) * rstd);
    r.y = pk((f1.x - mean) * rstd, (f1.y - mean) * rstd);
    r.z = pk((f2.x - mean) * rstd, (f2.y - mean) * rstd);
    r.w = pk((f3.x - mean) * rstd, (f3.y - mean) * rstd);
    ((uint4*)(out + row * 256))[lane] = r;
}

__global__ void k_ln_f(const float* __restrict__ in, __half* __restrict__ out)
{
    int w = threadIdx.x >> 5, lane = threadIdx.x & 31;
    size_t row = (size_t)blockIdx.x * 8 + w;
    const float4* ip = (const float4*)(in + row * 256);
    float4 v0 = ip[lane], v1 = ip[lane + 32];
    float a = v0.x + v0.y + v0.z + v0.w + v1.x + v1.y + v1.z + v1.w;
    float b = v0.x*v0.x + v0.y*v0.y + v0.z*v0.z + v0.w*v0.w
            + v1.x*v1.x + v1.y*v1.y + v1.z*v1.z + v1.w*v1.w;
    #pragma unroll
    for (int o = 16; o; o >>= 1) {
        a += __shfl_xor_sync(0xffffffff, a, o);
        b += __shfl_xor_sync(0xffffffff, b, o);
    }
    float mean = a * (1.f / 256.f);
    float var = b * (1.f / 256.f) - mean * mean;
    float rstd = rsqrtf(var + 1e-5f);
    uint2 p0, p1;
    p0.x = pk((v0.x - mean) * rstd, (v0.y - mean) * rstd);
    p0.y = pk((v0.z - mean) * rstd, (v0.w - mean) * rstd);
    p1.x = pk((v1.x - mean) * rstd, (v1.y - mean) * rstd);
    p1.y = pk((v1.z - mean) * rstd, (v1.w - mean) * rstd);
    *(uint2*)(out + row * 256 + lane * 4) = p0;
    *(uint2*)(out + row * 256 + 128 + lane * 4) = p1;
}

__global__ void k_attn(const __half* __restrict__ q0, const __half* __restrict__ kv,
                       __half* __restrict__ o0)
{
    size_t t = blockIdx.x;
    int d = threadIdx.x;
    int w = d >> 5, lane = d & 31, h = d >> 6;
    __shared__ float red[8][8];
    const __half* kvb = kv + t * 8 * 512;
    float qd = __half2float(q0[t * 256 + d]);
    #pragma unroll
    for (int s = 0; s < 8; s++) {
        float v = qd * __half2float(kvb[s * 512 + d]);
        #pragma unroll
        for (int o = 16; o; o >>= 1) v += __shfl_xor_sync(0xffffffff, v, o);
        if (lane == 0) red[w][s] = v;
    }
    __syncthreads();
    float lg[8];
    float m = -1e30f;
    #pragma unroll
    for (int s = 0; s < 8; s++) {
        lg[s] = (red[2 * h][s] + red[2 * h + 1][s]) * 0.125f;
        m = fmaxf(m, lg[s]);
    }
    float sum = 0.f;
    #pragma unroll
    for (int s = 0; s < 8; s++) { lg[s] = __expf(lg[s] - m); sum += lg[s]; }
    float inv = 1.f / sum;
    float o = 0.f;
    #pragma unroll
    for (int s = 0; s < 8; s++) o += lg[s] * inv * __half2float(kvb[s * 512 + 256 + d]);
    o0[t * 256 + d] = __float2half(o);
}

__global__ void k_feat0(const __half* __restrict__ tr_emb, const float* __restrict__ x1,
                        const float* __restrict__ ffout, const __half* __restrict__ det_emb,
                        float* __restrict__ feat0, __half* __restrict__ x)
{
    int tid = threadIdx.x;
    size_t row = (size_t)blockIdx.x * 4 + (tid >> 6);
    int c4 = (tid & 63) * 4;
    int i = (int)(row & 1023);
    int b = (int)(row >> 10);
    float4 v;
    if (i < 512) {
        size_t t = (size_t)b * 512 + i;
        uint2 te = *(const uint2*)(tr_emb + t * 2048 + c4);
        float2 e01 = __half22float2(*(__half2*)&te.x);
        float2 e23 = __half22float2(*(__half2*)&te.y);
        float4 a = *(const float4*)(x1 + t * 256 + c4);
        float4 f = *(const float4*)(ffout + t * 256 + c4);
        v.x = e01.x + 0.9f * (a.x + f.x);
        v.y = e01.y + 0.9f * (a.y + f.y);
        v.z = e23.x + 0.9f * (a.z + f.z);
        v.w = e23.y + 0.9f * (a.w + f.w);
    } else {
        size_t t = (size_t)b * 512 + (i - 512);
        uint2 de = *(const uint2*)(det_emb + t * 256 + c4);
        float2 e01 = __half22float2(*(__half2*)&de.x);
        float2 e23 = __half22float2(*(__half2*)&de.y);
        v = make_float4(e01.x, e01.y, e23.x, e23.y);
    }
    *(float4*)(feat0 + row * 256 + c4) = v;
    uint2 p;
    p.x = pk(v.x, v.y);
    p.y = pk(v.z, v.w);
    *(uint2*)(x + row * 256 + c4) = p;
}

__global__ void k_posvm(const float* __restrict__ tracks, const float* __restrict__ dets,
                        const int* __restrict__ tmarks, const int* __restrict__ dmarks,
                        float* __restrict__ pos, unsigned char* __restrict__ vm)
{
    int idx = blockIdx.x * 256 + threadIdx.x;
    if (idx >= BB * NN1) return;
    int b = idx >> 10, i = idx & 1023;
    float x, y; unsigned char v;
    if (i < 512) {
        const float* p = tracks + ((size_t)(b * 512 + i)) * 8 * 4;
        x = p[0]; y = p[1];
        v = (i < tmarks[b]);
    } else {
        int n = i - 512;
        const float* p = dets + ((size_t)(b * 512 + n)) * 4;
        x = p[0]; y = p[1];
        v = (n < dmarks[b]);
    }
    pos[idx * 2] = x; pos[idx * 2 + 1] = y; vm[idx] = v;
}

__global__ void k_adj(const float* __restrict__ pos, const unsigned char* __restrict__ vm,
                      unsigned char* __restrict__ adj)
{
    int i = blockIdx.x, b = blockIdx.y;
    size_t base = (size_t)b * NN1;
    const float2* p2 = (const float2*)pos;
    float2 pi = p2[base + i];
    unsigned char vi = vm[base + i];
    int j0 = threadIdx.x * 4;
    uchar4 r;
    unsigned char* rp = &r.x;
    #pragma unroll
    for (int u = 0; u < 4; u++) {
        int j = j0 + u;
        float2 pj = p2[base + j];
        float dx = pi.x - pj.x, dy = pi.y - pj.y;
        rp[u] = (unsigned char)((dx * dx + dy * dy < 4.0f) && vi && vm[base + j]);
    }
    ((uchar4*)(adj + ((size_t)b * NN1 + i) * NN1))[threadIdx.x] = r;
}

__global__ void k_adjd(const float* __restrict__ pos, const unsigned char* __restrict__ vm,
                       unsigned char* __restrict__ adjd)
{
    int i = blockIdx.x, b = blockIdx.y;
    size_t base = (size_t)b * NN1 + 512;
    const float2* p2 = (const float2*)pos;
    float2 pi = p2[base + i];
    unsigned char vi = vm[base + i];
    int j0 = threadIdx.x * 4;
    uchar4 r;
    unsigned char* rp = &r.x;
    #pragma unroll
    for (int u = 0; u < 4; u++) {
        int j = j0 + u;
        float2 pj = p2[base + j];
        float dx = pi.x - pj.x, dy = pi.y - pj.y;
        rp[u] = (unsigned char)((dx * dx + dy * dy < 4.0f) && vi && vm[base + j]);
    }
    ((uchar4*)(adjd + ((size_t)b * NNd + i) * NNd))[threadIdx.x] = r;
}

// src/dst projections: warp per row, 8 rows/block.
__global__ void k_srcdst(const __half* __restrict__ Hm, const float* __restrict__ a0,
                         float* __restrict__ src, float* __restrict__ dstT, int NN)
{
    int w = threadIdx.x >> 5, lane = threadIdx.x & 31;
    size_t row = (size_t)blockIdx.x * 8 + w;
    uint4 u = ((const uint4*)(Hm + row * 256))[lane];
    float2 f0 = __half22float2(*(__half2*)&u.x);
    float2 f1 = __half22float2(*(__half2*)&u.y);
    float2 f2 = __half22float2(*(__half2*)&u.z);
    float2 f3 = __half22float2(*(__half2*)&u.w);
    const float4* s0p = (const float4*)(a0 + lane * 8);
    const float4* s1p = (const float4*)(a0 + 256 + lane * 8);
    float4 sa = s0p[0], sb = s0p[1];
    float4 ta = s1p[0], tb = s1p[1];
    float s = f0.x * sa.x + f0.y * sa.y + f1.x * sa.z + f1.y * sa.w
            + f2.x * sb.x + f2.y * sb.y + f3.x * sb.z + f3.y * sb.w;
    float t = f0.x * ta.x + f0.y * ta.y + f1.x * ta.z + f1.y * ta.w
            + f2.x * tb.x + f2.y * tb.y + f3.x * tb.z + f3.y * tb.w;
    #pragma unroll
    for (int o = 4; o; o >>= 1) {
        s += __shfl_xor_sync(0xffffffff, s, o);
        t += __shfl_xor_sync(0xffffffff, t, o);
    }
    if ((lane & 7) == 0) {
        int h = lane >> 3;
        int b = (int)(row / NN);
        int i = (int)(row - (size_t)b * NN);
        src[row * 4 + h] = s;
        dstT[((size_t)b * 4 + h) * NN + i] = t;
    }
}

__global__ void k_rowstat(const float* __restrict__ src, const float* __restrict__ dstT,
                          const unsigned char* __restrict__ adj, float2* __restrict__ stat,
                          __half* __restrict__ anum, int NN)
{
    int i = blockIdx.x, b = blockIdx.y;
    int h = threadIdx.x >> 5, lane = threadIdx.x & 31;
    int z = b * 4 + h;
    float s = src[((size_t)b * NN + i) * 4 + h];
    const uchar4* adjrow = (const uchar4*)(adj + ((size_t)b * NN + i) * NN);
    const float4* dsth = (const float4*)(dstT + ((size_t)z) * NN);
    __half* arow = anum + ((size_t)z * NN + i) * NN;
    int nq = NN >> 2;
    float mx = -1e30f;
    for (int jq = lane; jq < nq; jq += 32) {
        uchar4 a4 = adjrow[jq];
        float4 d4 = dsth[jq];
        float e0 = s + d4.x; e0 = e0 > 0.f ? e0 : 0.2f * e0; e0 = a4.x ? e0 : -1e9f;
        float e1 = s + d4.y; e1 = e1 > 0.f ? e1 : 0.2f * e1; e1 = a4.y ? e1 : -1e9f;
        float e2 = s + d4.z; e2 = e2 > 0.f ? e2 : 0.2f * e2; e2 = a4.z ? e2 : -1e9f;
        float e3 = s + d4.w; e3 = e3 > 0.f ? e3 : 0.2f * e3; e3 = a4.w ? e3 : -1e9f;
        mx = fmaxf(mx, fmaxf(fmaxf(e0, e1), fmaxf(e2, e3)));
    }
    #pragma unroll
    for (int o = 16; o; o >>= 1) mx = fmaxf(mx, __shfl_xor_sync(0xffffffff, mx, o));
    float sum = 0.f;
    for (int jq = lane; jq < nq; jq += 32) {
        uchar4 a4 = adjrow[jq];
        float4 d4 = dsth[jq];
        float e0 = s + d4.x; e0 = e0 > 0.f ? e0 : 0.2f * e0; e0 = a4.x ? e0 : -1e9f;
        float e1 = s + d4.y; e1 = e1 > 0.f ? e1 : 0.2f * e1; e1 = a4.y ? e1 : -1e9f;
        float e2 = s + d4.z; e2 = e2 > 0.f ? e2 : 0.2f * e2; e2 = a4.z ? e2 : -1e9f;
        float e3 = s + d4.w; e3 = e3 > 0.f ? e3 : 0.2f * e3; e3 = a4.w ? e3 : -1e9f;
        float n0 = __expf(e0 - mx), n1 = __expf(e1 - mx);
        float n2 = __expf(e2 - mx), n3 = __expf(e3 - mx);
        sum += n0 + n1 + n2 + n3;
        uint2 pkd;
        pkd.x = pk(n0, n1);
        pkd.y = pk(n2, n3);
        *(uint2*)(arow + jq * 4) = pkd;
    }
    #pragma unroll
    for (int o = 16; o; o >>= 1) sum += __shfl_xor_sync(0xffffffff, sum, o);
    if (lane == 0)
        stat[(size_t)z * NN + i] = make_float2(mx, 1.f / sum);
}

// ---------------------------------------------------------------------------
// Host side
// ---------------------------------------------------------------------------
#define TG_DSMEM 73728

static void run_big(const __half* A, int lda, long long sA,
                    const __half* B, int ldb, long long sB,
                    void* C, int ldc, long long sC,
                    int M, int N, int K, int batch,
                    const float* bias, const __half* aux, int auxld,
                    const unsigned char* adjp, long long sAdj,
                    int flags, bool transb, int mt = 128,
                    const __half* B2 = nullptr, void* C2 = nullptr, int dual = 0,
                    float* asso = nullptr, cudaStream_t st = 0)
{
    dim3 g(N / 128, M / mt, batch);
#define CALLBIG(MTV, T, F) do { \
        cudaFuncSetAttribute(tgemm_big<MTV, T, F>, cudaFuncAttributeMaxDynamicSharedMemorySize, TG_DSMEM); \
        tgemm_big<MTV, T, F><<<g, 256, TG_DSMEM, st>>>(A, lda, sA, B, ldb, sB, \
            C, ldc, sC, K, bias, aux, auxld, adjp, sAdj, B2, C2, dual, asso); \
    } while (0)
    if (mt == 64) {
        if (flags == F_OUT16)                 CALLBIG(64, false, F_OUT16);
        else if (flags == F_AUX)              CALLBIG(64, false, F_AUX);
        else                                  CALLBIG(64, false, 0);
    } else if (!transb) {
        if (flags == (F_BIAS | F_OUT16))      CALLBIG(128, false, F_BIAS | F_OUT16);
        else if (flags == F_OUT16)            CALLBIG(128, false, F_OUT16);
        else if (flags == F_AUX)              CALLBIG(128, false, F_AUX);
        else if (flags == (F_RELU | F_OUT16)) CALLBIG(128, false, F_RELU | F_OUT16);
        else                                  CALLBIG(128, false, 0);
    } else {
        if (flags == (F_SIG | F_ASSO))        CALLBIG(128, true, F_SIG | F_ASSO);
        else                                  CALLBIG(128, true, F_SIG | F_DIAG);
    }
#undef CALLBIG
}

#define SYM(p, s) cudaGetSymbolAddress((void**)&p, s)

extern "C" void kernel_launch(void* const* d_in, const int* in_sizes, int n_in,
                              void* d_out, int out_size)
{
    (void)in_sizes; (void)n_in; (void)out_size;
    const float* tracks = (const float*)d_in[0];
    const float* dets   = (const float*)d_in[1];
    const int* tmarks   = (const int*)d_in[2];
    const int* dmarks   = (const int*)d_in[3];
    const float* W1     = (const float*)d_in[4];
    const float* b1     = (const float*)d_in[5];
    const float* W2     = (const float*)d_in[6];
    const float* b2     = (const float*)d_in[7];
    const float* Wqkv   = (const float*)d_in[8];
    const float* Wo     = (const float*)d_in[9];
    const float* ff1    = (const float*)d_in[10];
    const float* ff2    = (const float*)d_in[11];
    const float* gatW   = (const float*)d_in[12];
    const float* gata   = (const float*)d_in[13];
    const float* dgatW  = (const float*)d_in[14];
    const float* dgata  = (const float*)d_in[15];
    const float* clsWq  = (const float*)d_in[16];
    const float* clsWk  = (const float*)d_in[17];

    float* out = (float*)d_out;
    float* out_scores = out;
    float* out_det    = out + (size_t)BB * NN1 * NN1;
    float* out_asso   = out_det + (size_t)BB * NNd * NNd;

    __half *h1, *emb, *lnb, *kv, *q0, *o0, *ln2, *ffh, *x, *hh, *xq, *xk, *anum;
    __half *hh_d, *x_d, *xq_d, *xk_d, *anum_d;
    __half *w2h, *wqkvh, *woh, *ff1h, *ff2h, *gatWh, *dgatWh, *clsWqh, *clsWkh;
    float *x1, *ffout, *feat0, *src, *dstT, *pos, *pos_d, *src_d, *dstT_d;
    float2 *stat, *stat_d;
    unsigned char *adj, *adjd, *vm, *vm_d;
    SYM(h1, g_h1);         SYM(emb, g_emb);       SYM(lnb, g_lnb);
    SYM(kv, g_kv);         SYM(q0, g_q0);         SYM(o0, g_o0);
    SYM(x1, g_x1);         SYM(ln2, g_ln2);       SYM(ffh, g_ffh);
    SYM(ffout, g_ffout);   SYM(feat0, g_feat0);
    SYM(x, g_x);           SYM(hh, g_hh);         SYM(src, g_src);
    SYM(dstT, g_dstT);     SYM(stat, g_stat);     SYM(anum, g_anum);
    SYM(adj, g_adj);       SYM(adjd, g_adjd);     SYM(pos, g_pos);
    SYM(vm, g_vm);         SYM(xq, g_xq);         SYM(xk, g_xk);
    SYM(pos_d, g_pos_d);   SYM(vm_d, g_vm_d);     SYM(hh_d, g_hh_d);
    SYM(src_d, g_src_d);   SYM(dstT_d, g_dstT_d); SYM(stat_d, g_stat_d);
    SYM(anum_d, g_anum_d); SYM(x_d, g_x_d);       SYM(xq_d, g_xq_d);
    SYM(xk_d, g_xk_d);
    SYM(w2h, g_w2h);       SYM(wqkvh, g_wqkvh);   SYM(woh, g_woh);
    SYM(ff1h, g_ff1h);     SYM(ff2h, g_ff2h);     SYM(gatWh, g_gatWh);
    SYM(dgatWh, g_dgatWh); SYM(clsWqh, g_clsWqh); SYM(clsWkh, g_clsWkh);

    __half* tr_emb = emb;
    __half* det_emb = emb + (size_t)TM * DD;

    // ---- streams / events for fork-join (created fresh per call) ----
    cudaStream_t s1;
    cudaStreamCreateWithFlags(&s1, cudaStreamNonBlocking);
    cudaEvent_t evRoot, evMLP, evDet;
    cudaEventCreateWithFlags(&evRoot, cudaEventDisableTiming);
    cudaEventCreateWithFlags(&evMLP, cudaEventDisableTiming);
    cudaEventCreateWithFlags(&evDet, cudaEventDisableTiming);

    // fork root
    cudaEventRecord(evRoot, 0);
    cudaStreamWaitEvent(s1, evRoot, 0);

    // s1: det adjacency (independent of everything but inputs)
    k_posvm<<<64, 256, 0, s1>>>(tracks, dets, tmarks, dmarks, pos_d, vm_d);
    k_adjd<<<dim3(NNd, BB), 128, 0, s1>>>(pos_d, vm_d, adjd);

    // ---- main stream: weights + feature MLP ----
    {
        WPack p;
        p.s[0] = W2;    p.d[0] = w2h;    p.n[0] = 65536;
        p.s[1] = Wqkv;  p.d[1] = wqkvh;  p.n[1] = 196608;
        p.s[2] = Wo;    p.d[2] = woh;    p.n[2] = 65536;
        p.s[3] = ff1;   p.d[3] = ff1h;   p.n[3] = 262144;
        p.s[4] = ff2;   p.d[4] = ff2h;   p.n[4] = 262144;
        p.s[5] = gatW;  p.d[5] = gatWh;  p.n[5] = 131072;
        p.s[6] = dgatW; p.d[6] = dgatWh; p.n[6] = 131072;
        p.s[7] = clsWq; p.d[7] = clsWqh; p.n[7] = 131072;
        p.s[8] = clsWk; p.d[8] = clsWkh; p.n[8] = 131072;
        k_f2h_all<<<dim3(256, 9), 256>>>(p);
    }
    k_feat1<<<(TM + ND) / 4, 256>>>(tracks, dets, W1, b1, h1);
    run_big(h1, 256, 0, w2h, 256, 0, emb, 256, 0,
            TM + ND, 256, 256, 1, b2, nullptr, 0, nullptr, 0, F_BIAS | F_OUT16, false);
    cudaEventRecord(evMLP, 0);
    cudaStreamWaitEvent(s1, evMLP, 0);

    // ---- s1: detection branch (needs det_emb + adjd + fp16 weights) ----
    for (int l = 0; l < 2; l++) {
        const __half* xin = (l == 0) ? det_emb : x_d;
        run_big(xin, 256, 0, dgatWh + (size_t)l * 65536, 256, 0, hh_d, 256, 0,
                ND, 256, 256, 1, nullptr, nullptr, 0, nullptr, 0, F_OUT16, false, 64,
                nullptr, nullptr, 0, nullptr, s1);
        k_srcdst<<<ND / 8, 256, 0, s1>>>(hh_d, dgata + (size_t)l * 512, src_d, dstT_d, NNd);
        k_rowstat<<<dim3(NNd, BB), 128, 0, s1>>>(src_d, dstT_d, adjd, stat_d, anum_d, NNd);
        agg_fused<true><<<dim3(1, NNd / 128, BB * HH), 256, 0, s1>>>(
            anum_d, stat_d, hh_d, det_emb, x_d, NNd);
    }
    run_big(x_d, 256, 0, clsWqh + 65536, 256, 0, xq_d, 256, 0,
            ND, 256, 256, 2, nullptr, nullptr, 0, nullptr, 0, F_OUT16, false, 128,
            clsWkh + 65536, xk_d, 1, nullptr, s1);
    run_big(xq_d, 256, (long long)NNd * 256, xk_d, 256, (long long)NNd * 256,
            out_det, NNd, (long long)NNd * NNd,
            NNd, NNd, 256, BB, nullptr, nullptr, 0,
            adjd, (long long)NNd * NNd, F_SIG | F_DIAG, true, 128,
            nullptr, nullptr, 0, nullptr, s1);
    cudaEventRecord(evDet, s1);

    // ---- main stream: adjacency + encoder ----
    k_posvm<<<64, 256>>>(tracks, dets, tmarks, dmarks, pos, vm);
    k_adj<<<dim3(NN1, BB), 256>>>(pos, vm, adj);

    k_ln_h<<<TM / 8, 256>>>(tr_emb, lnb);
    run_big(lnb, 256, 0, wqkvh + 256, 768, 0, kv, 512, 0,
            TM, 512, 256, 1, nullptr, nullptr, 0, nullptr, 0, F_OUT16, false);
    run_big(lnb, 2048, 0, wqkvh, 768, 0, q0, 256, 0,
            TT, 256, 256, 1, nullptr, nullptr, 0, nullptr, 0, F_OUT16, false, 64);
    k_attn<<<TT, 256>>>(q0, kv, o0);
    run_big(o0, 256, 0, woh, 256, 0, x1, 256, 0,
            TT, 256, 256, 1, nullptr, tr_emb, 2048, nullptr, 0, F_AUX, false, 64);
    k_ln_f<<<TT / 8, 256>>>(x1, ln2);
    run_big(ln2, 256, 0, ff1h, 1024, 0, ffh, 1024, 0,
            TT, 1024, 256, 1, nullptr, nullptr, 0, nullptr, 0, F_RELU | F_OUT16, false);
    run_big(ffh, 1024, 0, ff2h, 256, 0, ffout, 256, 0,
            TT, 256, 1024, 1, nullptr, nullptr, 0, nullptr, 0, 0, false, 64);
    k_feat0<<<ROWS1 / 4, 256>>>(tr_emb, x1, ffout, det_emb, feat0, x);

    // ---- main GAT x2 ----
    for (int l = 0; l < 2; l++) {
        run_big(x, 256, 0, gatWh + (size_t)l * 65536, 256, 0, hh, 256, 0,
                ROWS1, 256, 256, 1, nullptr, nullptr, 0, nullptr, 0, F_OUT16, false);
        k_srcdst<<<ROWS1 / 8, 256>>>(hh, gata + (size_t)l * 512, src, dstT, NN1);
        k_rowstat<<<dim3(NN1, BB), 128>>>(src, dstT, adj, stat, anum, NN1);
        agg_fused<false><<<dim3(1, NN1 / 128, BB * HH), 256>>>(anum, stat, hh, feat0, x, NN1);
    }

    // ---- main scores (dual xq/xk; asso fused) ----
    run_big(x, 256, 0, clsWqh, 256, 0, xq, 256, 0,
            ROWS1, 256, 256, 2, nullptr, nullptr, 0, nullptr, 0, F_OUT16, false, 128,
            clsWkh, xk, 1);
    run_big(xq, 256, (long long)NN1 * 256, xk, 256, (long long)NN1 * 256,
            out_scores, NN1, (long long)NN1 * NN1,
            NN1, NN1, 256, BB, nullptr, nullptr, 0,
            adj, (long long)NN1 * NN1, F_SIG | F_ASSO, true, 128,
            nullptr, nullptr, 0, out_asso);

    // ---- join det branch back into the captured stream ----
    cudaStreamWaitEvent(0, evDet, 0);

    cudaEventDestroy(evRoot);
    cudaEventDestroy(evMLP);
    cudaEventDestroy(evDet);
    cudaStreamDestroy(s1);
}